// round 1
// baseline (speedup 1.0000x reference)
#include <cuda_runtime.h>
#include <math.h>

// Problem constants
#define BB 8
#define NN 4096
#define DD 128
#define KT 64
#define RR 512

// Output layout: concat(out[B,K,D], policy[B], scorer[B,D], entropy[B])
#define OFF_OUT     0
#define OFF_POL     (BB*KT*DD)          // 65536
#define OFF_SCORER  (OFF_POL + BB)      // 65544
#define OFF_ENT     (OFF_SCORER + BB*DD) // 66568

// Device scratch (no allocations allowed)
__device__ float g_z[BB*DD*DD];      // z_topk: [b][d][i]
__device__ float g_ne[BB*KT*DD];     // gathered topk node embeddings
__device__ float g_A[BB*KT*KT];      // normalized pooled adjacency
__device__ int   g_topk[BB*KT];
__device__ float g_tanhv[BB*KT];     // tanh(score) at topk
__device__ float g_u[BB*DD*DD];
__device__ float g_r[BB*DD*DD];
__device__ float g_newQ[BB*DD*DD];

// ---------------------------------------------------------------------------
// K1: per-batch scorer, scores, softmax stats, ordered top-64, policy/entropy
// ---------------------------------------------------------------------------
__global__ void __launch_bounds__(512) k_score_topk(
    const float* __restrict__ node_embs, const float* __restrict__ ht,
    const float* __restrict__ W_map, const float* __restrict__ b_map,
    float* __restrict__ out)
{
    const int b = blockIdx.x, tid = threadIdx.x;
    const int T = 512;
    const int warp = tid >> 5, lane = tid & 31;

    __shared__ float sh_ht[RR];
    __shared__ float sh_scorer[DD];
    __shared__ float sh_scores[NN];
    __shared__ float sh_red[16];
    __shared__ float sh_red2[16];
    __shared__ int   sh_redi[16];
    __shared__ float sh_bcast;
    __shared__ float sh_logZ;

    for (int i = tid; i < RR; i += T) sh_ht[i] = ht[b*RR + i];
    __syncthreads();

    // scorer[d] = tanh(sum_r ht[r]*W_map[r,d] + b_map[d])
    if (tid < DD) {
        float acc = b_map[tid];
        #pragma unroll 8
        for (int r = 0; r < RR; ++r) acc = fmaf(sh_ht[r], W_map[r*DD + tid], acc);
        sh_scorer[tid] = tanhf(acc);
    }
    __syncthreads();

    // ||scorer||
    float v = (tid < DD) ? sh_scorer[tid]*sh_scorer[tid] : 0.f;
    #pragma unroll
    for (int o = 16; o; o >>= 1) v += __shfl_xor_sync(0xffffffffu, v, o);
    if (lane == 0) sh_red[warp] = v;
    __syncthreads();
    if (tid == 0) { float s = 0.f; for (int w = 0; w < 16; ++w) s += sh_red[w]; sh_bcast = sqrtf(s); }
    __syncthreads();
    const float norm = sh_bcast;

    // scores[n] = (node_embs[b,n,:] . scorer) / norm   (warp per node)
    for (int n = warp; n < NN; n += 16) {
        const float* e = node_embs + ((size_t)(b*NN + n))*DD;
        float acc = 0.f;
        #pragma unroll
        for (int d = lane; d < DD; d += 32) acc = fmaf(e[d], sh_scorer[d], acc);
        #pragma unroll
        for (int o = 16; o; o >>= 1) acc += __shfl_xor_sync(0xffffffffu, acc, o);
        if (lane == 0) sh_scores[n] = acc / norm;
    }
    __syncthreads();

    // max
    float mx = -INFINITY;
    for (int n = tid; n < NN; n += T) mx = fmaxf(mx, sh_scores[n]);
    #pragma unroll
    for (int o = 16; o; o >>= 1) mx = fmaxf(mx, __shfl_xor_sync(0xffffffffu, mx, o));
    if (lane == 0) sh_red[warp] = mx;
    __syncthreads();
    if (tid == 0) { float m = -INFINITY; for (int w = 0; w < 16; ++w) m = fmaxf(m, sh_red[w]); sh_bcast = m; }
    __syncthreads();
    const float M = sh_bcast;

    // S1 = sum exp(s-M), S2 = sum s*exp(s-M)
    float s1 = 0.f, s2 = 0.f;
    for (int n = tid; n < NN; n += T) {
        float s = sh_scores[n];
        float e = expf(s - M);
        s1 += e; s2 = fmaf(s, e, s2);
    }
    #pragma unroll
    for (int o = 16; o; o >>= 1) {
        s1 += __shfl_xor_sync(0xffffffffu, s1, o);
        s2 += __shfl_xor_sync(0xffffffffu, s2, o);
    }
    if (lane == 0) { sh_red[warp] = s1; sh_red2[warp] = s2; }
    __syncthreads();
    if (tid == 0) {
        float S1 = 0.f, S2 = 0.f;
        for (int w = 0; w < 16; ++w) { S1 += sh_red[w]; S2 += sh_red2[w]; }
        float logZ = M + logf(S1);
        sh_logZ = logZ;
        out[OFF_ENT + b] = logZ - S2 / S1;   // entropy = logZ - E[s]
    }
    if (tid < DD) out[OFF_SCORER + b*DD + tid] = sh_scorer[tid];
    __syncthreads();

    // ordered top-64 via iterative block argmax (ties -> lowest index)
    float psum = 0.f;  // valid on tid 0
    for (int round = 0; round < KT; ++round) {
        float bv = -INFINITY; int bi = -1;
        for (int n = tid; n < NN; n += T) {
            float s = sh_scores[n];
            if (s > bv || (s == bv && n < bi)) { bv = s; bi = n; }
        }
        #pragma unroll
        for (int o = 16; o; o >>= 1) {
            float ov = __shfl_xor_sync(0xffffffffu, bv, o);
            int   oi = __shfl_xor_sync(0xffffffffu, bi, o);
            if (ov > bv || (ov == bv && oi < bi)) { bv = ov; bi = oi; }
        }
        if (lane == 0) { sh_red[warp] = bv; sh_redi[warp] = bi; }
        __syncthreads();
        if (tid == 0) {
            float Bv = -INFINITY; int Bi = -1;
            for (int w = 0; w < 16; ++w) {
                float ov = sh_red[w]; int oi = sh_redi[w];
                if (ov > Bv || (ov == Bv && oi < Bi)) { Bv = ov; Bi = oi; }
            }
            g_topk[b*KT + round]  = Bi;
            g_tanhv[b*KT + round] = tanhf(Bv);
            psum += Bv;
            sh_scores[Bi] = -INFINITY;
        }
        __syncthreads();
    }
    // policy = mean(logp at idx_rep) = mean(topk vals) - logZ (idx_rep = 2x topk)
    if (tid == 0) out[OFF_POL + b] = psum * (1.f/KT) - sh_logZ;
}

// ---------------------------------------------------------------------------
// K2: pooled adjacency gather + sym-normalize, z_topk (transposed), ne
// ---------------------------------------------------------------------------
__global__ void __launch_bounds__(256) k_gather(
    const float* __restrict__ node_embs, const float* __restrict__ Ahat)
{
    const int b = blockIdx.x, tid = threadIdx.x;
    __shared__ float sA[KT*KT];
    __shared__ int   s_idx[KT];
    __shared__ float s_t[KT];
    __shared__ float s_di[KT];

    if (tid < KT) { s_idx[tid] = g_topk[b*KT + tid]; s_t[tid] = g_tanhv[b*KT + tid]; }
    __syncthreads();

    for (int e = tid; e < KT*KT; e += 256) {
        int i = e >> 6, j = e & 63;
        sA[e] = Ahat[(size_t)b*NN*NN + (size_t)s_idx[i]*NN + s_idx[j]];
    }
    __syncthreads();
    if (tid < KT) {
        float s = 0.f;
        for (int i = 0; i < KT; ++i) s += sA[i*KT + tid];
        s_di[tid] = 1.0f / sqrtf(s);   // sum^(-0.5)
    }
    __syncthreads();
    for (int e = tid; e < KT*KT; e += 256) {
        int i = e >> 6, j = e & 63;
        g_A[b*KT*KT + e] = s_di[j] * sA[e] * s_di[i];
    }

    // z_topk[d][i] = node_embs[b, topk[i%64], d] * tanhv[i%64]; ne rows for i<64
    const int warp = tid >> 5, lane = tid & 31;   // 8 warps
    for (int i = warp; i < DD; i += 8) {
        int k = i & (KT - 1);
        const float* e = node_embs + ((size_t)(b*NN + s_idx[k]))*DD;
        float tv = s_t[k];
        for (int d = lane; d < DD; d += 32) {
            float val = e[d];
            g_z[((size_t)b*DD + d)*DD + i] = val * tv;
            if (i < KT) g_ne[(b*KT + i)*DD + d] = val;
        }
    }
}

// ---------------------------------------------------------------------------
// K3: update & reset gates (fused). One output row per block.
// ---------------------------------------------------------------------------
__global__ void __launch_bounds__(128) k_gates(
    const float* __restrict__ prevQ,
    const float* __restrict__ Wu, const float* __restrict__ Uu, const float* __restrict__ bu,
    const float* __restrict__ Wr, const float* __restrict__ Ur, const float* __restrict__ br)
{
    const int i = blockIdx.x, b = blockIdx.y, j = threadIdx.x;
    __shared__ float swu[DD], suu[DD], swr[DD], sur[DD];
    swu[j] = Wu[i*DD + j]; suu[j] = Uu[i*DD + j];
    swr[j] = Wr[i*DD + j]; sur[j] = Ur[i*DD + j];
    __syncthreads();
    const float* z = g_z + (size_t)b*DD*DD;
    const float* Q = prevQ + (size_t)b*DD*DD;
    float au = bu[i*DD + j], ar = br[i*DD + j];
    #pragma unroll 4
    for (int k = 0; k < DD; ++k) {
        float zk = z[k*DD + j], qk = Q[k*DD + j];
        au = fmaf(swu[k], zk, au); au = fmaf(suu[k], qk, au);
        ar = fmaf(swr[k], zk, ar); ar = fmaf(sur[k], qk, ar);
    }
    g_u[((size_t)b*DD + i)*DD + j] = 1.f / (1.f + expf(-au));
    g_r[((size_t)b*DD + i)*DD + j] = 1.f / (1.f + expf(-ar));
}

// ---------------------------------------------------------------------------
// K4: h_cap + new_Q
// ---------------------------------------------------------------------------
__global__ void __launch_bounds__(128) k_newQ(
    const float* __restrict__ prevQ,
    const float* __restrict__ Wh, const float* __restrict__ Uh, const float* __restrict__ bh)
{
    const int i = blockIdx.x, b = blockIdx.y, j = threadIdx.x;
    __shared__ float swh[DD], suh[DD];
    swh[j] = Wh[i*DD + j]; suh[j] = Uh[i*DD + j];
    __syncthreads();
    const float* z = g_z + (size_t)b*DD*DD;
    const float* Q = prevQ + (size_t)b*DD*DD;
    const float* r = g_r + (size_t)b*DD*DD;
    float a = bh[i*DD + j];
    #pragma unroll 4
    for (int k = 0; k < DD; ++k) {
        a = fmaf(swh[k], z[k*DD + j], a);
        a = fmaf(suh[k], r[k*DD + j] * Q[k*DD + j], a);
    }
    float h = tanhf(a);
    float u = g_u[((size_t)b*DD + i)*DD + j];
    float q = Q[i*DD + j];
    g_newQ[((size_t)b*DD + i)*DD + j] = (1.f - u)*q + u*h;
}

// ---------------------------------------------------------------------------
// K5: fused dual GCN per batch: h1=relu(A(ne@newQ)), h2=relu(A(h1@W)), out
// dyn smem: A[64*64] + P[64*128] + h1[64*128] = 80 KB
// ---------------------------------------------------------------------------
__global__ void __launch_bounds__(512) k_gcn(
    const float* __restrict__ staticW, float* __restrict__ out)
{
    extern __shared__ float sm[];
    float* sA  = sm;                 // 64*64
    float* sP  = sm + KT*KT;         // 64*128
    float* sH1 = sP + KT*DD;         // 64*128
    const int b = blockIdx.x, tid = threadIdx.x;

    for (int e = tid; e < KT*KT; e += 512) sA[e] = g_A[b*KT*KT + e];

    const float* ne = g_ne + (size_t)b*KT*DD;
    const float* NQ = g_newQ + (size_t)b*DD*DD;
    for (int e = tid; e < KT*DD; e += 512) {
        int k = e >> 7, j = e & 127;
        float acc = 0.f;
        #pragma unroll 4
        for (int d = 0; d < DD; ++d) acc = fmaf(ne[k*DD + d], NQ[d*DD + j], acc);
        sP[e] = acc;
    }
    __syncthreads();
    for (int e = tid; e < KT*DD; e += 512) {
        int k = e >> 7, j = e & 127;
        float acc = 0.f;
        #pragma unroll 4
        for (int m = 0; m < KT; ++m) acc = fmaf(sA[k*KT + m], sP[m*DD + j], acc);
        sH1[e] = fmaxf(acc, 0.f);
    }
    __syncthreads();
    for (int e = tid; e < KT*DD; e += 512) {
        int k = e >> 7, j = e & 127;
        float acc = 0.f;
        #pragma unroll 4
        for (int d = 0; d < DD; ++d) acc = fmaf(sH1[k*DD + d], staticW[d*DD + j], acc);
        sP[e] = acc;   // safe: sP reads completed before this sync barrier pair
    }
    __syncthreads();
    for (int e = tid; e < KT*DD; e += 512) {
        int k = e >> 7, j = e & 127;
        float acc = 0.f;
        #pragma unroll 4
        for (int m = 0; m < KT; ++m) acc = fmaf(sA[k*KT + m], sP[m*DD + j], acc);
        out[(size_t)b*KT*DD + e] = (sH1[e] + fmaxf(acc, 0.f)) * 0.5f;
    }
}

// ---------------------------------------------------------------------------
extern "C" void kernel_launch(void* const* d_in, const int* in_sizes, int n_in,
                              void* d_out, int out_size)
{
    const float* Ahat      = (const float*)d_in[0];
    const float* node_embs = (const float*)d_in[1];
    // d_in[2] = mask (unused by reference)
    const float* ht        = (const float*)d_in[3];
    const float* prevQ     = (const float*)d_in[4];
    const float* W_map     = (const float*)d_in[5];
    const float* b_map     = (const float*)d_in[6];
    const float* Wu        = (const float*)d_in[7];
    const float* Uu        = (const float*)d_in[8];
    const float* bu        = (const float*)d_in[9];
    const float* Wr        = (const float*)d_in[10];
    const float* Ur        = (const float*)d_in[11];
    const float* br        = (const float*)d_in[12];
    const float* Wh        = (const float*)d_in[13];
    const float* Uh        = (const float*)d_in[14];
    const float* bh        = (const float*)d_in[15];
    const float* sW        = (const float*)d_in[16];
    float* out = (float*)d_out;

    cudaFuncSetAttribute(k_gcn, cudaFuncAttributeMaxDynamicSharedMemorySize,
                         (KT*KT + 2*KT*DD) * (int)sizeof(float));

    k_score_topk<<<BB, 512>>>(node_embs, ht, W_map, b_map, out);
    k_gather<<<BB, 256>>>(node_embs, Ahat);
    dim3 g(DD, BB);
    k_gates<<<g, 128>>>(prevQ, Wu, Uu, bu, Wr, Ur, br);
    k_newQ<<<g, 128>>>(prevQ, Wh, Uh, bh);
    k_gcn<<<BB, 512, (KT*KT + 2*KT*DD) * (int)sizeof(float)>>>(sW, out);
}

// round 2
// speedup vs baseline: 1.9936x; 1.9936x over previous
#include <cuda_runtime.h>
#include <math.h>

#define BB 8
#define NN 4096
#define DD 128
#define KT 64
#define RR 512

// Output layout: concat(out[B,K,D], policy[B], scorer[B,D], entropy[B])
#define OFF_OUT     0
#define OFF_POL     (BB*KT*DD)
#define OFF_SCORER  (OFF_POL + BB)
#define OFF_ENT     (OFF_SCORER + BB*DD)

// Device scratch
__device__ float g_scorer_n[BB*DD];   // scorer / ||scorer||
__device__ float g_scores[BB*NN];
__device__ float g_z[BB*DD*DD];       // z_topk [b][d][i]
__device__ float g_ne[BB*KT*DD];
__device__ float g_A[BB*KT*KT];
__device__ float g_u[BB*DD*DD];
__device__ float g_r[BB*DD*DD];
__device__ float g_newQ[BB*DD*DD];
__device__ float g_P[BB*KT*DD];
__device__ float g_h1[BB*KT*DD];
__device__ float g_G[BB*KT*DD];

// ---------------------------------------------------------------------------
// K1: scorer[b][d] = tanh(ht@W_map + b_map); also scaled copy for scoring
// ---------------------------------------------------------------------------
__global__ void __launch_bounds__(512) k_scorer(
    const float* __restrict__ ht, const float* __restrict__ W_map,
    const float* __restrict__ b_map, float* __restrict__ out)
{
    const int b = blockIdx.x, tid = threadIdx.x;
    __shared__ float sht[RR];
    __shared__ float part[4][DD];
    __shared__ float ssc[DD];
    __shared__ float s_inv;
    sht[tid] = ht[b*RR + tid];
    __syncthreads();
    const int d = tid & 127, rq = tid >> 7;
    float acc = 0.f;
    const int r0 = rq * 128;
    #pragma unroll 4
    for (int r = 0; r < 128; ++r) acc = fmaf(sht[r0 + r], W_map[(r0 + r)*DD + d], acc);
    part[rq][d] = acc;
    __syncthreads();
    if (tid < DD) {
        float s = part[0][tid] + part[1][tid] + part[2][tid] + part[3][tid] + b_map[tid];
        float sc = tanhf(s);
        ssc[tid] = sc;
        out[OFF_SCORER + b*DD + tid] = sc;
    }
    __syncthreads();
    if (tid < 32) {
        float s = 0.f;
        for (int i = tid; i < DD; i += 32) s += ssc[i]*ssc[i];
        #pragma unroll
        for (int o = 16; o; o >>= 1) s += __shfl_xor_sync(0xffffffffu, s, o);
        if (tid == 0) s_inv = 1.0f / sqrtf(s);
    }
    __syncthreads();
    if (tid < DD) g_scorer_n[b*DD + tid] = ssc[tid] * s_inv;
}

// ---------------------------------------------------------------------------
// K2: scores[b][n] = node_embs[b,n,:] . scorer_n   (warp per node, float4)
// ---------------------------------------------------------------------------
__global__ void __launch_bounds__(128) k_scores(const float* __restrict__ node_embs)
{
    const int b = blockIdx.y, base = blockIdx.x * 128, tid = threadIdx.x;
    const int warp = tid >> 5, lane = tid & 31;
    __shared__ float4 ssc[32];
    if (tid < 32) ssc[tid] = ((const float4*)(g_scorer_n + b*DD))[tid];
    __syncthreads();
    const float4 sv = ssc[lane];
    #pragma unroll 4
    for (int t = 0; t < 32; ++t) {
        const int n = base + warp * 32 + t;
        const float4 v = ((const float4*)(node_embs + ((size_t)(b*NN + n))*DD))[lane];
        float acc = v.x*sv.x + v.y*sv.y + v.z*sv.z + v.w*sv.w;
        #pragma unroll
        for (int o = 16; o; o >>= 1) acc += __shfl_xor_sync(0xffffffffu, acc, o);
        if (lane == 0) g_scores[b*NN + n] = acc;
    }
}

// ---------------------------------------------------------------------------
// K3: per-batch softmax stats + bitonic top-64 + gather (A, z, ne)
// dynamic smem: 4096 u64 keys (32KB), reused as float sA[4096] after sort
// ---------------------------------------------------------------------------
__global__ void __launch_bounds__(512) k_topk_gather(
    const float* __restrict__ node_embs, const float* __restrict__ Ahat,
    float* __restrict__ out)
{
    extern __shared__ unsigned long long skey[];
    const int b = blockIdx.x, tid = threadIdx.x;
    const int warp = tid >> 5, lane = tid & 31;
    __shared__ float sred[16], sred2[16];
    __shared__ float s_M, s_logZ;
    __shared__ int   s_idx[KT];
    __shared__ float s_t[KT];
    __shared__ float s_v[KT];
    __shared__ float s_di[KT];

    // load + pack keys + max
    float lmax = -INFINITY;
    for (int n = tid; n < NN; n += 512) {
        float s = g_scores[b*NN + n];
        lmax = fmaxf(lmax, s);
        unsigned u = __float_as_uint(s);
        unsigned m = (u & 0x80000000u) ? ~u : (u | 0x80000000u);
        skey[n] = ((unsigned long long)m << 32) | (unsigned)(NN - 1 - n);
    }
    #pragma unroll
    for (int o = 16; o; o >>= 1) lmax = fmaxf(lmax, __shfl_xor_sync(0xffffffffu, lmax, o));
    if (lane == 0) sred[warp] = lmax;
    __syncthreads();
    if (tid == 0) { float m = -INFINITY; for (int w = 0; w < 16; ++w) m = fmaxf(m, sred[w]); s_M = m; }
    __syncthreads();
    const float M = s_M;

    // S1 = sum exp(s-M), S2 = sum s*exp(s-M)
    float s1 = 0.f, s2 = 0.f;
    for (int n = tid; n < NN; n += 512) {
        float s = g_scores[b*NN + n];
        float e = __expf(s - M);
        s1 += e; s2 = fmaf(s, e, s2);
    }
    #pragma unroll
    for (int o = 16; o; o >>= 1) {
        s1 += __shfl_xor_sync(0xffffffffu, s1, o);
        s2 += __shfl_xor_sync(0xffffffffu, s2, o);
    }
    if (lane == 0) { sred[warp] = s1; sred2[warp] = s2; }
    __syncthreads();
    if (tid == 0) {
        float S1 = 0.f, S2 = 0.f;
        for (int w = 0; w < 16; ++w) { S1 += sred[w]; S2 += sred2[w]; }
        float logZ = M + logf(S1);
        s_logZ = logZ;
        out[OFF_ENT + b] = logZ - S2 / S1;
    }

    // bitonic sort descending (full 4096)
    for (int k = 2; k <= NN; k <<= 1) {
        for (int j = k >> 1; j > 0; j >>= 1) {
            __syncthreads();
            #pragma unroll
            for (int p = 0; p < 8; ++p) {
                const int i = tid + p * 512;
                const int l = i ^ j;
                if (l > i) {
                    unsigned long long a = skey[i], c = skey[l];
                    bool desc = ((i & k) == 0);
                    if (desc ? (a < c) : (a > c)) { skey[i] = c; skey[l] = a; }
                }
            }
        }
    }
    __syncthreads();

    if (tid < KT) {
        unsigned long long kk = skey[tid];
        int n = NN - 1 - (int)(kk & 0xFFFu);
        unsigned m = (unsigned)(kk >> 32);
        unsigned u = (m & 0x80000000u) ? (m ^ 0x80000000u) : ~m;
        float s = __uint_as_float(u);
        s_idx[tid] = n; s_t[tid] = tanhf(s); s_v[tid] = s;
    }
    __syncthreads();
    if (tid == 0) {
        float sum = 0.f;
        for (int i = 0; i < KT; ++i) sum += s_v[i];
        out[OFF_POL + b] = sum * (1.f/KT) - s_logZ;
    }

    // gather pooled A (reuse key smem as float scratch)
    float* sA = (float*)skey;
    for (int e = tid; e < KT*KT; e += 512) {
        int i = e >> 6, j = e & 63;
        sA[e] = Ahat[(size_t)b*NN*NN + (size_t)s_idx[i]*NN + s_idx[j]];
    }
    __syncthreads();
    if (tid < KT) {
        float s = 0.f;
        for (int i = 0; i < KT; ++i) s += sA[i*KT + tid];
        s_di[tid] = 1.0f / sqrtf(s);
    }
    __syncthreads();
    for (int e = tid; e < KT*KT; e += 512) {
        int i = e >> 6, j = e & 63;
        g_A[b*KT*KT + e] = s_di[j] * sA[e] * s_di[i];
    }

    // z_topk [d][i] and ne
    for (int i = warp; i < DD; i += 16) {
        int k = i & (KT - 1);
        const float* e = node_embs + ((size_t)(b*NN + s_idx[k]))*DD;
        float tv = s_t[k];
        for (int d = lane; d < DD; d += 32) {
            float val = e[d];
            g_z[((size_t)b*DD + d)*DD + i] = val * tv;
            if (i < KT) g_ne[(b*KT + i)*DD + d] = val;
        }
    }
}

// ---------------------------------------------------------------------------
// K4: update & reset gates, 8 output rows per thread
// ---------------------------------------------------------------------------
__global__ void __launch_bounds__(128) k_gates(
    const float* __restrict__ prevQ,
    const float* __restrict__ Wu, const float* __restrict__ Uu, const float* __restrict__ bu,
    const float* __restrict__ Wr, const float* __restrict__ Ur, const float* __restrict__ br)
{
    const int i0 = blockIdx.x * 8, b = blockIdx.y, j = threadIdx.x;
    __shared__ float sw[4][8*DD];   // Wu,Uu,Wr,Ur rows
    for (int e = j; e < 8*DD; e += 128) {
        int r = e >> 7, c = e & 127;
        sw[0][e] = Wu[(i0+r)*DD + c]; sw[1][e] = Uu[(i0+r)*DD + c];
        sw[2][e] = Wr[(i0+r)*DD + c]; sw[3][e] = Ur[(i0+r)*DD + c];
    }
    __syncthreads();
    const float* z = g_z + (size_t)b*DD*DD;
    const float* Q = prevQ + (size_t)b*DD*DD;
    float au[8], ar[8];
    #pragma unroll
    for (int r = 0; r < 8; ++r) { au[r] = bu[(i0+r)*DD + j]; ar[r] = br[(i0+r)*DD + j]; }
    for (int k = 0; k < DD; k += 4) {
        float zk[4], qk[4];
        #pragma unroll
        for (int t = 0; t < 4; ++t) { zk[t] = z[(k+t)*DD + j]; qk[t] = Q[(k+t)*DD + j]; }
        #pragma unroll
        for (int r = 0; r < 8; ++r) {
            float4 wu = *(const float4*)&sw[0][r*DD + k];
            float4 uu = *(const float4*)&sw[1][r*DD + k];
            float4 wr = *(const float4*)&sw[2][r*DD + k];
            float4 ur = *(const float4*)&sw[3][r*DD + k];
            au[r] = fmaf(wu.x, zk[0], au[r]); au[r] = fmaf(wu.y, zk[1], au[r]);
            au[r] = fmaf(wu.z, zk[2], au[r]); au[r] = fmaf(wu.w, zk[3], au[r]);
            au[r] = fmaf(uu.x, qk[0], au[r]); au[r] = fmaf(uu.y, qk[1], au[r]);
            au[r] = fmaf(uu.z, qk[2], au[r]); au[r] = fmaf(uu.w, qk[3], au[r]);
            ar[r] = fmaf(wr.x, zk[0], ar[r]); ar[r] = fmaf(wr.y, zk[1], ar[r]);
            ar[r] = fmaf(wr.z, zk[2], ar[r]); ar[r] = fmaf(wr.w, zk[3], ar[r]);
            ar[r] = fmaf(ur.x, qk[0], ar[r]); ar[r] = fmaf(ur.y, qk[1], ar[r]);
            ar[r] = fmaf(ur.z, qk[2], ar[r]); ar[r] = fmaf(ur.w, qk[3], ar[r]);
        }
    }
    #pragma unroll
    for (int r = 0; r < 8; ++r) {
        g_u[((size_t)b*DD + i0 + r)*DD + j] = 1.f / (1.f + __expf(-au[r]));
        g_r[((size_t)b*DD + i0 + r)*DD + j] = 1.f / (1.f + __expf(-ar[r]));
    }
}

// ---------------------------------------------------------------------------
// K5: h_cap + new_Q, 8 rows per thread
// ---------------------------------------------------------------------------
__global__ void __launch_bounds__(128) k_newQ(
    const float* __restrict__ prevQ,
    const float* __restrict__ Wh, const float* __restrict__ Uh, const float* __restrict__ bh)
{
    const int i0 = blockIdx.x * 8, b = blockIdx.y, j = threadIdx.x;
    __shared__ float sw[2][8*DD];
    for (int e = j; e < 8*DD; e += 128) {
        int r = e >> 7, c = e & 127;
        sw[0][e] = Wh[(i0+r)*DD + c]; sw[1][e] = Uh[(i0+r)*DD + c];
    }
    __syncthreads();
    const float* z = g_z + (size_t)b*DD*DD;
    const float* Q = prevQ + (size_t)b*DD*DD;
    const float* rr = g_r + (size_t)b*DD*DD;
    float a[8];
    #pragma unroll
    for (int r = 0; r < 8; ++r) a[r] = bh[(i0+r)*DD + j];
    for (int k = 0; k < DD; k += 4) {
        float zk[4], rq[4];
        #pragma unroll
        for (int t = 0; t < 4; ++t) {
            zk[t] = z[(k+t)*DD + j];
            rq[t] = rr[(k+t)*DD + j] * Q[(k+t)*DD + j];
        }
        #pragma unroll
        for (int r = 0; r < 8; ++r) {
            float4 wh = *(const float4*)&sw[0][r*DD + k];
            float4 uh = *(const float4*)&sw[1][r*DD + k];
            a[r] = fmaf(wh.x, zk[0], a[r]); a[r] = fmaf(wh.y, zk[1], a[r]);
            a[r] = fmaf(wh.z, zk[2], a[r]); a[r] = fmaf(wh.w, zk[3], a[r]);
            a[r] = fmaf(uh.x, rq[0], a[r]); a[r] = fmaf(uh.y, rq[1], a[r]);
            a[r] = fmaf(uh.z, rq[2], a[r]); a[r] = fmaf(uh.w, rq[3], a[r]);
        }
    }
    #pragma unroll
    for (int r = 0; r < 8; ++r) {
        float h = tanhf(a[r]);
        float u = g_u[((size_t)b*DD + i0 + r)*DD + j];
        float q = Q[(i0 + r)*DD + j];
        g_newQ[((size_t)b*DD + i0 + r)*DD + j] = (1.f - u)*q + u*h;
    }
}

// ---------------------------------------------------------------------------
// K6a: P = ne @ newQ  (64x128 out per batch, 8 rows per block)
// ---------------------------------------------------------------------------
__global__ void __launch_bounds__(128) k_g1()
{
    const int r0 = blockIdx.x * 8, b = blockIdx.y, j = threadIdx.x;
    __shared__ float sa[8*DD];
    for (int e = j; e < 8*DD; e += 128) sa[e] = g_ne[(size_t)b*KT*DD + (r0 + (e >> 7))*DD + (e & 127)];
    __syncthreads();
    const float* Bm = g_newQ + (size_t)b*DD*DD;
    float acc[8] = {0,0,0,0,0,0,0,0};
    for (int k = 0; k < DD; k += 4) {
        float bk[4];
        #pragma unroll
        for (int t = 0; t < 4; ++t) bk[t] = Bm[(k+t)*DD + j];
        #pragma unroll
        for (int r = 0; r < 8; ++r) {
            float4 w = *(const float4*)&sa[r*DD + k];
            acc[r] = fmaf(w.x, bk[0], acc[r]); acc[r] = fmaf(w.y, bk[1], acc[r]);
            acc[r] = fmaf(w.z, bk[2], acc[r]); acc[r] = fmaf(w.w, bk[3], acc[r]);
        }
    }
    #pragma unroll
    for (int r = 0; r < 8; ++r) g_P[(size_t)b*KT*DD + (r0+r)*DD + j] = acc[r];
}

// ---------------------------------------------------------------------------
// K6b: h1 = relu(A @ P)
// ---------------------------------------------------------------------------
__global__ void __launch_bounds__(128) k_g2()
{
    const int r0 = blockIdx.x * 8, b = blockIdx.y, j = threadIdx.x;
    __shared__ float sa[8*KT];
    for (int e = j; e < 8*KT; e += 128) sa[e] = g_A[b*KT*KT + (r0 + (e >> 6))*KT + (e & 63)];
    __syncthreads();
    const float* Bm = g_P + (size_t)b*KT*DD;
    float acc[8] = {0,0,0,0,0,0,0,0};
    for (int m = 0; m < KT; m += 4) {
        float pm[4];
        #pragma unroll
        for (int t = 0; t < 4; ++t) pm[t] = Bm[(m+t)*DD + j];
        #pragma unroll
        for (int r = 0; r < 8; ++r) {
            float4 w = *(const float4*)&sa[r*KT + m];
            acc[r] = fmaf(w.x, pm[0], acc[r]); acc[r] = fmaf(w.y, pm[1], acc[r]);
            acc[r] = fmaf(w.z, pm[2], acc[r]); acc[r] = fmaf(w.w, pm[3], acc[r]);
        }
    }
    #pragma unroll
    for (int r = 0; r < 8; ++r) g_h1[(size_t)b*KT*DD + (r0+r)*DD + j] = fmaxf(acc[r], 0.f);
}

// ---------------------------------------------------------------------------
// K6c: G = h1 @ staticW
// ---------------------------------------------------------------------------
__global__ void __launch_bounds__(128) k_g3(const float* __restrict__ sW)
{
    const int r0 = blockIdx.x * 8, b = blockIdx.y, j = threadIdx.x;
    __shared__ float sa[8*DD];
    for (int e = j; e < 8*DD; e += 128) sa[e] = g_h1[(size_t)b*KT*DD + (r0 + (e >> 7))*DD + (e & 127)];
    __syncthreads();
    float acc[8] = {0,0,0,0,0,0,0,0};
    for (int k = 0; k < DD; k += 4) {
        float bk[4];
        #pragma unroll
        for (int t = 0; t < 4; ++t) bk[t] = sW[(k+t)*DD + j];
        #pragma unroll
        for (int r = 0; r < 8; ++r) {
            float4 w = *(const float4*)&sa[r*DD + k];
            acc[r] = fmaf(w.x, bk[0], acc[r]); acc[r] = fmaf(w.y, bk[1], acc[r]);
            acc[r] = fmaf(w.z, bk[2], acc[r]); acc[r] = fmaf(w.w, bk[3], acc[r]);
        }
    }
    #pragma unroll
    for (int r = 0; r < 8; ++r) g_G[(size_t)b*KT*DD + (r0+r)*DD + j] = acc[r];
}

// ---------------------------------------------------------------------------
// K6d: out = (h1 + relu(A @ G)) / 2
// ---------------------------------------------------------------------------
__global__ void __launch_bounds__(128) k_g4(float* __restrict__ out)
{
    const int r0 = blockIdx.x * 8, b = blockIdx.y, j = threadIdx.x;
    __shared__ float sa[8*KT];
    for (int e = j; e < 8*KT; e += 128) sa[e] = g_A[b*KT*KT + (r0 + (e >> 6))*KT + (e & 63)];
    __syncthreads();
    const float* Bm = g_G + (size_t)b*KT*DD;
    float acc[8] = {0,0,0,0,0,0,0,0};
    for (int m = 0; m < KT; m += 4) {
        float pm[4];
        #pragma unroll
        for (int t = 0; t < 4; ++t) pm[t] = Bm[(m+t)*DD + j];
        #pragma unroll
        for (int r = 0; r < 8; ++r) {
            float4 w = *(const float4*)&sa[r*KT + m];
            acc[r] = fmaf(w.x, pm[0], acc[r]); acc[r] = fmaf(w.y, pm[1], acc[r]);
            acc[r] = fmaf(w.z, pm[2], acc[r]); acc[r] = fmaf(w.w, pm[3], acc[r]);
        }
    }
    #pragma unroll
    for (int r = 0; r < 8; ++r) {
        float h1v = g_h1[(size_t)b*KT*DD + (r0+r)*DD + j];
        out[(size_t)b*KT*DD + (r0+r)*DD + j] = (h1v + fmaxf(acc[r], 0.f)) * 0.5f;
    }
}

// ---------------------------------------------------------------------------
extern "C" void kernel_launch(void* const* d_in, const int* in_sizes, int n_in,
                              void* d_out, int out_size)
{
    const float* Ahat      = (const float*)d_in[0];
    const float* node_embs = (const float*)d_in[1];
    const float* ht        = (const float*)d_in[3];
    const float* prevQ     = (const float*)d_in[4];
    const float* W_map     = (const float*)d_in[5];
    const float* b_map     = (const float*)d_in[6];
    const float* Wu        = (const float*)d_in[7];
    const float* Uu        = (const float*)d_in[8];
    const float* bu        = (const float*)d_in[9];
    const float* Wr        = (const float*)d_in[10];
    const float* Ur        = (const float*)d_in[11];
    const float* br        = (const float*)d_in[12];
    const float* Wh        = (const float*)d_in[13];
    const float* Uh        = (const float*)d_in[14];
    const float* bh        = (const float*)d_in[15];
    const float* sW        = (const float*)d_in[16];
    float* out = (float*)d_out;

    k_scorer<<<BB, 512>>>(ht, W_map, b_map, out);
    k_scores<<<dim3(32, BB), 128>>>(node_embs);
    k_topk_gather<<<BB, 512, NN * sizeof(unsigned long long)>>>(node_embs, Ahat, out);
    k_gates<<<dim3(16, BB), 128>>>(prevQ, Wu, Uu, bu, Wr, Ur, br);
    k_newQ<<<dim3(16, BB), 128>>>(prevQ, Wh, Uh, bh);
    k_g1<<<dim3(8, BB), 128>>>();
    k_g2<<<dim3(8, BB), 128>>>();
    k_g3<<<dim3(8, BB), 128>>>(sW);
    k_g4<<<dim3(8, BB), 128>>>(out);
}

// round 3
// speedup vs baseline: 2.2682x; 1.1378x over previous
#include <cuda_runtime.h>
#include <math.h>

#define BB 8
#define NN 4096
#define DD 128
#define KT 64
#define RR 512

// Output layout: concat(out[B,K,D], policy[B], scorer[B,D], entropy[B])
#define OFF_OUT     0
#define OFF_POL     (BB*KT*DD)
#define OFF_SCORER  (OFF_POL + BB)
#define OFF_ENT     (OFF_SCORER + BB*DD)

// Device scratch
__device__ float g_scorer_n[BB*DD];
__device__ float g_scores[BB*NN];
__device__ float g_z[BB*DD*DD];       // z_topk [b][d][i]
__device__ float g_ne[BB*KT*DD];
__device__ float g_A[BB*KT*KT];
__device__ float g_u[BB*DD*DD];
__device__ float g_rq[BB*DD*DD];      // reset * prevQ
__device__ float g_preh[BB*DD*DD];    // Wh@z + bh
__device__ float g_newQ[BB*DD*DD];
__device__ float g_P[BB*KT*DD];
__device__ float g_h1[BB*KT*DD];
__device__ float g_G[BB*KT*DD];

// ---------------------------------------------------------------------------
// K1: scorer
// ---------------------------------------------------------------------------
__global__ void __launch_bounds__(512) k_scorer(
    const float* __restrict__ ht, const float* __restrict__ W_map,
    const float* __restrict__ b_map, float* __restrict__ out)
{
    const int b = blockIdx.x, tid = threadIdx.x;
    __shared__ float sht[RR];
    __shared__ float part[4][DD];
    __shared__ float ssc[DD];
    __shared__ float s_inv;
    sht[tid] = ht[b*RR + tid];
    __syncthreads();
    const int d = tid & 127, rq = tid >> 7;
    float acc = 0.f;
    const int r0 = rq * 128;
    #pragma unroll 4
    for (int r = 0; r < 128; ++r) acc = fmaf(sht[r0 + r], W_map[(r0 + r)*DD + d], acc);
    part[rq][d] = acc;
    __syncthreads();
    if (tid < DD) {
        float s = part[0][tid] + part[1][tid] + part[2][tid] + part[3][tid] + b_map[tid];
        float sc = tanhf(s);
        ssc[tid] = sc;
        out[OFF_SCORER + b*DD + tid] = sc;
    }
    __syncthreads();
    if (tid < 32) {
        float s = 0.f;
        for (int i = tid; i < DD; i += 32) s += ssc[i]*ssc[i];
        #pragma unroll
        for (int o = 16; o; o >>= 1) s += __shfl_xor_sync(0xffffffffu, s, o);
        if (tid == 0) s_inv = 1.0f / sqrtf(s);
    }
    __syncthreads();
    if (tid < DD) g_scorer_n[b*DD + tid] = ssc[tid] * s_inv;
}

// ---------------------------------------------------------------------------
// K2: scores (warp per node, float4)
// ---------------------------------------------------------------------------
__global__ void __launch_bounds__(128) k_scores(const float* __restrict__ node_embs)
{
    const int b = blockIdx.y, base = blockIdx.x * 128, tid = threadIdx.x;
    const int warp = tid >> 5, lane = tid & 31;
    __shared__ float4 ssc[32];
    if (tid < 32) ssc[tid] = ((const float4*)(g_scorer_n + b*DD))[tid];
    __syncthreads();
    const float4 sv = ssc[lane];
    #pragma unroll 4
    for (int t = 0; t < 32; ++t) {
        const int n = base + warp * 32 + t;
        const float4 v = ((const float4*)(node_embs + ((size_t)(b*NN + n))*DD))[lane];
        float acc = v.x*sv.x + v.y*sv.y + v.z*sv.z + v.w*sv.w;
        #pragma unroll
        for (int o = 16; o; o >>= 1) acc += __shfl_xor_sync(0xffffffffu, acc, o);
        if (lane == 0) g_scores[b*NN + n] = acc;
    }
}

// ---------------------------------------------------------------------------
// K3: softmax stats + bitonic top-64 + gather (A, z, ne)
// ---------------------------------------------------------------------------
__global__ void __launch_bounds__(512) k_topk_gather(
    const float* __restrict__ node_embs, const float* __restrict__ Ahat,
    float* __restrict__ out)
{
    extern __shared__ unsigned long long skey[];
    const int b = blockIdx.x, tid = threadIdx.x;
    const int warp = tid >> 5, lane = tid & 31;
    __shared__ float sred[16], sred2[16];
    __shared__ float s_M, s_logZ;
    __shared__ int   s_idx[KT];
    __shared__ float s_t[KT];
    __shared__ float s_v[KT];
    __shared__ float s_di[KT];

    float lmax = -INFINITY;
    for (int n = tid; n < NN; n += 512) {
        float s = g_scores[b*NN + n];
        lmax = fmaxf(lmax, s);
        unsigned u = __float_as_uint(s);
        unsigned m = (u & 0x80000000u) ? ~u : (u | 0x80000000u);
        skey[n] = ((unsigned long long)m << 32) | (unsigned)(NN - 1 - n);
    }
    #pragma unroll
    for (int o = 16; o; o >>= 1) lmax = fmaxf(lmax, __shfl_xor_sync(0xffffffffu, lmax, o));
    if (lane == 0) sred[warp] = lmax;
    __syncthreads();
    if (tid == 0) { float m = -INFINITY; for (int w = 0; w < 16; ++w) m = fmaxf(m, sred[w]); s_M = m; }
    __syncthreads();
    const float M = s_M;

    float s1 = 0.f, s2 = 0.f;
    for (int n = tid; n < NN; n += 512) {
        float s = g_scores[b*NN + n];
        float e = __expf(s - M);
        s1 += e; s2 = fmaf(s, e, s2);
    }
    #pragma unroll
    for (int o = 16; o; o >>= 1) {
        s1 += __shfl_xor_sync(0xffffffffu, s1, o);
        s2 += __shfl_xor_sync(0xffffffffu, s2, o);
    }
    if (lane == 0) { sred[warp] = s1; sred2[warp] = s2; }
    __syncthreads();
    if (tid == 0) {
        float S1 = 0.f, S2 = 0.f;
        for (int w = 0; w < 16; ++w) { S1 += sred[w]; S2 += sred2[w]; }
        float logZ = M + logf(S1);
        s_logZ = logZ;
        out[OFF_ENT + b] = logZ - S2 / S1;
    }

    for (int k = 2; k <= NN; k <<= 1) {
        for (int j = k >> 1; j > 0; j >>= 1) {
            __syncthreads();
            #pragma unroll
            for (int p = 0; p < 8; ++p) {
                const int i = tid + p * 512;
                const int l = i ^ j;
                if (l > i) {
                    unsigned long long a = skey[i], c = skey[l];
                    bool desc = ((i & k) == 0);
                    if (desc ? (a < c) : (a > c)) { skey[i] = c; skey[l] = a; }
                }
            }
        }
    }
    __syncthreads();

    if (tid < KT) {
        unsigned long long kk = skey[tid];
        int n = NN - 1 - (int)(kk & 0xFFFu);
        unsigned m = (unsigned)(kk >> 32);
        unsigned u = (m & 0x80000000u) ? (m ^ 0x80000000u) : ~m;
        float s = __uint_as_float(u);
        s_idx[tid] = n; s_t[tid] = tanhf(s); s_v[tid] = s;
    }
    __syncthreads();
    if (tid == 0) {
        float sum = 0.f;
        for (int i = 0; i < KT; ++i) sum += s_v[i];
        out[OFF_POL + b] = sum * (1.f/KT) - s_logZ;
    }

    float* sA = (float*)skey;
    for (int e = tid; e < KT*KT; e += 512) {
        int i = e >> 6, j = e & 63;
        sA[e] = Ahat[(size_t)b*NN*NN + (size_t)s_idx[i]*NN + s_idx[j]];
    }
    __syncthreads();
    if (tid < KT) {
        float s = 0.f;
        for (int i = 0; i < KT; ++i) s += sA[i*KT + tid];
        s_di[tid] = 1.0f / sqrtf(s);
    }
    __syncthreads();
    for (int e = tid; e < KT*KT; e += 512) {
        int i = e >> 6, j = e & 63;
        g_A[b*KT*KT + e] = s_di[j] * sA[e] * s_di[i];
    }

    for (int i = warp; i < DD; i += 16) {
        int k = i & (KT - 1);
        const float* e = node_embs + ((size_t)(b*NN + s_idx[k]))*DD;
        float tv = s_t[k];
        for (int d = lane; d < DD; d += 32) {
            float val = e[d];
            g_z[((size_t)b*DD + d)*DD + i] = val * tv;
            if (i < KT) g_ne[(b*KT + i)*DD + d] = val;
        }
    }
}

// ---------------------------------------------------------------------------
// K4: fused u / rq / preh. 4 rows per block, grid (32, B).
// au = Wu@z + Uu@Q, ar = Wr@z + Ur@Q, ah = Wh@z (all share z/Q column loads)
// ---------------------------------------------------------------------------
__global__ void __launch_bounds__(128) k_gates(
    const float* __restrict__ prevQ,
    const float* __restrict__ Wu, const float* __restrict__ Uu, const float* __restrict__ bu,
    const float* __restrict__ Wr, const float* __restrict__ Ur, const float* __restrict__ br,
    const float* __restrict__ Wh, const float* __restrict__ bh)
{
    const int i0 = blockIdx.x * 4, b = blockIdx.y, j = threadIdx.x;
    __shared__ float sw[5][4*DD];   // Wu, Uu, Wr, Ur, Wh rows
    for (int e = j; e < 4*DD; e += 128) {
        int r = e >> 7, c = e & 127;
        sw[0][e] = Wu[(i0+r)*DD + c]; sw[1][e] = Uu[(i0+r)*DD + c];
        sw[2][e] = Wr[(i0+r)*DD + c]; sw[3][e] = Ur[(i0+r)*DD + c];
        sw[4][e] = Wh[(i0+r)*DD + c];
    }
    __syncthreads();
    const float* z = g_z + (size_t)b*DD*DD;
    const float* Q = prevQ + (size_t)b*DD*DD;
    float au[4], ar[4], ah[4];
    #pragma unroll
    for (int r = 0; r < 4; ++r) {
        au[r] = bu[(i0+r)*DD + j]; ar[r] = br[(i0+r)*DD + j]; ah[r] = bh[(i0+r)*DD + j];
    }
    #pragma unroll 2
    for (int k = 0; k < DD; k += 4) {
        float zk[4], qk[4];
        #pragma unroll
        for (int t = 0; t < 4; ++t) { zk[t] = z[(k+t)*DD + j]; qk[t] = Q[(k+t)*DD + j]; }
        #pragma unroll
        for (int r = 0; r < 4; ++r) {
            float4 wu = *(const float4*)&sw[0][r*DD + k];
            float4 uu = *(const float4*)&sw[1][r*DD + k];
            float4 wr = *(const float4*)&sw[2][r*DD + k];
            float4 ur = *(const float4*)&sw[3][r*DD + k];
            float4 wh = *(const float4*)&sw[4][r*DD + k];
            au[r] = fmaf(wu.x, zk[0], au[r]); au[r] = fmaf(wu.y, zk[1], au[r]);
            au[r] = fmaf(wu.z, zk[2], au[r]); au[r] = fmaf(wu.w, zk[3], au[r]);
            au[r] = fmaf(uu.x, qk[0], au[r]); au[r] = fmaf(uu.y, qk[1], au[r]);
            au[r] = fmaf(uu.z, qk[2], au[r]); au[r] = fmaf(uu.w, qk[3], au[r]);
            ar[r] = fmaf(wr.x, zk[0], ar[r]); ar[r] = fmaf(wr.y, zk[1], ar[r]);
            ar[r] = fmaf(wr.z, zk[2], ar[r]); ar[r] = fmaf(wr.w, zk[3], ar[r]);
            ar[r] = fmaf(ur.x, qk[0], ar[r]); ar[r] = fmaf(ur.y, qk[1], ar[r]);
            ar[r] = fmaf(ur.z, qk[2], ar[r]); ar[r] = fmaf(ur.w, qk[3], ar[r]);
            ah[r] = fmaf(wh.x, zk[0], ah[r]); ah[r] = fmaf(wh.y, zk[1], ah[r]);
            ah[r] = fmaf(wh.z, zk[2], ah[r]); ah[r] = fmaf(wh.w, zk[3], ah[r]);
        }
    }
    #pragma unroll
    for (int r = 0; r < 4; ++r) {
        const size_t o = ((size_t)b*DD + i0 + r)*DD + j;
        float rv = 1.f / (1.f + __expf(-ar[r]));
        g_u[o]    = 1.f / (1.f + __expf(-au[r]));
        g_rq[o]   = rv * Q[(i0+r)*DD + j];
        g_preh[o] = ah[r];
    }
}

// ---------------------------------------------------------------------------
// K5: newQ = (1-u)*Q + u*tanh(preh + Uh@rq). 4 rows per block.
// ---------------------------------------------------------------------------
__global__ void __launch_bounds__(128) k_newQ(
    const float* __restrict__ prevQ, const float* __restrict__ Uh)
{
    const int i0 = blockIdx.x * 4, b = blockIdx.y, j = threadIdx.x;
    __shared__ float sw[4*DD];
    for (int e = j; e < 4*DD; e += 128) sw[e] = Uh[(i0 + (e >> 7))*DD + (e & 127)];
    __syncthreads();
    const float* rq = g_rq + (size_t)b*DD*DD;
    float a[4] = {0,0,0,0};
    #pragma unroll 2
    for (int k = 0; k < DD; k += 4) {
        float rk[4];
        #pragma unroll
        for (int t = 0; t < 4; ++t) rk[t] = rq[(k+t)*DD + j];
        #pragma unroll
        for (int r = 0; r < 4; ++r) {
            float4 uh = *(const float4*)&sw[r*DD + k];
            a[r] = fmaf(uh.x, rk[0], a[r]); a[r] = fmaf(uh.y, rk[1], a[r]);
            a[r] = fmaf(uh.z, rk[2], a[r]); a[r] = fmaf(uh.w, rk[3], a[r]);
        }
    }
    #pragma unroll
    for (int r = 0; r < 4; ++r) {
        const size_t o = ((size_t)b*DD + i0 + r)*DD + j;
        float h = tanhf(a[r] + g_preh[o]);
        float u = g_u[o];
        float q = prevQ[(size_t)b*DD*DD + (i0+r)*DD + j];
        g_newQ[o] = (1.f - u)*q + u*h;
    }
}

// ---------------------------------------------------------------------------
// K6: P = ne @ newQ. 4 rows per block, grid (16, B).
// ---------------------------------------------------------------------------
__global__ void __launch_bounds__(128) k_g1()
{
    const int r0 = blockIdx.x * 4, b = blockIdx.y, j = threadIdx.x;
    __shared__ float sa[4*DD];
    for (int e = j; e < 4*DD; e += 128) sa[e] = g_ne[(size_t)b*KT*DD + (r0 + (e >> 7))*DD + (e & 127)];
    __syncthreads();
    const float* Bm = g_newQ + (size_t)b*DD*DD;
    float acc[4] = {0,0,0,0};
    #pragma unroll 2
    for (int k = 0; k < DD; k += 4) {
        float bk[4];
        #pragma unroll
        for (int t = 0; t < 4; ++t) bk[t] = Bm[(k+t)*DD + j];
        #pragma unroll
        for (int r = 0; r < 4; ++r) {
            float4 w = *(const float4*)&sa[r*DD + k];
            acc[r] = fmaf(w.x, bk[0], acc[r]); acc[r] = fmaf(w.y, bk[1], acc[r]);
            acc[r] = fmaf(w.z, bk[2], acc[r]); acc[r] = fmaf(w.w, bk[3], acc[r]);
        }
    }
    #pragma unroll
    for (int r = 0; r < 4; ++r) g_P[(size_t)b*KT*DD + (r0+r)*DD + j] = acc[r];
}

// ---------------------------------------------------------------------------
// K7: h1 = relu(A@P) and G = h1@staticW (fused, row-local). 4 rows per block.
// ---------------------------------------------------------------------------
__global__ void __launch_bounds__(128) k_g23(const float* __restrict__ sW)
{
    const int r0 = blockIdx.x * 4, b = blockIdx.y, j = threadIdx.x;
    __shared__ float sa[4*KT];
    __shared__ float sh1[4*DD];
    for (int e = j; e < 4*KT; e += 128) sa[e] = g_A[b*KT*KT + (r0 + (e >> 6))*KT + (e & 63)];
    __syncthreads();
    const float* Bm = g_P + (size_t)b*KT*DD;
    float acc[4] = {0,0,0,0};
    #pragma unroll 2
    for (int m = 0; m < KT; m += 4) {
        float pm[4];
        #pragma unroll
        for (int t = 0; t < 4; ++t) pm[t] = Bm[(m+t)*DD + j];
        #pragma unroll
        for (int r = 0; r < 4; ++r) {
            float4 w = *(const float4*)&sa[r*KT + m];
            acc[r] = fmaf(w.x, pm[0], acc[r]); acc[r] = fmaf(w.y, pm[1], acc[r]);
            acc[r] = fmaf(w.z, pm[2], acc[r]); acc[r] = fmaf(w.w, pm[3], acc[r]);
        }
    }
    #pragma unroll
    for (int r = 0; r < 4; ++r) {
        float h = fmaxf(acc[r], 0.f);
        sh1[r*DD + j] = h;
        g_h1[(size_t)b*KT*DD + (r0+r)*DD + j] = h;
    }
    __syncthreads();
    // G = h1_local @ sW
    float g[4] = {0,0,0,0};
    #pragma unroll 2
    for (int k = 0; k < DD; k += 4) {
        float wk[4];
        #pragma unroll
        for (int t = 0; t < 4; ++t) wk[t] = sW[(k+t)*DD + j];
        #pragma unroll
        for (int r = 0; r < 4; ++r) {
            float4 w = *(const float4*)&sh1[r*DD + k];
            g[r] = fmaf(w.x, wk[0], g[r]); g[r] = fmaf(w.y, wk[1], g[r]);
            g[r] = fmaf(w.z, wk[2], g[r]); g[r] = fmaf(w.w, wk[3], g[r]);
        }
    }
    #pragma unroll
    for (int r = 0; r < 4; ++r) g_G[(size_t)b*KT*DD + (r0+r)*DD + j] = g[r];
}

// ---------------------------------------------------------------------------
// K8: out = (h1 + relu(A @ G)) / 2
// ---------------------------------------------------------------------------
__global__ void __launch_bounds__(128) k_g4(float* __restrict__ out)
{
    const int r0 = blockIdx.x * 4, b = blockIdx.y, j = threadIdx.x;
    __shared__ float sa[4*KT];
    for (int e = j; e < 4*KT; e += 128) sa[e] = g_A[b*KT*KT + (r0 + (e >> 6))*KT + (e & 63)];
    __syncthreads();
    const float* Bm = g_G + (size_t)b*KT*DD;
    float acc[4] = {0,0,0,0};
    #pragma unroll 2
    for (int m = 0; m < KT; m += 4) {
        float pm[4];
        #pragma unroll
        for (int t = 0; t < 4; ++t) pm[t] = Bm[(m+t)*DD + j];
        #pragma unroll
        for (int r = 0; r < 4; ++r) {
            float4 w = *(const float4*)&sa[r*KT + m];
            acc[r] = fmaf(w.x, pm[0], acc[r]); acc[r] = fmaf(w.y, pm[1], acc[r]);
            acc[r] = fmaf(w.z, pm[2], acc[r]); acc[r] = fmaf(w.w, pm[3], acc[r]);
        }
    }
    #pragma unroll
    for (int r = 0; r < 4; ++r) {
        float h1v = g_h1[(size_t)b*KT*DD + (r0+r)*DD + j];
        out[(size_t)b*KT*DD + (r0+r)*DD + j] = (h1v + fmaxf(acc[r], 0.f)) * 0.5f;
    }
}

// ---------------------------------------------------------------------------
extern "C" void kernel_launch(void* const* d_in, const int* in_sizes, int n_in,
                              void* d_out, int out_size)
{
    const float* Ahat      = (const float*)d_in[0];
    const float* node_embs = (const float*)d_in[1];
    const float* ht        = (const float*)d_in[3];
    const float* prevQ     = (const float*)d_in[4];
    const float* W_map     = (const float*)d_in[5];
    const float* b_map     = (const float*)d_in[6];
    const float* Wu        = (const float*)d_in[7];
    const float* Uu        = (const float*)d_in[8];
    const float* bu        = (const float*)d_in[9];
    const float* Wr        = (const float*)d_in[10];
    const float* Ur        = (const float*)d_in[11];
    const float* br        = (const float*)d_in[12];
    const float* Wh        = (const float*)d_in[13];
    const float* Uh        = (const float*)d_in[14];
    const float* bh        = (const float*)d_in[15];
    const float* sW        = (const float*)d_in[16];
    float* out = (float*)d_out;

    k_scorer<<<BB, 512>>>(ht, W_map, b_map, out);
    k_scores<<<dim3(32, BB), 128>>>(node_embs);
    k_topk_gather<<<BB, 512, NN * sizeof(unsigned long long)>>>(node_embs, Ahat, out);
    k_gates<<<dim3(32, BB), 128>>>(prevQ, Wu, Uu, bu, Wr, Ur, br, Wh, bh);
    k_newQ<<<dim3(32, BB), 128>>>(prevQ, Uh);
    k_g1<<<dim3(16, BB), 128>>>();
    k_g23<<<dim3(16, BB), 128>>>(sW);
    k_g4<<<dim3(16, BB), 128>>>(out);
}

// round 4
// speedup vs baseline: 2.5798x; 1.1374x over previous
#include <cuda_runtime.h>
#include <math.h>

#define BB 8
#define NN 4096
#define DD 128
#define KT 64
#define RR 512

// Output layout: concat(out[B,K,D], policy[B], scorer[B,D], entropy[B])
#define OFF_POL     (BB*KT*DD)
#define OFF_SCORER  (OFF_POL + BB)
#define OFF_ENT     (OFF_SCORER + BB*DD)

typedef unsigned long long u64;

__device__ __forceinline__ u64 pk2(float lo, float hi) {
    u64 r; asm("mov.b64 %0,{%1,%2};" : "=l"(r) : "f"(lo), "f"(hi)); return r;
}
__device__ __forceinline__ void up2(u64 v, float& lo, float& hi) {
    asm("mov.b64 {%0,%1},%2;" : "=f"(lo), "=f"(hi) : "l"(v));
}
__device__ __forceinline__ u64 ffma2(u64 a, u64 b, u64 c) {
    u64 d; asm("fma.rn.f32x2 %0,%1,%2,%3;" : "=l"(d) : "l"(a), "l"(b), "l"(c)); return d;
}
__device__ __forceinline__ float sigf(float x) { return 1.f / (1.f + __expf(-x)); }

// Device scratch
__device__ float g_scorer_n[BB*DD];
__device__ float g_scores[BB*NN];
__device__ float g_z[BB*DD*DD];       // z_topk [b][d][i]
__device__ float g_ne[BB*KT*DD];
__device__ float g_A[BB*KT*KT];
__device__ float g_u[BB*DD*DD];
__device__ float g_rq[BB*DD*DD];      // reset * prevQ
__device__ float g_preh[BB*DD*DD];    // Wh@z + bh
__device__ float g_newQ[BB*DD*DD];
__device__ float g_P[BB*KT*DD];
__device__ float g_h1[BB*KT*DD];
__device__ float g_G[BB*KT*DD];

// ---------------------------------------------------------------------------
// K1: scorer
// ---------------------------------------------------------------------------
__global__ void __launch_bounds__(512) k_scorer(
    const float* __restrict__ ht, const float* __restrict__ W_map,
    const float* __restrict__ b_map, float* __restrict__ out)
{
    const int b = blockIdx.x, tid = threadIdx.x;
    __shared__ float sht[RR];
    __shared__ float part[4][DD];
    __shared__ float ssc[DD];
    __shared__ float s_inv;
    sht[tid] = ht[b*RR + tid];
    __syncthreads();
    const int d = tid & 127, rq = tid >> 7;
    float acc = 0.f;
    const int r0 = rq * 128;
    #pragma unroll 4
    for (int r = 0; r < 128; ++r) acc = fmaf(sht[r0 + r], W_map[(r0 + r)*DD + d], acc);
    part[rq][d] = acc;
    __syncthreads();
    if (tid < DD) {
        float s = part[0][tid] + part[1][tid] + part[2][tid] + part[3][tid] + b_map[tid];
        float sc = tanhf(s);
        ssc[tid] = sc;
        out[OFF_SCORER + b*DD + tid] = sc;
    }
    __syncthreads();
    if (tid < 32) {
        float s = 0.f;
        for (int i = tid; i < DD; i += 32) s += ssc[i]*ssc[i];
        #pragma unroll
        for (int o = 16; o; o >>= 1) s += __shfl_xor_sync(0xffffffffu, s, o);
        if (tid == 0) s_inv = 1.0f / sqrtf(s);
    }
    __syncthreads();
    if (tid < DD) g_scorer_n[b*DD + tid] = ssc[tid] * s_inv;
}

// ---------------------------------------------------------------------------
// K2: scores (warp per node, float4)
// ---------------------------------------------------------------------------
__global__ void __launch_bounds__(128) k_scores(const float* __restrict__ node_embs)
{
    const int b = blockIdx.y, base = blockIdx.x * 128, tid = threadIdx.x;
    const int warp = tid >> 5, lane = tid & 31;
    __shared__ float4 ssc[32];
    if (tid < 32) ssc[tid] = ((const float4*)(g_scorer_n + b*DD))[tid];
    __syncthreads();
    const float4 sv = ssc[lane];
    #pragma unroll
    for (int t = 0; t < 32; t += 4) {
        const int n0 = base + warp * 32 + t;
        float a[4];
        #pragma unroll
        for (int q = 0; q < 4; ++q) {
            const float4 v = ((const float4*)(node_embs + ((size_t)(b*NN + n0 + q))*DD))[lane];
            a[q] = v.x*sv.x + v.y*sv.y + v.z*sv.z + v.w*sv.w;
        }
        #pragma unroll
        for (int o = 16; o; o >>= 1) {
            #pragma unroll
            for (int q = 0; q < 4; ++q) a[q] += __shfl_xor_sync(0xffffffffu, a[q], o);
        }
        if (lane < 4) g_scores[b*NN + n0 + lane] = a[lane];
    }
}

// ---------------------------------------------------------------------------
// K3: softmax stats + bitonic top-64 + gather (A, z, ne)
// ---------------------------------------------------------------------------
__global__ void __launch_bounds__(512) k_topk_gather(
    const float* __restrict__ node_embs, const float* __restrict__ Ahat,
    float* __restrict__ out)
{
    extern __shared__ unsigned long long skey[];
    const int b = blockIdx.x, tid = threadIdx.x;
    const int warp = tid >> 5, lane = tid & 31;
    __shared__ float sred[16], sred2[16];
    __shared__ float s_M, s_logZ;
    __shared__ int   s_idx[KT];
    __shared__ float s_t[KT];
    __shared__ float s_v[KT];
    __shared__ float s_di[KT];

    float lmax = -INFINITY;
    for (int n = tid; n < NN; n += 512) {
        float s = g_scores[b*NN + n];
        lmax = fmaxf(lmax, s);
        unsigned u = __float_as_uint(s);
        unsigned m = (u & 0x80000000u) ? ~u : (u | 0x80000000u);
        skey[n] = ((unsigned long long)m << 32) | (unsigned)(NN - 1 - n);
    }
    #pragma unroll
    for (int o = 16; o; o >>= 1) lmax = fmaxf(lmax, __shfl_xor_sync(0xffffffffu, lmax, o));
    if (lane == 0) sred[warp] = lmax;
    __syncthreads();
    if (tid == 0) { float m = -INFINITY; for (int w = 0; w < 16; ++w) m = fmaxf(m, sred[w]); s_M = m; }
    __syncthreads();
    const float M = s_M;

    float s1 = 0.f, s2 = 0.f;
    for (int n = tid; n < NN; n += 512) {
        float s = g_scores[b*NN + n];
        float e = __expf(s - M);
        s1 += e; s2 = fmaf(s, e, s2);
    }
    #pragma unroll
    for (int o = 16; o; o >>= 1) {
        s1 += __shfl_xor_sync(0xffffffffu, s1, o);
        s2 += __shfl_xor_sync(0xffffffffu, s2, o);
    }
    if (lane == 0) { sred[warp] = s1; sred2[warp] = s2; }
    __syncthreads();
    if (tid == 0) {
        float S1 = 0.f, S2 = 0.f;
        for (int w = 0; w < 16; ++w) { S1 += sred[w]; S2 += sred2[w]; }
        float logZ = M + logf(S1);
        s_logZ = logZ;
        out[OFF_ENT + b] = logZ - S2 / S1;
    }

    for (int k = 2; k <= NN; k <<= 1) {
        for (int j = k >> 1; j > 0; j >>= 1) {
            __syncthreads();
            #pragma unroll
            for (int p = 0; p < 8; ++p) {
                const int i = tid + p * 512;
                const int l = i ^ j;
                if (l > i) {
                    unsigned long long a = skey[i], c = skey[l];
                    bool desc = ((i & k) == 0);
                    if (desc ? (a < c) : (a > c)) { skey[i] = c; skey[l] = a; }
                }
            }
        }
    }
    __syncthreads();

    if (tid < KT) {
        unsigned long long kk = skey[tid];
        int n = NN - 1 - (int)(kk & 0xFFFu);
        unsigned m = (unsigned)(kk >> 32);
        unsigned u = (m & 0x80000000u) ? (m ^ 0x80000000u) : ~m;
        float s = __uint_as_float(u);
        s_idx[tid] = n; s_t[tid] = tanhf(s); s_v[tid] = s;
    }
    __syncthreads();
    if (tid == 0) {
        float sum = 0.f;
        for (int i = 0; i < KT; ++i) sum += s_v[i];
        out[OFF_POL + b] = sum * (1.f/KT) - s_logZ;
    }

    float* sA = (float*)skey;
    for (int e = tid; e < KT*KT; e += 512) {
        int i = e >> 6, j = e & 63;
        sA[e] = Ahat[(size_t)b*NN*NN + (size_t)s_idx[i]*NN + s_idx[j]];
    }
    __syncthreads();
    if (tid < KT) {
        float s = 0.f;
        for (int i = 0; i < KT; ++i) s += sA[i*KT + tid];
        s_di[tid] = 1.0f / sqrtf(s);
    }
    __syncthreads();
    for (int e = tid; e < KT*KT; e += 512) {
        int i = e >> 6, j = e & 63;
        g_A[b*KT*KT + e] = s_di[j] * sA[e] * s_di[i];
    }

    for (int i = warp; i < DD; i += 16) {
        int k = i & (KT - 1);
        const float* e = node_embs + ((size_t)(b*NN + s_idx[k]))*DD;
        float tv = s_t[k];
        for (int d = lane; d < DD; d += 32) {
            float val = e[d];
            g_z[((size_t)b*DD + d)*DD + i] = val * tv;
            if (i < KT) g_ne[(b*KT + i)*DD + d] = val;
        }
    }
}

// ---------------------------------------------------------------------------
// K4: fused u / rq / preh. Warp-per-row, f32x2, smem-staged z/Q.
// grid (32, B), 128 threads, 4 rows/block.
// ---------------------------------------------------------------------------
__global__ void __launch_bounds__(128) k_gates(
    const float* __restrict__ prevQ,
    const float* __restrict__ Wu, const float* __restrict__ Uu, const float* __restrict__ bu,
    const float* __restrict__ Wr, const float* __restrict__ Ur, const float* __restrict__ br,
    const float* __restrict__ Wh, const float* __restrict__ bh)
{
    extern __shared__ char smraw[];
    u64*    swt = (u64*)smraw;                         // 5*512 packed weights
    float4* sz  = (float4*)(smraw + 5*512*8);          // 2 bufs * 512
    float4* sq  = sz + 2*512;                          // 2 bufs * 512
    const int b = blockIdx.y, i0 = blockIdx.x*4;
    const int tid = threadIdx.x, w = tid>>5, lane = tid&31;
    const int i = i0 + w;

    for (int e = tid; e < 4*DD; e += 128) {
        int r = e>>7, k = e&127;
        float a;
        a = Wu[(i0+r)*DD+k]; swt[0*512+e] = pk2(a,a);
        a = Uu[(i0+r)*DD+k]; swt[1*512+e] = pk2(a,a);
        a = Wr[(i0+r)*DD+k]; swt[2*512+e] = pk2(a,a);
        a = Ur[(i0+r)*DD+k]; swt[3*512+e] = pk2(a,a);
        a = Wh[(i0+r)*DD+k]; swt[4*512+e] = pk2(a,a);
    }
    const float* z = g_z + (size_t)b*DD*DD;
    const float* Q = prevQ + (size_t)b*DD*DD;

    float4 rz[4], rqv[4];
    #pragma unroll
    for (int p = 0; p < 4; ++p) {
        int e = tid + 128*p;
        rz[p]  = ((const float4*)(z + (size_t)(e>>5)*DD))[e&31];
        rqv[p] = ((const float4*)(Q + (size_t)(e>>5)*DD))[e&31];
    }
    #pragma unroll
    for (int p = 0; p < 4; ++p) { int e = tid+128*p; sz[e]=rz[p]; sq[e]=rqv[p]; }
    __syncthreads();

    u64 au0,au1,ar0,ar1,ah0,ah1;
    {
        float4 v;
        v = *(const float4*)&bu[i*DD + 4*lane]; au0=pk2(v.x,v.y); au1=pk2(v.z,v.w);
        v = *(const float4*)&br[i*DD + 4*lane]; ar0=pk2(v.x,v.y); ar1=pk2(v.z,v.w);
        v = *(const float4*)&bh[i*DD + 4*lane]; ah0=pk2(v.x,v.y); ah1=pk2(v.z,v.w);
    }

    for (int c = 0; c < 8; ++c) {
        const int cb = c & 1, nb = cb ^ 1;
        if (c < 7) {
            #pragma unroll
            for (int p = 0; p < 4; ++p) {
                int e = tid + 128*p;
                int row = (c+1)*16 + (e>>5);
                rz[p]  = ((const float4*)(z + (size_t)row*DD))[e&31];
                rqv[p] = ((const float4*)(Q + (size_t)row*DD))[e&31];
            }
        }
        const ulonglong2* zz = (const ulonglong2*)(sz + cb*512);
        const ulonglong2* qq = (const ulonglong2*)(sq + cb*512);
        const u64* w0 = swt + 0*512 + w*128 + c*16;
        const u64* w1 = swt + 1*512 + w*128 + c*16;
        const u64* w2 = swt + 2*512 + w*128 + c*16;
        const u64* w3 = swt + 3*512 + w*128 + c*16;
        const u64* w4 = swt + 4*512 + w*128 + c*16;
        #pragma unroll
        for (int kk = 0; kk < 16; ++kk) {
            ulonglong2 zv = zz[kk*32 + lane];
            ulonglong2 qv = qq[kk*32 + lane];
            u64 wu = w0[kk], uu = w1[kk], wr = w2[kk], ur = w3[kk], wh = w4[kk];
            au0=ffma2(wu,zv.x,au0); au1=ffma2(wu,zv.y,au1);
            au0=ffma2(uu,qv.x,au0); au1=ffma2(uu,qv.y,au1);
            ar0=ffma2(wr,zv.x,ar0); ar1=ffma2(wr,zv.y,ar1);
            ar0=ffma2(ur,qv.x,ar0); ar1=ffma2(ur,qv.y,ar1);
            ah0=ffma2(wh,zv.x,ah0); ah1=ffma2(wh,zv.y,ah1);
        }
        if (c < 7) {
            #pragma unroll
            for (int p = 0; p < 4; ++p) { int e = tid+128*p; sz[nb*512+e]=rz[p]; sq[nb*512+e]=rqv[p]; }
        }
        __syncthreads();
    }

    float f0,f1,f2,f3;
    const size_t o = ((size_t)b*DD + i)*DD + 4*lane;
    up2(au0,f0,f1); up2(au1,f2,f3);
    *(float4*)&g_u[o] = make_float4(sigf(f0),sigf(f1),sigf(f2),sigf(f3));
    up2(ar0,f0,f1); up2(ar1,f2,f3);
    float4 q4 = *(const float4*)&Q[(size_t)i*DD + 4*lane];
    *(float4*)&g_rq[o] = make_float4(sigf(f0)*q4.x, sigf(f1)*q4.y, sigf(f2)*q4.z, sigf(f3)*q4.w);
    up2(ah0,f0,f1); up2(ah1,f2,f3);
    *(float4*)&g_preh[o] = make_float4(f0,f1,f2,f3);
}

// ---------------------------------------------------------------------------
// K5: newQ = (1-u)*Q + u*tanh(preh + Uh@rq). Warp-per-row, staged rq.
// ---------------------------------------------------------------------------
__global__ void __launch_bounds__(128) k_newQ(
    const float* __restrict__ prevQ, const float* __restrict__ Uh)
{
    __shared__ u64 swt[4*DD];
    __shared__ float4 sb[2*512];
    const int b = blockIdx.y, i0 = blockIdx.x*4;
    const int tid = threadIdx.x, w = tid>>5, lane = tid&31;
    const int i = i0 + w;
    for (int e = tid; e < 4*DD; e += 128) {
        float a = Uh[(i0 + (e>>7))*DD + (e&127)]; swt[e] = pk2(a,a);
    }
    const float* Bm = g_rq + (size_t)b*DD*DD;
    float4 rb[4];
    #pragma unroll
    for (int p = 0; p < 4; ++p) { int e = tid+128*p; rb[p] = ((const float4*)(Bm + (size_t)(e>>5)*DD))[e&31]; }
    #pragma unroll
    for (int p = 0; p < 4; ++p) { int e = tid+128*p; sb[e]=rb[p]; }
    __syncthreads();
    u64 a0 = 0, a1 = 0;
    for (int c = 0; c < 8; ++c) {
        const int cb = c & 1, nb = cb ^ 1;
        if (c < 7) {
            #pragma unroll
            for (int p = 0; p < 4; ++p) {
                int e = tid + 128*p;
                rb[p] = ((const float4*)(Bm + (size_t)((c+1)*16 + (e>>5))*DD))[e&31];
            }
        }
        const ulonglong2* bb = (const ulonglong2*)(sb + cb*512);
        const u64* wp = swt + w*128 + c*16;
        #pragma unroll
        for (int kk = 0; kk < 16; ++kk) {
            ulonglong2 bv = bb[kk*32 + lane];
            u64 wt = wp[kk];
            a0 = ffma2(wt, bv.x, a0); a1 = ffma2(wt, bv.y, a1);
        }
        if (c < 7) {
            #pragma unroll
            for (int p = 0; p < 4; ++p) { int e = tid+128*p; sb[nb*512+e]=rb[p]; }
        }
        __syncthreads();
    }
    float f0,f1,f2,f3; up2(a0,f0,f1); up2(a1,f2,f3);
    const size_t o = ((size_t)b*DD + i)*DD + 4*lane;
    float4 ph = *(const float4*)&g_preh[o];
    float4 uv = *(const float4*)&g_u[o];
    float4 q4 = *(const float4*)&prevQ[(size_t)b*DD*DD + i*DD + 4*lane];
    float h0 = tanhf(f0+ph.x), h1 = tanhf(f1+ph.y), h2 = tanhf(f2+ph.z), h3 = tanhf(f3+ph.w);
    *(float4*)&g_newQ[o] = make_float4(
        (1.f-uv.x)*q4.x + uv.x*h0, (1.f-uv.y)*q4.y + uv.y*h1,
        (1.f-uv.z)*q4.z + uv.z*h2, (1.f-uv.w)*q4.w + uv.w*h3);
}

// ---------------------------------------------------------------------------
// K6: P = ne @ newQ. Warp-per-row, staged newQ. grid (16, B).
// ---------------------------------------------------------------------------
__global__ void __launch_bounds__(128) k_g1()
{
    __shared__ u64 swt[4*DD];
    __shared__ float4 sb[2*512];
    const int b = blockIdx.y, i0 = blockIdx.x*4;
    const int tid = threadIdx.x, w = tid>>5, lane = tid&31;
    const int i = i0 + w;
    for (int e = tid; e < 4*DD; e += 128) {
        float a = g_ne[((size_t)b*KT + i0 + (e>>7))*DD + (e&127)]; swt[e] = pk2(a,a);
    }
    const float* Bm = g_newQ + (size_t)b*DD*DD;
    float4 rb[4];
    #pragma unroll
    for (int p = 0; p < 4; ++p) { int e = tid+128*p; rb[p] = ((const float4*)(Bm + (size_t)(e>>5)*DD))[e&31]; }
    #pragma unroll
    for (int p = 0; p < 4; ++p) { int e = tid+128*p; sb[e]=rb[p]; }
    __syncthreads();
    u64 a0 = 0, a1 = 0;
    for (int c = 0; c < 8; ++c) {
        const int cb = c & 1, nb = cb ^ 1;
        if (c < 7) {
            #pragma unroll
            for (int p = 0; p < 4; ++p) {
                int e = tid + 128*p;
                rb[p] = ((const float4*)(Bm + (size_t)((c+1)*16 + (e>>5))*DD))[e&31];
            }
        }
        const ulonglong2* bb = (const ulonglong2*)(sb + cb*512);
        const u64* wp = swt + w*128 + c*16;
        #pragma unroll
        for (int kk = 0; kk < 16; ++kk) {
            ulonglong2 bv = bb[kk*32 + lane];
            u64 wt = wp[kk];
            a0 = ffma2(wt, bv.x, a0); a1 = ffma2(wt, bv.y, a1);
        }
        if (c < 7) {
            #pragma unroll
            for (int p = 0; p < 4; ++p) { int e = tid+128*p; sb[nb*512+e]=rb[p]; }
        }
        __syncthreads();
    }
    float f0,f1,f2,f3; up2(a0,f0,f1); up2(a1,f2,f3);
    *(float4*)&g_P[((size_t)b*KT + i)*DD + 4*lane] = make_float4(f0,f1,f2,f3);
}

// ---------------------------------------------------------------------------
// K7: h1 = relu(A@P) then G = h1@staticW (fused). grid (16, B).
// ---------------------------------------------------------------------------
__global__ void __launch_bounds__(128) k_g23(const float* __restrict__ sW)
{
    __shared__ u64 sAW[4*KT];
    __shared__ u64 sh1p[4*DD];
    __shared__ float buf[KT*DD];   // 32KB: P (phase1), then sW chunks (phase2, 2 halves)
    const int b = blockIdx.y, i0 = blockIdx.x*4;
    const int tid = threadIdx.x, w = tid>>5, lane = tid&31;
    const int i = i0 + w;
    for (int e = tid; e < 4*KT; e += 128) {
        float a = g_A[b*KT*KT + (i0 + (e>>6))*KT + (e&63)]; sAW[e] = pk2(a,a);
    }
    float4* bf4 = (float4*)buf;
    const float4* Psrc = (const float4*)(g_P + (size_t)b*KT*DD);
    for (int e = tid; e < 2048; e += 128) bf4[e] = Psrc[e];
    __syncthreads();
    u64 a0 = 0, a1 = 0;
    {
        const ulonglong2* bb = (const ulonglong2*)buf;
        const u64* wp = sAW + w*KT;
        #pragma unroll 8
        for (int k = 0; k < KT; ++k) {
            ulonglong2 bv = bb[k*32 + lane];
            u64 wt = wp[k];
            a0 = ffma2(wt, bv.x, a0); a1 = ffma2(wt, bv.y, a1);
        }
    }
    float f0,f1,f2,f3; up2(a0,f0,f1); up2(a1,f2,f3);
    f0 = fmaxf(f0,0.f); f1 = fmaxf(f1,0.f); f2 = fmaxf(f2,0.f); f3 = fmaxf(f3,0.f);
    *(float4*)&g_h1[((size_t)b*KT + i)*DD + 4*lane] = make_float4(f0,f1,f2,f3);
    sh1p[w*DD + 4*lane + 0] = pk2(f0,f0);
    sh1p[w*DD + 4*lane + 1] = pk2(f1,f1);
    sh1p[w*DD + 4*lane + 2] = pk2(f2,f2);
    sh1p[w*DD + 4*lane + 3] = pk2(f3,f3);
    __syncthreads();

    // Phase 2: G = h1 @ sW, sW staged in 32-row chunks (2 halves of buf)
    float4 rb[8];
    #pragma unroll
    for (int p = 0; p < 8; ++p) {
        int e = tid + 128*p;
        rb[p] = ((const float4*)(sW + (size_t)(e>>5)*DD))[e&31];
    }
    #pragma unroll
    for (int p = 0; p < 8; ++p) { int e = tid+128*p; bf4[e] = rb[p]; }
    __syncthreads();
    u64 g0 = 0, g1v = 0;
    for (int c = 0; c < 4; ++c) {
        const int cb = c & 1, nb = cb ^ 1;
        if (c < 3) {
            #pragma unroll
            for (int p = 0; p < 8; ++p) {
                int e = tid + 128*p;
                rb[p] = ((const float4*)(sW + (size_t)((c+1)*32 + (e>>5))*DD))[e&31];
            }
        }
        const ulonglong2* bb = (const ulonglong2*)(buf + cb*4096);
        const u64* hp = sh1p + w*DD + c*32;
        #pragma unroll
        for (int kk = 0; kk < 32; ++kk) {
            ulonglong2 bv = bb[kk*32 + lane];
            u64 wt = hp[kk];
            g0 = ffma2(wt, bv.x, g0); g1v = ffma2(wt, bv.y, g1v);
        }
        if (c < 3) {
            #pragma unroll
            for (int p = 0; p < 8; ++p) { int e = tid+128*p; bf4[nb*1024 + e] = rb[p]; }
        }
        __syncthreads();
    }
    up2(g0,f0,f1); up2(g1v,f2,f3);
    *(float4*)&g_G[((size_t)b*KT + i)*DD + 4*lane] = make_float4(f0,f1,f2,f3);
}

// ---------------------------------------------------------------------------
// K8: out = (h1 + relu(A @ G)) / 2. grid (16, B).
// ---------------------------------------------------------------------------
__global__ void __launch_bounds__(128) k_g4(float* __restrict__ out)
{
    __shared__ u64 sAW[4*KT];
    __shared__ float buf[KT*DD];
    const int b = blockIdx.y, i0 = blockIdx.x*4;
    const int tid = threadIdx.x, w = tid>>5, lane = tid&31;
    const int i = i0 + w;
    for (int e = tid; e < 4*KT; e += 128) {
        float a = g_A[b*KT*KT + (i0 + (e>>6))*KT + (e&63)]; sAW[e] = pk2(a,a);
    }
    float4* bf4 = (float4*)buf;
    const float4* Gsrc = (const float4*)(g_G + (size_t)b*KT*DD);
    for (int e = tid; e < 2048; e += 128) bf4[e] = Gsrc[e];
    __syncthreads();
    u64 a0 = 0, a1 = 0;
    const ulonglong2* bb = (const ulonglong2*)buf;
    const u64* wp = sAW + w*KT;
    #pragma unroll 8
    for (int k = 0; k < KT; ++k) {
        ulonglong2 bv = bb[k*32 + lane];
        u64 wt = wp[k];
        a0 = ffma2(wt, bv.x, a0); a1 = ffma2(wt, bv.y, a1);
    }
    float f0,f1,f2,f3; up2(a0,f0,f1); up2(a1,f2,f3);
    float4 h1v = *(const float4*)&g_h1[((size_t)b*KT + i)*DD + 4*lane];
    *(float4*)&out[((size_t)b*KT + i)*DD + 4*lane] = make_float4(
        (h1v.x + fmaxf(f0,0.f))*0.5f, (h1v.y + fmaxf(f1,0.f))*0.5f,
        (h1v.z + fmaxf(f2,0.f))*0.5f, (h1v.w + fmaxf(f3,0.f))*0.5f);
}

// ---------------------------------------------------------------------------
extern "C" void kernel_launch(void* const* d_in, const int* in_sizes, int n_in,
                              void* d_out, int out_size)
{
    const float* Ahat      = (const float*)d_in[0];
    const float* node_embs = (const float*)d_in[1];
    const float* ht        = (const float*)d_in[3];
    const float* prevQ     = (const float*)d_in[4];
    const float* W_map     = (const float*)d_in[5];
    const float* b_map     = (const float*)d_in[6];
    const float* Wu        = (const float*)d_in[7];
    const float* Uu        = (const float*)d_in[8];
    const float* bu        = (const float*)d_in[9];
    const float* Wr        = (const float*)d_in[10];
    const float* Ur        = (const float*)d_in[11];
    const float* br        = (const float*)d_in[12];
    const float* Wh        = (const float*)d_in[13];
    const float* Uh        = (const float*)d_in[14];
    const float* bh        = (const float*)d_in[15];
    const float* sW        = (const float*)d_in[16];
    float* out = (float*)d_out;

    const int gates_smem = 5*512*8 + 2*512*16 + 2*512*16;   // 53248 B
    cudaFuncSetAttribute(k_gates, cudaFuncAttributeMaxDynamicSharedMemorySize, gates_smem);

    k_scorer<<<BB, 512>>>(ht, W_map, b_map, out);
    k_scores<<<dim3(32, BB), 128>>>(node_embs);
    k_topk_gather<<<BB, 512, NN * sizeof(unsigned long long)>>>(node_embs, Ahat, out);
    k_gates<<<dim3(32, BB), 128, gates_smem>>>(prevQ, Wu, Uu, bu, Wr, Ur, br, Wh, bh);
    k_newQ<<<dim3(32, BB), 128>>>(prevQ, Uh);
    k_g1<<<dim3(16, BB), 128>>>();
    k_g23<<<dim3(16, BB), 128>>>(sW);
    k_g4<<<dim3(16, BB), 128>>>(out);
}

// round 5
// speedup vs baseline: 3.3963x; 1.3165x over previous
#include <cuda_runtime.h>
#include <math.h>

#define BB 8
#define NN 4096
#define DD 128
#define KT 64
#define RR 512

// Output layout: concat(out[B,K,D], policy[B], scorer[B,D], entropy[B])
#define OFF_POL     (BB*KT*DD)
#define OFF_SCORER  (OFF_POL + BB)
#define OFF_ENT     (OFF_SCORER + BB*DD)

typedef unsigned long long u64;

__device__ __forceinline__ u64 pk2(float lo, float hi) {
    u64 r; asm("mov.b64 %0,{%1,%2};" : "=l"(r) : "f"(lo), "f"(hi)); return r;
}
__device__ __forceinline__ void up2(u64 v, float& lo, float& hi) {
    asm("mov.b64 {%0,%1},%2;" : "=f"(lo), "=f"(hi) : "l"(v));
}
__device__ __forceinline__ u64 ffma2(u64 a, u64 b, u64 c) {
    u64 d; asm("fma.rn.f32x2 %0,%1,%2,%3;" : "=l"(d) : "l"(a), "l"(b), "l"(c)); return d;
}
__device__ __forceinline__ u64 padd2(u64 a, u64 b) {
    u64 d; asm("add.rn.f32x2 %0,%1,%2;" : "=l"(d) : "l"(a), "l"(b)); return d;
}
__device__ __forceinline__ float sigf(float x) { return 1.f / (1.f + __expf(-x)); }

// Device scratch
__device__ float g_scorer_n[BB*DD];
__device__ float g_scores[BB*NN];
__device__ float g_z[BB*DD*DD];       // z_topk [b][d][i]
__device__ float g_ne[BB*KT*DD];
__device__ float g_A[BB*KT*KT];
__device__ float g_u[BB*DD*DD];
__device__ float g_rq[BB*DD*DD];      // reset * prevQ
__device__ float g_preh[BB*DD*DD];    // Wh@z + bh
__device__ float g_newQ[BB*DD*DD];
__device__ float g_P[BB*KT*DD];
__device__ float g_h1[BB*KT*DD];
__device__ float g_G[BB*KT*DD];

// ---------------------------------------------------------------------------
// K1: scorer
// ---------------------------------------------------------------------------
__global__ void __launch_bounds__(512) k_scorer(
    const float* __restrict__ ht, const float* __restrict__ W_map,
    const float* __restrict__ b_map, float* __restrict__ out)
{
    const int b = blockIdx.x, tid = threadIdx.x;
    __shared__ float sht[RR];
    __shared__ float part[4][DD];
    __shared__ float ssc[DD];
    __shared__ float s_inv;
    sht[tid] = ht[b*RR + tid];
    __syncthreads();
    const int d = tid & 127, rq = tid >> 7;
    float acc = 0.f;
    const int r0 = rq * 128;
    #pragma unroll 4
    for (int r = 0; r < 128; ++r) acc = fmaf(sht[r0 + r], W_map[(r0 + r)*DD + d], acc);
    part[rq][d] = acc;
    __syncthreads();
    if (tid < DD) {
        float s = part[0][tid] + part[1][tid] + part[2][tid] + part[3][tid] + b_map[tid];
        float sc = tanhf(s);
        ssc[tid] = sc;
        out[OFF_SCORER + b*DD + tid] = sc;
    }
    __syncthreads();
    if (tid < 32) {
        float s = 0.f;
        for (int i = tid; i < DD; i += 32) s += ssc[i]*ssc[i];
        #pragma unroll
        for (int o = 16; o; o >>= 1) s += __shfl_xor_sync(0xffffffffu, s, o);
        if (tid == 0) s_inv = 1.0f / sqrtf(s);
    }
    __syncthreads();
    if (tid < DD) g_scorer_n[b*DD + tid] = ssc[tid] * s_inv;
}

// ---------------------------------------------------------------------------
// K2: scores (warp per node, float4)
// ---------------------------------------------------------------------------
__global__ void __launch_bounds__(128) k_scores(const float* __restrict__ node_embs)
{
    const int b = blockIdx.y, base = blockIdx.x * 128, tid = threadIdx.x;
    const int warp = tid >> 5, lane = tid & 31;
    __shared__ float4 ssc[32];
    if (tid < 32) ssc[tid] = ((const float4*)(g_scorer_n + b*DD))[tid];
    __syncthreads();
    const float4 sv = ssc[lane];
    #pragma unroll
    for (int t = 0; t < 32; t += 4) {
        const int n0 = base + warp * 32 + t;
        float a[4];
        #pragma unroll
        for (int q = 0; q < 4; ++q) {
            const float4 v = ((const float4*)(node_embs + ((size_t)(b*NN + n0 + q))*DD))[lane];
            a[q] = v.x*sv.x + v.y*sv.y + v.z*sv.z + v.w*sv.w;
        }
        #pragma unroll
        for (int o = 16; o; o >>= 1) {
            #pragma unroll
            for (int q = 0; q < 4; ++q) a[q] += __shfl_xor_sync(0xffffffffu, a[q], o);
        }
        if (lane < 4) g_scores[b*NN + n0 + lane] = a[lane];
    }
}

// ---------------------------------------------------------------------------
// K3: softmax stats + partial-bitonic top-64 + gather (A, z, ne)
// ---------------------------------------------------------------------------
__global__ void __launch_bounds__(512) k_topk_gather(
    const float* __restrict__ node_embs, const float* __restrict__ Ahat,
    float* __restrict__ out)
{
    extern __shared__ unsigned long long skey[];
    const int b = blockIdx.x, tid = threadIdx.x;
    const int warp = tid >> 5, lane = tid & 31;
    __shared__ float sred[16], sred2[16];
    __shared__ float s_M, s_logZ;
    __shared__ int   s_idx[KT];
    __shared__ float s_t[KT];
    __shared__ float s_v[KT];
    __shared__ float s_di[KT];

    float lmax = -INFINITY;
    for (int n = tid; n < NN; n += 512) {
        float s = g_scores[b*NN + n];
        lmax = fmaxf(lmax, s);
        unsigned u = __float_as_uint(s);
        unsigned m = (u & 0x80000000u) ? ~u : (u | 0x80000000u);
        skey[n] = ((unsigned long long)m << 32) | (unsigned)(NN - 1 - n);
    }
    #pragma unroll
    for (int o = 16; o; o >>= 1) lmax = fmaxf(lmax, __shfl_xor_sync(0xffffffffu, lmax, o));
    if (lane == 0) sred[warp] = lmax;
    __syncthreads();
    if (tid == 0) { float m = -INFINITY; for (int w = 0; w < 16; ++w) m = fmaxf(m, sred[w]); s_M = m; }
    __syncthreads();
    const float M = s_M;

    float s1 = 0.f, s2 = 0.f;
    for (int n = tid; n < NN; n += 512) {
        float s = g_scores[b*NN + n];
        float e = __expf(s - M);
        s1 += e; s2 = fmaf(s, e, s2);
    }
    #pragma unroll
    for (int o = 16; o; o >>= 1) {
        s1 += __shfl_xor_sync(0xffffffffu, s1, o);
        s2 += __shfl_xor_sync(0xffffffffu, s2, o);
    }
    if (lane == 0) { sred[warp] = s1; sred2[warp] = s2; }
    __syncthreads();
    if (tid == 0) {
        float S1 = 0.f, S2 = 0.f;
        for (int w = 0; w < 16; ++w) { S1 += sred[w]; S2 += sred2[w]; }
        float logZ = M + logf(S1);
        s_logZ = logZ;
        out[OFF_ENT + b] = logZ - S2 / S1;
    }

    // ---- partial bitonic top-64 ----
    // Stage 1: sort each aligned 64-block, alternating direction (desc iff (i&64)==0)
    for (int k = 2; k <= KT; k <<= 1) {
        for (int j = k >> 1; j > 0; j >>= 1) {
            __syncthreads();
            #pragma unroll
            for (int p = 0; p < 8; ++p) {
                const int i = tid + p * 512;
                const int l = i ^ j;
                if (l > i) {
                    u64 a = skey[i], c = skey[l];
                    bool desc = ((i & k) == 0);
                    if (desc ? (a < c) : (a > c)) { skey[i] = c; skey[l] = a; }
                }
            }
        }
    }
    // Stage 2: halving rounds — half-cleaner max-compact + 64-block bitonic merge
    for (int size = NN; size > KT; size >>= 1) {
        const int half = size >> 1;
        __syncthreads();
        u64 tv[4]; int cnt = 0;
        for (int e = tid; e < half; e += 512) {
            int p = e >> 6, t = e & 63;
            u64 a = skey[p*128 + t], c = skey[p*128 + 64 + t];
            tv[cnt++] = (a > c) ? a : c;
        }
        __syncthreads();
        cnt = 0;
        for (int e = tid; e < half; e += 512) skey[e] = tv[cnt++];
        for (int j = 32; j > 0; j >>= 1) {
            __syncthreads();
            for (int i = tid; i < half; i += 512) {
                const int l = i ^ j;
                if (l > i) {
                    u64 a = skey[i], c = skey[l];
                    bool desc = ((i & KT) == 0);
                    if (desc ? (a < c) : (a > c)) { skey[i] = c; skey[l] = a; }
                }
            }
        }
    }
    __syncthreads();

    if (tid < KT) {
        u64 kk = skey[tid];
        int n = NN - 1 - (int)(kk & 0xFFFu);
        unsigned m = (unsigned)(kk >> 32);
        unsigned u = (m & 0x80000000u) ? (m ^ 0x80000000u) : ~m;
        float s = __uint_as_float(u);
        s_idx[tid] = n; s_t[tid] = tanhf(s); s_v[tid] = s;
    }
    __syncthreads();
    if (tid == 0) {
        float sum = 0.f;
        for (int i = 0; i < KT; ++i) sum += s_v[i];
        out[OFF_POL + b] = sum * (1.f/KT) - s_logZ;
    }

    float* sA = (float*)skey;
    for (int e = tid; e < KT*KT; e += 512) {
        int i = e >> 6, j = e & 63;
        sA[e] = Ahat[(size_t)b*NN*NN + (size_t)s_idx[i]*NN + s_idx[j]];
    }
    __syncthreads();
    if (tid < KT) {
        float s = 0.f;
        for (int i = 0; i < KT; ++i) s += sA[i*KT + tid];
        s_di[tid] = 1.0f / sqrtf(s);
    }
    __syncthreads();
    for (int e = tid; e < KT*KT; e += 512) {
        int i = e >> 6, j = e & 63;
        g_A[b*KT*KT + e] = s_di[j] * sA[e] * s_di[i];
    }

    for (int i = warp; i < DD; i += 16) {
        int k = i & (KT - 1);
        const float* e = node_embs + ((size_t)(b*NN + s_idx[k]))*DD;
        float tv2 = s_t[k];
        for (int d = lane; d < DD; d += 32) {
            float val = e[d];
            g_z[((size_t)b*DD + d)*DD + i] = val * tv2;
            if (i < KT) g_ne[(b*KT + i)*DD + d] = val;
        }
    }
}

// ---------------------------------------------------------------------------
// K4: fused u / rq / preh. 256 thr, k-split x2, f32x2, staged z/Q.
// grid (32, B): 4 rows/block; warp-group g sums kk half of each chunk.
// ---------------------------------------------------------------------------
__global__ void __launch_bounds__(256) k_gates(
    const float* __restrict__ prevQ,
    const float* __restrict__ Wu, const float* __restrict__ Uu, const float* __restrict__ bu,
    const float* __restrict__ Wr, const float* __restrict__ Ur, const float* __restrict__ br,
    const float* __restrict__ Wh, const float* __restrict__ bh)
{
    extern __shared__ char smraw[];
    u64*    swt = (u64*)smraw;                         // 5*512 packed weights (20KB)
    float4* sz  = (float4*)(smraw + 5*512*8);          // 2 bufs * 512 (16KB)
    float4* sq  = sz + 2*512;                          // 2 bufs * 512 (16KB)
    const int b = blockIdx.y, i0 = blockIdx.x*4;
    const int tid = threadIdx.x, w = tid>>5, lane = tid&31;
    const int g = w >> 2, row = w & 3;
    const int i = i0 + row;

    for (int e = tid; e < 4*DD; e += 256) {
        int r = e>>7, k = e&127;
        float a;
        a = Wu[(i0+r)*DD+k]; swt[0*512+e] = pk2(a,a);
        a = Uu[(i0+r)*DD+k]; swt[1*512+e] = pk2(a,a);
        a = Wr[(i0+r)*DD+k]; swt[2*512+e] = pk2(a,a);
        a = Ur[(i0+r)*DD+k]; swt[3*512+e] = pk2(a,a);
        a = Wh[(i0+r)*DD+k]; swt[4*512+e] = pk2(a,a);
    }
    const float* z = g_z + (size_t)b*DD*DD;
    const float* Q = prevQ + (size_t)b*DD*DD;

    float4 rz[2], rqv[2];
    #pragma unroll
    for (int p = 0; p < 2; ++p) {
        int e = tid + 256*p;
        rz[p]  = ((const float4*)(z + (size_t)(e>>5)*DD))[e&31];
        rqv[p] = ((const float4*)(Q + (size_t)(e>>5)*DD))[e&31];
    }
    #pragma unroll
    for (int p = 0; p < 2; ++p) { int e = tid+256*p; sz[e]=rz[p]; sq[e]=rqv[p]; }
    __syncthreads();

    u64 au0=0,au1=0,ar0=0,ar1=0,ah0=0,ah1=0;
    if (g == 0) {
        float4 v;
        v = *(const float4*)&bu[i*DD + 4*lane]; au0=pk2(v.x,v.y); au1=pk2(v.z,v.w);
        v = *(const float4*)&br[i*DD + 4*lane]; ar0=pk2(v.x,v.y); ar1=pk2(v.z,v.w);
        v = *(const float4*)&bh[i*DD + 4*lane]; ah0=pk2(v.x,v.y); ah1=pk2(v.z,v.w);
    }

    for (int c = 0; c < 8; ++c) {
        const int cb = c & 1, nb = cb ^ 1;
        if (c < 7) {
            #pragma unroll
            for (int p = 0; p < 2; ++p) {
                int e = tid + 256*p;
                int r16 = (c+1)*16 + (e>>5);
                rz[p]  = ((const float4*)(z + (size_t)r16*DD))[e&31];
                rqv[p] = ((const float4*)(Q + (size_t)r16*DD))[e&31];
            }
        }
        const ulonglong2* zz = (const ulonglong2*)(sz + cb*512);
        const ulonglong2* qq = (const ulonglong2*)(sq + cb*512);
        const int kb = c*16 + g*8;
        const u64* w0 = swt + 0*512 + row*128 + kb;
        const u64* w1 = swt + 1*512 + row*128 + kb;
        const u64* w2 = swt + 2*512 + row*128 + kb;
        const u64* w3 = swt + 3*512 + row*128 + kb;
        const u64* w4 = swt + 4*512 + row*128 + kb;
        #pragma unroll
        for (int q = 0; q < 8; ++q) {
            ulonglong2 zv = zz[(g*8+q)*32 + lane];
            ulonglong2 qv = qq[(g*8+q)*32 + lane];
            u64 wu = w0[q], uu = w1[q], wr = w2[q], ur = w3[q], wh = w4[q];
            au0=ffma2(wu,zv.x,au0); au1=ffma2(wu,zv.y,au1);
            au0=ffma2(uu,qv.x,au0); au1=ffma2(uu,qv.y,au1);
            ar0=ffma2(wr,zv.x,ar0); ar1=ffma2(wr,zv.y,ar1);
            ar0=ffma2(ur,qv.x,ar0); ar1=ffma2(ur,qv.y,ar1);
            ah0=ffma2(wh,zv.x,ah0); ah1=ffma2(wh,zv.y,ah1);
        }
        if (c < 7) {
            #pragma unroll
            for (int p = 0; p < 2; ++p) { int e = tid+256*p; sz[nb*512+e]=rz[p]; sq[nb*512+e]=rqv[p]; }
        }
        __syncthreads();
    }

    // combine k-split partials (reuse sz buffer)
    u64* sp = (u64*)sz;
    if (g == 1) {
        int base = (row*6)*32 + lane;
        sp[base] = au0; sp[base+32] = au1; sp[base+64] = ar0;
        sp[base+96] = ar1; sp[base+128] = ah0; sp[base+160] = ah1;
    }
    __syncthreads();
    if (g == 0) {
        int base = (row*6)*32 + lane;
        au0 = padd2(au0, sp[base]);     au1 = padd2(au1, sp[base+32]);
        ar0 = padd2(ar0, sp[base+64]);  ar1 = padd2(ar1, sp[base+96]);
        ah0 = padd2(ah0, sp[base+128]); ah1 = padd2(ah1, sp[base+160]);

        float f0,f1,f2,f3;
        const size_t o = ((size_t)b*DD + i)*DD + 4*lane;
        up2(au0,f0,f1); up2(au1,f2,f3);
        *(float4*)&g_u[o] = make_float4(sigf(f0),sigf(f1),sigf(f2),sigf(f3));
        up2(ar0,f0,f1); up2(ar1,f2,f3);
        float4 q4 = *(const float4*)&Q[(size_t)i*DD + 4*lane];
        *(float4*)&g_rq[o] = make_float4(sigf(f0)*q4.x, sigf(f1)*q4.y, sigf(f2)*q4.z, sigf(f3)*q4.w);
        up2(ah0,f0,f1); up2(ah1,f2,f3);
        *(float4*)&g_preh[o] = make_float4(f0,f1,f2,f3);
    }
}

// ---------------------------------------------------------------------------
// K5: newQ = (1-u)*Q + u*tanh(preh + Uh@rq). 256 thr, k-split x2.
// ---------------------------------------------------------------------------
__global__ void __launch_bounds__(256) k_newQ(
    const float* __restrict__ prevQ, const float* __restrict__ Uh)
{
    __shared__ u64 swt[4*DD];
    __shared__ float4 sb[2*512];
    __shared__ u64 sp[4*2*32];
    const int b = blockIdx.y, i0 = blockIdx.x*4;
    const int tid = threadIdx.x, w = tid>>5, lane = tid&31;
    const int g = w >> 2, row = w & 3;
    const int i = i0 + row;
    for (int e = tid; e < 4*DD; e += 256) {
        float a = Uh[(i0 + (e>>7))*DD + (e&127)]; swt[e] = pk2(a,a);
    }
    const float* Bm = g_rq + (size_t)b*DD*DD;
    float4 rb[2];
    #pragma unroll
    for (int p = 0; p < 2; ++p) { int e = tid+256*p; rb[p] = ((const float4*)(Bm + (size_t)(e>>5)*DD))[e&31]; }
    #pragma unroll
    for (int p = 0; p < 2; ++p) { int e = tid+256*p; sb[e]=rb[p]; }
    __syncthreads();
    u64 a0 = 0, a1 = 0;
    for (int c = 0; c < 8; ++c) {
        const int cb = c & 1, nb = cb ^ 1;
        if (c < 7) {
            #pragma unroll
            for (int p = 0; p < 2; ++p) {
                int e = tid + 256*p;
                rb[p] = ((const float4*)(Bm + (size_t)((c+1)*16 + (e>>5))*DD))[e&31];
            }
        }
        const ulonglong2* bb = (const ulonglong2*)(sb + cb*512);
        const u64* wp = swt + row*128 + c*16 + g*8;
        #pragma unroll
        for (int q = 0; q < 8; ++q) {
            ulonglong2 bv = bb[(g*8+q)*32 + lane];
            u64 wt = wp[q];
            a0 = ffma2(wt, bv.x, a0); a1 = ffma2(wt, bv.y, a1);
        }
        if (c < 7) {
            #pragma unroll
            for (int p = 0; p < 2; ++p) { int e = tid+256*p; sb[nb*512+e]=rb[p]; }
        }
        __syncthreads();
    }
    if (g == 1) { sp[row*64 + lane] = a0; sp[row*64 + 32 + lane] = a1; }
    __syncthreads();
    if (g == 0) {
        a0 = padd2(a0, sp[row*64 + lane]); a1 = padd2(a1, sp[row*64 + 32 + lane]);
        float f0,f1,f2,f3; up2(a0,f0,f1); up2(a1,f2,f3);
        const size_t o = ((size_t)b*DD + i)*DD + 4*lane;
        float4 ph = *(const float4*)&g_preh[o];
        float4 uv = *(const float4*)&g_u[o];
        float4 q4 = *(const float4*)&prevQ[(size_t)b*DD*DD + i*DD + 4*lane];
        float h0 = tanhf(f0+ph.x), h1 = tanhf(f1+ph.y), h2 = tanhf(f2+ph.z), h3 = tanhf(f3+ph.w);
        *(float4*)&g_newQ[o] = make_float4(
            (1.f-uv.x)*q4.x + uv.x*h0, (1.f-uv.y)*q4.y + uv.y*h1,
            (1.f-uv.z)*q4.z + uv.z*h2, (1.f-uv.w)*q4.w + uv.w*h3);
    }
}

// ---------------------------------------------------------------------------
// K6: P = ne @ newQ. 256 thr, k-split x2. grid (16, B).
// ---------------------------------------------------------------------------
__global__ void __launch_bounds__(256) k_g1()
{
    __shared__ u64 swt[4*DD];
    __shared__ float4 sb[2*512];
    __shared__ u64 sp[4*2*32];
    const int b = blockIdx.y, i0 = blockIdx.x*4;
    const int tid = threadIdx.x, w = tid>>5, lane = tid&31;
    const int g = w >> 2, row = w & 3;
    const int i = i0 + row;
    for (int e = tid; e < 4*DD; e += 256) {
        float a = g_ne[((size_t)b*KT + i0 + (e>>7))*DD + (e&127)]; swt[e] = pk2(a,a);
    }
    const float* Bm = g_newQ + (size_t)b*DD*DD;
    float4 rb[2];
    #pragma unroll
    for (int p = 0; p < 2; ++p) { int e = tid+256*p; rb[p] = ((const float4*)(Bm + (size_t)(e>>5)*DD))[e&31]; }
    #pragma unroll
    for (int p = 0; p < 2; ++p) { int e = tid+256*p; sb[e]=rb[p]; }
    __syncthreads();
    u64 a0 = 0, a1 = 0;
    for (int c = 0; c < 8; ++c) {
        const int cb = c & 1, nb = cb ^ 1;
        if (c < 7) {
            #pragma unroll
            for (int p = 0; p < 2; ++p) {
                int e = tid + 256*p;
                rb[p] = ((const float4*)(Bm + (size_t)((c+1)*16 + (e>>5))*DD))[e&31];
            }
        }
        const ulonglong2* bb = (const ulonglong2*)(sb + cb*512);
        const u64* wp = swt + row*128 + c*16 + g*8;
        #pragma unroll
        for (int q = 0; q < 8; ++q) {
            ulonglong2 bv = bb[(g*8+q)*32 + lane];
            u64 wt = wp[q];
            a0 = ffma2(wt, bv.x, a0); a1 = ffma2(wt, bv.y, a1);
        }
        if (c < 7) {
            #pragma unroll
            for (int p = 0; p < 2; ++p) { int e = tid+256*p; sb[nb*512+e]=rb[p]; }
        }
        __syncthreads();
    }
    if (g == 1) { sp[row*64 + lane] = a0; sp[row*64 + 32 + lane] = a1; }
    __syncthreads();
    if (g == 0) {
        a0 = padd2(a0, sp[row*64 + lane]); a1 = padd2(a1, sp[row*64 + 32 + lane]);
        float f0,f1,f2,f3; up2(a0,f0,f1); up2(a1,f2,f3);
        *(float4*)&g_P[((size_t)b*KT + i)*DD + 4*lane] = make_float4(f0,f1,f2,f3);
    }
}

// ---------------------------------------------------------------------------
// K7: h1 = relu(A@P) then G = h1@staticW (fused). grid (16, B).
// ---------------------------------------------------------------------------
__global__ void __launch_bounds__(128) k_g23(const float* __restrict__ sW)
{
    __shared__ u64 sAW[4*KT];
    __shared__ u64 sh1p[4*DD];
    __shared__ float buf[KT*DD];
    const int b = blockIdx.y, i0 = blockIdx.x*4;
    const int tid = threadIdx.x, w = tid>>5, lane = tid&31;
    const int i = i0 + w;
    for (int e = tid; e < 4*KT; e += 128) {
        float a = g_A[b*KT*KT + (i0 + (e>>6))*KT + (e&63)]; sAW[e] = pk2(a,a);
    }
    float4* bf4 = (float4*)buf;
    const float4* Psrc = (const float4*)(g_P + (size_t)b*KT*DD);
    for (int e = tid; e < 2048; e += 128) bf4[e] = Psrc[e];
    __syncthreads();
    u64 a0 = 0, a1 = 0;
    {
        const ulonglong2* bb = (const ulonglong2*)buf;
        const u64* wp = sAW + w*KT;
        #pragma unroll 8
        for (int k = 0; k < KT; ++k) {
            ulonglong2 bv = bb[k*32 + lane];
            u64 wt = wp[k];
            a0 = ffma2(wt, bv.x, a0); a1 = ffma2(wt, bv.y, a1);
        }
    }
    float f0,f1,f2,f3; up2(a0,f0,f1); up2(a1,f2,f3);
    f0 = fmaxf(f0,0.f); f1 = fmaxf(f1,0.f); f2 = fmaxf(f2,0.f); f3 = fmaxf(f3,0.f);
    *(float4*)&g_h1[((size_t)b*KT + i)*DD + 4*lane] = make_float4(f0,f1,f2,f3);
    sh1p[w*DD + 4*lane + 0] = pk2(f0,f0);
    sh1p[w*DD + 4*lane + 1] = pk2(f1,f1);
    sh1p[w*DD + 4*lane + 2] = pk2(f2,f2);
    sh1p[w*DD + 4*lane + 3] = pk2(f3,f3);
    __syncthreads();

    float4 rb[8];
    #pragma unroll
    for (int p = 0; p < 8; ++p) {
        int e = tid + 128*p;
        rb[p] = ((const float4*)(sW + (size_t)(e>>5)*DD))[e&31];
    }
    #pragma unroll
    for (int p = 0; p < 8; ++p) { int e = tid+128*p; bf4[e] = rb[p]; }
    __syncthreads();
    u64 g0 = 0, g1v = 0;
    for (int c = 0; c < 4; ++c) {
        const int cb = c & 1, nb = cb ^ 1;
        if (c < 3) {
            #pragma unroll
            for (int p = 0; p < 8; ++p) {
                int e = tid + 128*p;
                rb[p] = ((const float4*)(sW + (size_t)((c+1)*32 + (e>>5))*DD))[e&31];
            }
        }
        const ulonglong2* bb = (const ulonglong2*)(buf + cb*4096);
        const u64* hp = sh1p + w*DD + c*32;
        #pragma unroll
        for (int kk = 0; kk < 32; ++kk) {
            ulonglong2 bv = bb[kk*32 + lane];
            u64 wt = hp[kk];
            g0 = ffma2(wt, bv.x, g0); g1v = ffma2(wt, bv.y, g1v);
        }
        if (c < 3) {
            #pragma unroll
            for (int p = 0; p < 8; ++p) { int e = tid+128*p; bf4[nb*1024 + e] = rb[p]; }
        }
        __syncthreads();
    }
    up2(g0,f0,f1); up2(g1v,f2,f3);
    *(float4*)&g_G[((size_t)b*KT + i)*DD + 4*lane] = make_float4(f0,f1,f2,f3);
}

// ---------------------------------------------------------------------------
// K8: out = (h1 + relu(A @ G)) / 2. grid (16, B).
// ---------------------------------------------------------------------------
__global__ void __launch_bounds__(128) k_g4(float* __restrict__ out)
{
    __shared__ u64 sAW[4*KT];
    __shared__ float buf[KT*DD];
    const int b = blockIdx.y, i0 = blockIdx.x*4;
    const int tid = threadIdx.x, w = tid>>5, lane = tid&31;
    const int i = i0 + w;
    for (int e = tid; e < 4*KT; e += 128) {
        float a = g_A[b*KT*KT + (i0 + (e>>6))*KT + (e&63)]; sAW[e] = pk2(a,a);
    }
    float4* bf4 = (float4*)buf;
    const float4* Gsrc = (const float4*)(g_G + (size_t)b*KT*DD);
    for (int e = tid; e < 2048; e += 128) bf4[e] = Gsrc[e];
    __syncthreads();
    u64 a0 = 0, a1 = 0;
    const ulonglong2* bb = (const ulonglong2*)buf;
    const u64* wp = sAW + w*KT;
    #pragma unroll 8
    for (int k = 0; k < KT; ++k) {
        ulonglong2 bv = bb[k*32 + lane];
        u64 wt = wp[k];
        a0 = ffma2(wt, bv.x, a0); a1 = ffma2(wt, bv.y, a1);
    }
    float f0,f1,f2,f3; up2(a0,f0,f1); up2(a1,f2,f3);
    float4 h1v = *(const float4*)&g_h1[((size_t)b*KT + i)*DD + 4*lane];
    *(float4*)&out[((size_t)b*KT + i)*DD + 4*lane] = make_float4(
        (h1v.x + fmaxf(f0,0.f))*0.5f, (h1v.y + fmaxf(f1,0.f))*0.5f,
        (h1v.z + fmaxf(f2,0.f))*0.5f, (h1v.w + fmaxf(f3,0.f))*0.5f);
}

// ---------------------------------------------------------------------------
extern "C" void kernel_launch(void* const* d_in, const int* in_sizes, int n_in,
                              void* d_out, int out_size)
{
    const float* Ahat      = (const float*)d_in[0];
    const float* node_embs = (const float*)d_in[1];
    const float* ht        = (const float*)d_in[3];
    const float* prevQ     = (const float*)d_in[4];
    const float* W_map     = (const float*)d_in[5];
    const float* b_map     = (const float*)d_in[6];
    const float* Wu        = (const float*)d_in[7];
    const float* Uu        = (const float*)d_in[8];
    const float* bu        = (const float*)d_in[9];
    const float* Wr        = (const float*)d_in[10];
    const float* Ur        = (const float*)d_in[11];
    const float* br        = (const float*)d_in[12];
    const float* Wh        = (const float*)d_in[13];
    const float* Uh        = (const float*)d_in[14];
    const float* bh        = (const float*)d_in[15];
    const float* sW        = (const float*)d_in[16];
    float* out = (float*)d_out;

    const int gates_smem = 5*512*8 + 2*512*16 + 2*512*16;   // 53248 B
    cudaFuncSetAttribute(k_gates, cudaFuncAttributeMaxDynamicSharedMemorySize, gates_smem);

    k_scorer<<<BB, 512>>>(ht, W_map, b_map, out);
    k_scores<<<dim3(32, BB), 128>>>(node_embs);
    k_topk_gather<<<BB, 512, NN * sizeof(unsigned long long)>>>(node_embs, Ahat, out);
    k_gates<<<dim3(32, BB), 256, gates_smem>>>(prevQ, Wu, Uu, bu, Wr, Ur, br, Wh, bh);
    k_newQ<<<dim3(32, BB), 256>>>(prevQ, Uh);
    k_g1<<<dim3(16, BB), 256>>>();
    k_g23<<<dim3(16, BB), 128>>>(sW);
    k_g4<<<dim3(16, BB), 128>>>(out);
}

// round 6
// speedup vs baseline: 3.4761x; 1.0235x over previous
#include <cuda_runtime.h>
#include <math.h>

#define BB 8
#define NN 4096
#define DD 128
#define KT 64
#define RR 512

// Output layout: concat(out[B,K,D], policy[B], scorer[B,D], entropy[B])
#define OFF_POL     (BB*KT*DD)
#define OFF_SCORER  (OFF_POL + BB)
#define OFF_ENT     (OFF_SCORER + BB*DD)

typedef unsigned long long u64;

__device__ __forceinline__ u64 pk2(float lo, float hi) {
    u64 r; asm("mov.b64 %0,{%1,%2};" : "=l"(r) : "f"(lo), "f"(hi)); return r;
}
__device__ __forceinline__ void up2(u64 v, float& lo, float& hi) {
    asm("mov.b64 {%0,%1},%2;" : "=f"(lo), "=f"(hi) : "l"(v));
}
__device__ __forceinline__ u64 ffma2(u64 a, u64 b, u64 c) {
    u64 d; asm("fma.rn.f32x2 %0,%1,%2,%3;" : "=l"(d) : "l"(a), "l"(b), "l"(c)); return d;
}
__device__ __forceinline__ u64 padd2(u64 a, u64 b) {
    u64 d; asm("add.rn.f32x2 %0,%1,%2;" : "=l"(d) : "l"(a), "l"(b)); return d;
}
__device__ __forceinline__ float sigf(float x) { return 1.f / (1.f + __expf(-x)); }

// Device scratch
__device__ float g_scorer_n[BB*DD];
__device__ float g_scores[BB*NN];
__device__ float g_z[BB*DD*DD];       // z_topk [b][d][i]
__device__ float g_ne[BB*KT*DD];
__device__ float g_A[BB*KT*KT];
__device__ float g_u[BB*DD*DD];
__device__ float g_rq[BB*DD*DD];      // reset * prevQ
__device__ float g_preh[BB*DD*DD];    // Wh@z + bh
__device__ float g_newQ[BB*DD*DD];
__device__ float g_P[BB*KT*DD];
__device__ float g_h1[BB*KT*DD];
__device__ float g_G[BB*KT*DD];

// ---------------------------------------------------------------------------
// K1: scorer
// ---------------------------------------------------------------------------
__global__ void __launch_bounds__(512) k_scorer(
    const float* __restrict__ ht, const float* __restrict__ W_map,
    const float* __restrict__ b_map, float* __restrict__ out)
{
    const int b = blockIdx.x, tid = threadIdx.x;
    __shared__ float sht[RR];
    __shared__ float part[4][DD];
    __shared__ float ssc[DD];
    __shared__ float s_inv;
    sht[tid] = ht[b*RR + tid];
    __syncthreads();
    const int d = tid & 127, rq = tid >> 7;
    float acc = 0.f;
    const int r0 = rq * 128;
    #pragma unroll 4
    for (int r = 0; r < 128; ++r) acc = fmaf(sht[r0 + r], W_map[(r0 + r)*DD + d], acc);
    part[rq][d] = acc;
    __syncthreads();
    if (tid < DD) {
        float s = part[0][tid] + part[1][tid] + part[2][tid] + part[3][tid] + b_map[tid];
        float sc = tanhf(s);
        ssc[tid] = sc;
        out[OFF_SCORER + b*DD + tid] = sc;
    }
    __syncthreads();
    if (tid < 32) {
        float s = 0.f;
        for (int i = tid; i < DD; i += 32) s += ssc[i]*ssc[i];
        #pragma unroll
        for (int o = 16; o; o >>= 1) s += __shfl_xor_sync(0xffffffffu, s, o);
        if (tid == 0) s_inv = 1.0f / sqrtf(s);
    }
    __syncthreads();
    if (tid < DD) g_scorer_n[b*DD + tid] = ssc[tid] * s_inv;
}

// ---------------------------------------------------------------------------
// K2: scores (warp per node, float4)
// ---------------------------------------------------------------------------
__global__ void __launch_bounds__(128) k_scores(const float* __restrict__ node_embs)
{
    const int b = blockIdx.y, base = blockIdx.x * 128, tid = threadIdx.x;
    const int warp = tid >> 5, lane = tid & 31;
    __shared__ float4 ssc[32];
    if (tid < 32) ssc[tid] = ((const float4*)(g_scorer_n + b*DD))[tid];
    __syncthreads();
    const float4 sv = ssc[lane];
    #pragma unroll
    for (int t = 0; t < 32; t += 4) {
        const int n0 = base + warp * 32 + t;
        float a[4];
        #pragma unroll
        for (int q = 0; q < 4; ++q) {
            const float4 v = ((const float4*)(node_embs + ((size_t)(b*NN + n0 + q))*DD))[lane];
            a[q] = v.x*sv.x + v.y*sv.y + v.z*sv.z + v.w*sv.w;
        }
        #pragma unroll
        for (int o = 16; o; o >>= 1) {
            #pragma unroll
            for (int q = 0; q < 4; ++q) a[q] += __shfl_xor_sync(0xffffffffu, a[q], o);
        }
        if (lane < 4) g_scores[b*NN + n0 + lane] = a[lane];
    }
}

// ---------------------------------------------------------------------------
// K3: softmax stats + partial-bitonic top-64 + gather (A, z, ne)
// ---------------------------------------------------------------------------
__global__ void __launch_bounds__(512) k_topk_gather(
    const float* __restrict__ node_embs, const float* __restrict__ Ahat,
    float* __restrict__ out)
{
    extern __shared__ unsigned long long skey[];
    const int b = blockIdx.x, tid = threadIdx.x;
    const int warp = tid >> 5, lane = tid & 31;
    __shared__ float sred[16], sred2[16];
    __shared__ float s_M, s_logZ;
    __shared__ int   s_idx[KT];
    __shared__ float s_t[KT];
    __shared__ float s_v[KT];
    __shared__ float s_di[KT];

    float lmax = -INFINITY;
    for (int n = tid; n < NN; n += 512) {
        float s = g_scores[b*NN + n];
        lmax = fmaxf(lmax, s);
        unsigned u = __float_as_uint(s);
        unsigned m = (u & 0x80000000u) ? ~u : (u | 0x80000000u);
        skey[n] = ((unsigned long long)m << 32) | (unsigned)(NN - 1 - n);
    }
    #pragma unroll
    for (int o = 16; o; o >>= 1) lmax = fmaxf(lmax, __shfl_xor_sync(0xffffffffu, lmax, o));
    if (lane == 0) sred[warp] = lmax;
    __syncthreads();
    if (tid == 0) { float m = -INFINITY; for (int w = 0; w < 16; ++w) m = fmaxf(m, sred[w]); s_M = m; }
    __syncthreads();
    const float M = s_M;

    float s1 = 0.f, s2 = 0.f;
    for (int n = tid; n < NN; n += 512) {
        float s = g_scores[b*NN + n];
        float e = __expf(s - M);
        s1 += e; s2 = fmaf(s, e, s2);
    }
    #pragma unroll
    for (int o = 16; o; o >>= 1) {
        s1 += __shfl_xor_sync(0xffffffffu, s1, o);
        s2 += __shfl_xor_sync(0xffffffffu, s2, o);
    }
    if (lane == 0) { sred[warp] = s1; sred2[warp] = s2; }
    __syncthreads();
    if (tid == 0) {
        float S1 = 0.f, S2 = 0.f;
        for (int w = 0; w < 16; ++w) { S1 += sred[w]; S2 += sred2[w]; }
        float logZ = M + logf(S1);
        s_logZ = logZ;
        out[OFF_ENT + b] = logZ - S2 / S1;
    }

    // Stage 1: sort each aligned 64-block, alternating direction
    for (int k = 2; k <= KT; k <<= 1) {
        for (int j = k >> 1; j > 0; j >>= 1) {
            __syncthreads();
            #pragma unroll
            for (int p = 0; p < 8; ++p) {
                const int i = tid + p * 512;
                const int l = i ^ j;
                if (l > i) {
                    u64 a = skey[i], c = skey[l];
                    bool desc = ((i & k) == 0);
                    if (desc ? (a < c) : (a > c)) { skey[i] = c; skey[l] = a; }
                }
            }
        }
    }
    // Stage 2: halving rounds — half-cleaner max-compact + 64-block bitonic merge
    for (int size = NN; size > KT; size >>= 1) {
        const int half = size >> 1;
        __syncthreads();
        u64 tv[4]; int cnt = 0;
        for (int e = tid; e < half; e += 512) {
            int p = e >> 6, t = e & 63;
            u64 a = skey[p*128 + t], c = skey[p*128 + 64 + t];
            tv[cnt++] = (a > c) ? a : c;
        }
        __syncthreads();
        cnt = 0;
        for (int e = tid; e < half; e += 512) skey[e] = tv[cnt++];
        for (int j = 32; j > 0; j >>= 1) {
            __syncthreads();
            for (int i = tid; i < half; i += 512) {
                const int l = i ^ j;
                if (l > i) {
                    u64 a = skey[i], c = skey[l];
                    bool desc = ((i & KT) == 0);
                    if (desc ? (a < c) : (a > c)) { skey[i] = c; skey[l] = a; }
                }
            }
        }
    }
    __syncthreads();

    if (tid < KT) {
        u64 kk = skey[tid];
        int n = NN - 1 - (int)(kk & 0xFFFu);
        unsigned m = (unsigned)(kk >> 32);
        unsigned u = (m & 0x80000000u) ? (m ^ 0x80000000u) : ~m;
        float s = __uint_as_float(u);
        s_idx[tid] = n; s_t[tid] = tanhf(s); s_v[tid] = s;
    }
    __syncthreads();
    if (tid == 0) {
        float sum = 0.f;
        for (int i = 0; i < KT; ++i) sum += s_v[i];
        out[OFF_POL + b] = sum * (1.f/KT) - s_logZ;
    }

    float* sA = (float*)skey;
    for (int e = tid; e < KT*KT; e += 512) {
        int i = e >> 6, j = e & 63;
        sA[e] = Ahat[(size_t)b*NN*NN + (size_t)s_idx[i]*NN + s_idx[j]];
    }
    __syncthreads();
    if (tid < KT) {
        float s = 0.f;
        for (int i = 0; i < KT; ++i) s += sA[i*KT + tid];
        s_di[tid] = 1.0f / sqrtf(s);
    }
    __syncthreads();
    for (int e = tid; e < KT*KT; e += 512) {
        int i = e >> 6, j = e & 63;
        g_A[b*KT*KT + e] = s_di[j] * sA[e] * s_di[i];
    }

    for (int i = warp; i < DD; i += 16) {
        int k = i & (KT - 1);
        const float* e = node_embs + ((size_t)(b*NN + s_idx[k]))*DD;
        float tv2 = s_t[k];
        for (int d = lane; d < DD; d += 32) {
            float val = e[d];
            g_z[((size_t)b*DD + d)*DD + i] = val * tv2;
            if (i < KT) g_ne[(b*KT + i)*DD + d] = val;
        }
    }
}

// ---------------------------------------------------------------------------
// K4: fused u / rq / preh. 128 thr; 2 rows/warp, k-split x2, f32x2.
// grid (32, B): 4 rows/block.
// ---------------------------------------------------------------------------
__global__ void __launch_bounds__(128, 4) k_gates(
    const float* __restrict__ prevQ,
    const float* __restrict__ Wu, const float* __restrict__ Uu, const float* __restrict__ bu,
    const float* __restrict__ Wr, const float* __restrict__ Ur, const float* __restrict__ br,
    const float* __restrict__ Wh, const float* __restrict__ bh)
{
    extern __shared__ char smraw[];
    u64*    swt = (u64*)smraw;                         // 5*512 packed weights (20KB)
    float4* sz  = (float4*)(smraw + 5*512*8);          // 2 bufs * 512 (16KB)
    float4* sq  = sz + 2*512;                          // 2 bufs * 512 (16KB)
    const int b = blockIdx.y, i0 = blockIdx.x*4;
    const int tid = threadIdx.x, w = tid>>5, lane = tid&31;
    const int pr = w >> 1, g = w & 1;
    const int rA = pr*2, rB = rA + 1;        // local rows
    const int giA = i0 + rA, giB = i0 + rB;  // global rows

    for (int e = tid; e < 512; e += 128) {
        int r = e>>7, k = e&127;
        float a;
        a = Wu[(i0+r)*DD+k]; swt[       e] = pk2(a,a);
        a = Uu[(i0+r)*DD+k]; swt[ 512 + e] = pk2(a,a);
        a = Wr[(i0+r)*DD+k]; swt[1024 + e] = pk2(a,a);
        a = Ur[(i0+r)*DD+k]; swt[1536 + e] = pk2(a,a);
        a = Wh[(i0+r)*DD+k]; swt[2048 + e] = pk2(a,a);
    }
    const float* z = g_z + (size_t)b*DD*DD;
    const float* Q = prevQ + (size_t)b*DD*DD;

    float4 rz[4], rqv[4];
    #pragma unroll
    for (int p = 0; p < 4; ++p) {
        int e = tid + 128*p;
        rz[p]  = ((const float4*)(z + (size_t)(e>>5)*DD))[e&31];
        rqv[p] = ((const float4*)(Q + (size_t)(e>>5)*DD))[e&31];
    }
    #pragma unroll
    for (int p = 0; p < 4; ++p) { int e = tid+128*p; sz[e]=rz[p]; sq[e]=rqv[p]; }
    __syncthreads();

    u64 auA0=0,auA1=0,arA0=0,arA1=0,ahA0=0,ahA1=0;
    u64 auB0=0,auB1=0,arB0=0,arB1=0,ahB0=0,ahB1=0;
    if (g == 0) {
        float4 v;
        v = *(const float4*)&bu[giA*DD + 4*lane]; auA0=pk2(v.x,v.y); auA1=pk2(v.z,v.w);
        v = *(const float4*)&br[giA*DD + 4*lane]; arA0=pk2(v.x,v.y); arA1=pk2(v.z,v.w);
        v = *(const float4*)&bh[giA*DD + 4*lane]; ahA0=pk2(v.x,v.y); ahA1=pk2(v.z,v.w);
        v = *(const float4*)&bu[giB*DD + 4*lane]; auB0=pk2(v.x,v.y); auB1=pk2(v.z,v.w);
        v = *(const float4*)&br[giB*DD + 4*lane]; arB0=pk2(v.x,v.y); arB1=pk2(v.z,v.w);
        v = *(const float4*)&bh[giB*DD + 4*lane]; ahB0=pk2(v.x,v.y); ahB1=pk2(v.z,v.w);
    }

    for (int c = 0; c < 8; ++c) {
        const int cb = c & 1, nb = cb ^ 1;
        if (c < 7) {
            #pragma unroll
            for (int p = 0; p < 4; ++p) {
                int e = tid + 128*p;
                int r16 = (c+1)*16 + (e>>5);
                rz[p]  = ((const float4*)(z + (size_t)r16*DD))[e&31];
                rqv[p] = ((const float4*)(Q + (size_t)r16*DD))[e&31];
            }
        }
        const ulonglong2* zz = (const ulonglong2*)(sz + cb*512);
        const ulonglong2* qq = (const ulonglong2*)(sq + cb*512);
        const int kb = c*16 + g*8;
        const u64* pA = swt + rA*128 + kb;
        const u64* pB = swt + rB*128 + kb;
        #pragma unroll
        for (int q = 0; q < 8; ++q) {
            ulonglong2 zv = zz[(g*8+q)*32 + lane];
            ulonglong2 qv = qq[(g*8+q)*32 + lane];
            u64 wuA=pA[q], uuA=pA[512+q], wrA=pA[1024+q], urA=pA[1536+q], whA=pA[2048+q];
            u64 wuB=pB[q], uuB=pB[512+q], wrB=pB[1024+q], urB=pB[1536+q], whB=pB[2048+q];
            auA0=ffma2(wuA,zv.x,auA0); auA1=ffma2(wuA,zv.y,auA1);
            auA0=ffma2(uuA,qv.x,auA0); auA1=ffma2(uuA,qv.y,auA1);
            arA0=ffma2(wrA,zv.x,arA0); arA1=ffma2(wrA,zv.y,arA1);
            arA0=ffma2(urA,qv.x,arA0); arA1=ffma2(urA,qv.y,arA1);
            ahA0=ffma2(whA,zv.x,ahA0); ahA1=ffma2(whA,zv.y,ahA1);
            auB0=ffma2(wuB,zv.x,auB0); auB1=ffma2(wuB,zv.y,auB1);
            auB0=ffma2(uuB,qv.x,auB0); auB1=ffma2(uuB,qv.y,auB1);
            arB0=ffma2(wrB,zv.x,arB0); arB1=ffma2(wrB,zv.y,arB1);
            arB0=ffma2(urB,qv.x,arB0); arB1=ffma2(urB,qv.y,arB1);
            ahB0=ffma2(whB,zv.x,ahB0); ahB1=ffma2(whB,zv.y,ahB1);
        }
        if (c < 7) {
            #pragma unroll
            for (int p = 0; p < 4; ++p) { int e = tid+128*p; sz[nb*512+e]=rz[p]; sq[nb*512+e]=rqv[p]; }
        }
        __syncthreads();
    }

    u64* sp = (u64*)sz;
    if (g == 1) {
        int base = pr*12*32 + lane;
        sp[base+0*32]=auA0;  sp[base+1*32]=auA1;  sp[base+2*32]=arA0;  sp[base+3*32]=arA1;
        sp[base+4*32]=ahA0;  sp[base+5*32]=ahA1;  sp[base+6*32]=auB0;  sp[base+7*32]=auB1;
        sp[base+8*32]=arB0;  sp[base+9*32]=arB1;  sp[base+10*32]=ahB0; sp[base+11*32]=ahB1;
    }
    __syncthreads();
    if (g == 0) {
        int base = pr*12*32 + lane;
        auA0=padd2(auA0,sp[base+0*32]);  auA1=padd2(auA1,sp[base+1*32]);
        arA0=padd2(arA0,sp[base+2*32]);  arA1=padd2(arA1,sp[base+3*32]);
        ahA0=padd2(ahA0,sp[base+4*32]);  ahA1=padd2(ahA1,sp[base+5*32]);
        auB0=padd2(auB0,sp[base+6*32]);  auB1=padd2(auB1,sp[base+7*32]);
        arB0=padd2(arB0,sp[base+8*32]);  arB1=padd2(arB1,sp[base+9*32]);
        ahB0=padd2(ahB0,sp[base+10*32]); ahB1=padd2(ahB1,sp[base+11*32]);

        float f0,f1,f2,f3;
        {
            const size_t o = ((size_t)b*DD + giA)*DD + 4*lane;
            up2(auA0,f0,f1); up2(auA1,f2,f3);
            *(float4*)&g_u[o] = make_float4(sigf(f0),sigf(f1),sigf(f2),sigf(f3));
            up2(arA0,f0,f1); up2(arA1,f2,f3);
            float4 q4 = *(const float4*)&Q[(size_t)giA*DD + 4*lane];
            *(float4*)&g_rq[o] = make_float4(sigf(f0)*q4.x, sigf(f1)*q4.y, sigf(f2)*q4.z, sigf(f3)*q4.w);
            up2(ahA0,f0,f1); up2(ahA1,f2,f3);
            *(float4*)&g_preh[o] = make_float4(f0,f1,f2,f3);
        }
        {
            const size_t o = ((size_t)b*DD + giB)*DD + 4*lane;
            up2(auB0,f0,f1); up2(auB1,f2,f3);
            *(float4*)&g_u[o] = make_float4(sigf(f0),sigf(f1),sigf(f2),sigf(f3));
            up2(arB0,f0,f1); up2(arB1,f2,f3);
            float4 q4 = *(const float4*)&Q[(size_t)giB*DD + 4*lane];
            *(float4*)&g_rq[o] = make_float4(sigf(f0)*q4.x, sigf(f1)*q4.y, sigf(f2)*q4.z, sigf(f3)*q4.w);
            up2(ahB0,f0,f1); up2(ahB1,f2,f3);
            *(float4*)&g_preh[o] = make_float4(f0,f1,f2,f3);
        }
    }
}

// ---------------------------------------------------------------------------
// K5: newQ = (1-u)*Q + u*tanh(preh + Uh@rq). 128 thr, 2 rows/warp, k-split x2.
// ---------------------------------------------------------------------------
__global__ void __launch_bounds__(128, 4) k_newQ(
    const float* __restrict__ prevQ, const float* __restrict__ Uh)
{
    __shared__ u64 swt[512];
    __shared__ float4 sb[2*512];
    __shared__ u64 sp[2*4*32];
    const int b = blockIdx.y, i0 = blockIdx.x*4;
    const int tid = threadIdx.x, w = tid>>5, lane = tid&31;
    const int pr = w >> 1, g = w & 1;
    const int rA = pr*2, rB = rA + 1;
    const int giA = i0 + rA, giB = i0 + rB;
    for (int e = tid; e < 512; e += 128) {
        float a = Uh[(i0 + (e>>7))*DD + (e&127)]; swt[e] = pk2(a,a);
    }
    const float* Bm = g_rq + (size_t)b*DD*DD;
    float4 rb[4];
    #pragma unroll
    for (int p = 0; p < 4; ++p) { int e = tid+128*p; rb[p] = ((const float4*)(Bm + (size_t)(e>>5)*DD))[e&31]; }
    #pragma unroll
    for (int p = 0; p < 4; ++p) { int e = tid+128*p; sb[e]=rb[p]; }
    __syncthreads();
    u64 aA0=0,aA1=0,aB0=0,aB1=0;
    for (int c = 0; c < 8; ++c) {
        const int cb = c & 1, nb = cb ^ 1;
        if (c < 7) {
            #pragma unroll
            for (int p = 0; p < 4; ++p) {
                int e = tid + 128*p;
                rb[p] = ((const float4*)(Bm + (size_t)((c+1)*16 + (e>>5))*DD))[e&31];
            }
        }
        const ulonglong2* bb = (const ulonglong2*)(sb + cb*512);
        const u64* pA = swt + rA*128 + c*16 + g*8;
        const u64* pB = swt + rB*128 + c*16 + g*8;
        #pragma unroll
        for (int q = 0; q < 8; ++q) {
            ulonglong2 bv = bb[(g*8+q)*32 + lane];
            u64 wtA = pA[q], wtB = pB[q];
            aA0 = ffma2(wtA, bv.x, aA0); aA1 = ffma2(wtA, bv.y, aA1);
            aB0 = ffma2(wtB, bv.x, aB0); aB1 = ffma2(wtB, bv.y, aB1);
        }
        if (c < 7) {
            #pragma unroll
            for (int p = 0; p < 4; ++p) { int e = tid+128*p; sb[nb*512+e]=rb[p]; }
        }
        __syncthreads();
    }
    if (g == 1) {
        int base = pr*4*32 + lane;
        sp[base] = aA0; sp[base+32] = aA1; sp[base+64] = aB0; sp[base+96] = aB1;
    }
    __syncthreads();
    if (g == 0) {
        int base = pr*4*32 + lane;
        aA0 = padd2(aA0, sp[base]);    aA1 = padd2(aA1, sp[base+32]);
        aB0 = padd2(aB0, sp[base+64]); aB1 = padd2(aB1, sp[base+96]);
        float f0,f1,f2,f3;
        {
            up2(aA0,f0,f1); up2(aA1,f2,f3);
            const size_t o = ((size_t)b*DD + giA)*DD + 4*lane;
            float4 ph = *(const float4*)&g_preh[o];
            float4 uv = *(const float4*)&g_u[o];
            float4 q4 = *(const float4*)&prevQ[(size_t)b*DD*DD + giA*DD + 4*lane];
            float h0 = tanhf(f0+ph.x), h1 = tanhf(f1+ph.y), h2 = tanhf(f2+ph.z), h3 = tanhf(f3+ph.w);
            *(float4*)&g_newQ[o] = make_float4(
                (1.f-uv.x)*q4.x + uv.x*h0, (1.f-uv.y)*q4.y + uv.y*h1,
                (1.f-uv.z)*q4.z + uv.z*h2, (1.f-uv.w)*q4.w + uv.w*h3);
        }
        {
            up2(aB0,f0,f1); up2(aB1,f2,f3);
            const size_t o = ((size_t)b*DD + giB)*DD + 4*lane;
            float4 ph = *(const float4*)&g_preh[o];
            float4 uv = *(const float4*)&g_u[o];
            float4 q4 = *(const float4*)&prevQ[(size_t)b*DD*DD + giB*DD + 4*lane];
            float h0 = tanhf(f0+ph.x), h1 = tanhf(f1+ph.y), h2 = tanhf(f2+ph.z), h3 = tanhf(f3+ph.w);
            *(float4*)&g_newQ[o] = make_float4(
                (1.f-uv.x)*q4.x + uv.x*h0, (1.f-uv.y)*q4.y + uv.y*h1,
                (1.f-uv.z)*q4.z + uv.z*h2, (1.f-uv.w)*q4.w + uv.w*h3);
        }
    }
}

// ---------------------------------------------------------------------------
// K6: P = ne @ newQ. 128 thr, 2 rows/warp, k-split x2. grid (16, B).
// ---------------------------------------------------------------------------
__global__ void __launch_bounds__(128, 4) k_g1()
{
    __shared__ u64 swt[512];
    __shared__ float4 sb[2*512];
    __shared__ u64 sp[2*4*32];
    const int b = blockIdx.y, i0 = blockIdx.x*4;
    const int tid = threadIdx.x, w = tid>>5, lane = tid&31;
    const int pr = w >> 1, g = w & 1;
    const int rA = pr*2, rB = rA + 1;
    const int giA = i0 + rA, giB = i0 + rB;
    for (int e = tid; e < 512; e += 128) {
        float a = g_ne[((size_t)b*KT + i0 + (e>>7))*DD + (e&127)]; swt[e] = pk2(a,a);
    }
    const float* Bm = g_newQ + (size_t)b*DD*DD;
    float4 rb[4];
    #pragma unroll
    for (int p = 0; p < 4; ++p) { int e = tid+128*p; rb[p] = ((const float4*)(Bm + (size_t)(e>>5)*DD))[e&31]; }
    #pragma unroll
    for (int p = 0; p < 4; ++p) { int e = tid+128*p; sb[e]=rb[p]; }
    __syncthreads();
    u64 aA0=0,aA1=0,aB0=0,aB1=0;
    for (int c = 0; c < 8; ++c) {
        const int cb = c & 1, nb = cb ^ 1;
        if (c < 7) {
            #pragma unroll
            for (int p = 0; p < 4; ++p) {
                int e = tid + 128*p;
                rb[p] = ((const float4*)(Bm + (size_t)((c+1)*16 + (e>>5))*DD))[e&31];
            }
        }
        const ulonglong2* bb = (const ulonglong2*)(sb + cb*512);
        const u64* pA = swt + rA*128 + c*16 + g*8;
        const u64* pB = swt + rB*128 + c*16 + g*8;
        #pragma unroll
        for (int q = 0; q < 8; ++q) {
            ulonglong2 bv = bb[(g*8+q)*32 + lane];
            u64 wtA = pA[q], wtB = pB[q];
            aA0 = ffma2(wtA, bv.x, aA0); aA1 = ffma2(wtA, bv.y, aA1);
            aB0 = ffma2(wtB, bv.x, aB0); aB1 = ffma2(wtB, bv.y, aB1);
        }
        if (c < 7) {
            #pragma unroll
            for (int p = 0; p < 4; ++p) { int e = tid+128*p; sb[nb*512+e]=rb[p]; }
        }
        __syncthreads();
    }
    if (g == 1) {
        int base = pr*4*32 + lane;
        sp[base] = aA0; sp[base+32] = aA1; sp[base+64] = aB0; sp[base+96] = aB1;
    }
    __syncthreads();
    if (g == 0) {
        int base = pr*4*32 + lane;
        aA0 = padd2(aA0, sp[base]);    aA1 = padd2(aA1, sp[base+32]);
        aB0 = padd2(aB0, sp[base+64]); aB1 = padd2(aB1, sp[base+96]);
        float f0,f1,f2,f3;
        up2(aA0,f0,f1); up2(aA1,f2,f3);
        *(float4*)&g_P[((size_t)b*KT + giA)*DD + 4*lane] = make_float4(f0,f1,f2,f3);
        up2(aB0,f0,f1); up2(aB1,f2,f3);
        *(float4*)&g_P[((size_t)b*KT + giB)*DD + 4*lane] = make_float4(f0,f1,f2,f3);
    }
}

// ---------------------------------------------------------------------------
// K7: h1 = relu(A@P) then G = h1@staticW (fused). grid (16, B).
// ---------------------------------------------------------------------------
__global__ void __launch_bounds__(128) k_g23(const float* __restrict__ sW)
{
    __shared__ u64 sAW[4*KT];
    __shared__ u64 sh1p[4*DD];
    __shared__ float buf[KT*DD];
    const int b = blockIdx.y, i0 = blockIdx.x*4;
    const int tid = threadIdx.x, w = tid>>5, lane = tid&31;
    const int i = i0 + w;
    for (int e = tid; e < 4*KT; e += 128) {
        float a = g_A[b*KT*KT + (i0 + (e>>6))*KT + (e&63)]; sAW[e] = pk2(a,a);
    }
    float4* bf4 = (float4*)buf;
    const float4* Psrc = (const float4*)(g_P + (size_t)b*KT*DD);
    for (int e = tid; e < 2048; e += 128) bf4[e] = Psrc[e];
    __syncthreads();
    u64 a0 = 0, a1 = 0;
    {
        const ulonglong2* bb = (const ulonglong2*)buf;
        const u64* wp = sAW + w*KT;
        #pragma unroll 8
        for (int k = 0; k < KT; ++k) {
            ulonglong2 bv = bb[k*32 + lane];
            u64 wt = wp[k];
            a0 = ffma2(wt, bv.x, a0); a1 = ffma2(wt, bv.y, a1);
        }
    }
    float f0,f1,f2,f3; up2(a0,f0,f1); up2(a1,f2,f3);
    f0 = fmaxf(f0,0.f); f1 = fmaxf(f1,0.f); f2 = fmaxf(f2,0.f); f3 = fmaxf(f3,0.f);
    *(float4*)&g_h1[((size_t)b*KT + i)*DD + 4*lane] = make_float4(f0,f1,f2,f3);
    sh1p[w*DD + 4*lane + 0] = pk2(f0,f0);
    sh1p[w*DD + 4*lane + 1] = pk2(f1,f1);
    sh1p[w*DD + 4*lane + 2] = pk2(f2,f2);
    sh1p[w*DD + 4*lane + 3] = pk2(f3,f3);
    __syncthreads();

    float4 rb[8];
    #pragma unroll
    for (int p = 0; p < 8; ++p) {
        int e = tid + 128*p;
        rb[p] = ((const float4*)(sW + (size_t)(e>>5)*DD))[e&31];
    }
    #pragma unroll
    for (int p = 0; p < 8; ++p) { int e = tid+128*p; bf4[e] = rb[p]; }
    __syncthreads();
    u64 g0 = 0, g1v = 0;
    for (int c = 0; c < 4; ++c) {
        const int cb = c & 1, nb = cb ^ 1;
        if (c < 3) {
            #pragma unroll
            for (int p = 0; p < 8; ++p) {
                int e = tid + 128*p;
                rb[p] = ((const float4*)(sW + (size_t)((c+1)*32 + (e>>5))*DD))[e&31];
            }
        }
        const ulonglong2* bb = (const ulonglong2*)(buf + cb*4096);
        const u64* hp = sh1p + w*DD + c*32;
        #pragma unroll
        for (int kk = 0; kk < 32; ++kk) {
            ulonglong2 bv = bb[kk*32 + lane];
            u64 wt = hp[kk];
            g0 = ffma2(wt, bv.x, g0); g1v = ffma2(wt, bv.y, g1v);
        }
        if (c < 3) {
            #pragma unroll
            for (int p = 0; p < 8; ++p) { int e = tid+128*p; bf4[nb*1024 + e] = rb[p]; }
        }
        __syncthreads();
    }
    up2(g0,f0,f1); up2(g1v,f2,f3);
    *(float4*)&g_G[((size_t)b*KT + i)*DD + 4*lane] = make_float4(f0,f1,f2,f3);
}

// ---------------------------------------------------------------------------
// K8: out = (h1 + relu(A @ G)) / 2. 128 thr, 2 rows/warp, k-split x2. grid (16, B).
// ---------------------------------------------------------------------------
__global__ void __launch_bounds__(128) k_g4(float* __restrict__ out)
{
    __shared__ u64 sAW[4*KT];
    __shared__ float buf[KT*DD];
    __shared__ u64 sp[2*4*32];
    const int b = blockIdx.y, i0 = blockIdx.x*4;
    const int tid = threadIdx.x, w = tid>>5, lane = tid&31;
    const int pr = w >> 1, g = w & 1;
    const int rA = pr*2, rB = rA + 1;
    const int giA = i0 + rA, giB = i0 + rB;
    for (int e = tid; e < 4*KT; e += 128) {
        float a = g_A[b*KT*KT + (i0 + (e>>6))*KT + (e&63)]; sAW[e] = pk2(a,a);
    }
    float4* bf4 = (float4*)buf;
    const float4* Gsrc = (const float4*)(g_G + (size_t)b*KT*DD);
    for (int e = tid; e < 2048; e += 128) bf4[e] = Gsrc[e];
    __syncthreads();
    u64 aA0=0,aA1=0,aB0=0,aB1=0;
    const ulonglong2* bb = (const ulonglong2*)buf;
    const u64* pA = sAW + rA*KT + g*32;
    const u64* pB = sAW + rB*KT + g*32;
    #pragma unroll 8
    for (int q = 0; q < 32; ++q) {
        ulonglong2 bv = bb[(g*32+q)*32 + lane];
        u64 wtA = pA[q], wtB = pB[q];
        aA0 = ffma2(wtA, bv.x, aA0); aA1 = ffma2(wtA, bv.y, aA1);
        aB0 = ffma2(wtB, bv.x, aB0); aB1 = ffma2(wtB, bv.y, aB1);
    }
    if (g == 1) {
        int base = pr*4*32 + lane;
        sp[base] = aA0; sp[base+32] = aA1; sp[base+64] = aB0; sp[base+96] = aB1;
    }
    __syncthreads();
    if (g == 0) {
        int base = pr*4*32 + lane;
        aA0 = padd2(aA0, sp[base]);    aA1 = padd2(aA1, sp[base+32]);
        aB0 = padd2(aB0, sp[base+64]); aB1 = padd2(aB1, sp[base+96]);
        float f0,f1,f2,f3;
        up2(aA0,f0,f1); up2(aA1,f2,f3);
        {
            float4 h1v = *(const float4*)&g_h1[((size_t)b*KT + giA)*DD + 4*lane];
            *(float4*)&out[((size_t)b*KT + giA)*DD + 4*lane] = make_float4(
                (h1v.x + fmaxf(f0,0.f))*0.5f, (h1v.y + fmaxf(f1,0.f))*0.5f,
                (h1v.z + fmaxf(f2,0.f))*0.5f, (h1v.w + fmaxf(f3,0.f))*0.5f);
        }
        up2(aB0,f0,f1); up2(aB1,f2,f3);
        {
            float4 h1v = *(const float4*)&g_h1[((size_t)b*KT + giB)*DD + 4*lane];
            *(float4*)&out[((size_t)b*KT + giB)*DD + 4*lane] = make_float4(
                (h1v.x + fmaxf(f0,0.f))*0.5f, (h1v.y + fmaxf(f1,0.f))*0.5f,
                (h1v.z + fmaxf(f2,0.f))*0.5f, (h1v.w + fmaxf(f3,0.f))*0.5f);
        }
    }
}

// ---------------------------------------------------------------------------
extern "C" void kernel_launch(void* const* d_in, const int* in_sizes, int n_in,
                              void* d_out, int out_size)
{
    const float* Ahat      = (const float*)d_in[0];
    const float* node_embs = (const float*)d_in[1];
    const float* ht        = (const float*)d_in[3];
    const float* prevQ     = (const float*)d_in[4];
    const float* W_map     = (const float*)d_in[5];
    const float* b_map     = (const float*)d_in[6];
    const float* Wu        = (const float*)d_in[7];
    const float* Uu        = (const float*)d_in[8];
    const float* bu        = (const float*)d_in[9];
    const float* Wr        = (const float*)d_in[10];
    const float* Ur        = (const float*)d_in[11];
    const float* br        = (const float*)d_in[12];
    const float* Wh        = (const float*)d_in[13];
    const float* Uh        = (const float*)d_in[14];
    const float* bh        = (const float*)d_in[15];
    const float* sW        = (const float*)d_in[16];
    float* out = (float*)d_out;

    const int gates_smem = 5*512*8 + 2*512*16 + 2*512*16;   // 53248 B
    cudaFuncSetAttribute(k_gates, cudaFuncAttributeMaxDynamicSharedMemorySize, gates_smem);

    k_scorer<<<BB, 512>>>(ht, W_map, b_map, out);
    k_scores<<<dim3(32, BB), 128>>>(node_embs);
    k_topk_gather<<<BB, 512, NN * sizeof(unsigned long long)>>>(node_embs, Ahat, out);
    k_gates<<<dim3(32, BB), 128, gates_smem>>>(prevQ, Wu, Uu, bu, Wr, Ur, br, Wh, bh);
    k_newQ<<<dim3(32, BB), 128>>>(prevQ, Uh);
    k_g1<<<dim3(16, BB), 128>>>();
    k_g23<<<dim3(16, BB), 128>>>(sW);
    k_g4<<<dim3(16, BB), 128>>>(out);
}

// round 7
// speedup vs baseline: 3.5757x; 1.0286x over previous
#include <cuda_runtime.h>
#include <math.h>

#define BB 8
#define NN 4096
#define DD 128
#define KT 64
#define RR 512

#define OFF_POL     (BB*KT*DD)
#define OFF_SCORER  (OFF_POL + BB)
#define OFF_ENT     (OFF_SCORER + BB*DD)

typedef unsigned long long u64;

__device__ __forceinline__ u64 pk2(float lo, float hi) {
    u64 r; asm("mov.b64 %0,{%1,%2};" : "=l"(r) : "f"(lo), "f"(hi)); return r;
}
__device__ __forceinline__ void up2(u64 v, float& lo, float& hi) {
    asm("mov.b64 {%0,%1},%2;" : "=f"(lo), "=f"(hi) : "l"(v));
}
__device__ __forceinline__ u64 ffma2(u64 a, u64 b, u64 c) {
    u64 d; asm("fma.rn.f32x2 %0,%1,%2,%3;" : "=l"(d) : "l"(a), "l"(b), "l"(c)); return d;
}
__device__ __forceinline__ u64 padd2(u64 a, u64 b) {
    u64 d; asm("add.rn.f32x2 %0,%1,%2;" : "=l"(d) : "l"(a), "l"(b)); return d;
}
__device__ __forceinline__ float sigf(float x) { return 1.f / (1.f + __expf(-x)); }

// Device scratch
__device__ float g_scorer_n[BB*DD];
__device__ float g_scores[BB*NN];
__device__ float g_z[BB*DD*DD];
__device__ float g_ne[BB*KT*DD];
__device__ float g_A[BB*KT*KT];
__device__ float g_u[BB*DD*DD];
__device__ float g_rq[BB*DD*DD];
__device__ float g_preh[BB*DD*DD];
__device__ float g_newQ[BB*DD*DD];
__device__ float g_P[BB*KT*DD];
__device__ float g_h1[BB*KT*DD];
__device__ float g_G[BB*KT*DD];

// ---------------------------------------------------------------------------
// K1: scorer
// ---------------------------------------------------------------------------
__global__ void __launch_bounds__(512) k_scorer(
    const float* __restrict__ ht, const float* __restrict__ W_map,
    const float* __restrict__ b_map, float* __restrict__ out)
{
    const int b = blockIdx.x, tid = threadIdx.x;
    __shared__ float sht[RR];
    __shared__ float part[4][DD];
    __shared__ float ssc[DD];
    __shared__ float s_inv;
    sht[tid] = ht[b*RR + tid];
    __syncthreads();
    const int d = tid & 127, rq = tid >> 7;
    float acc = 0.f;
    const int r0 = rq * 128;
    #pragma unroll 4
    for (int r = 0; r < 128; ++r) acc = fmaf(sht[r0 + r], W_map[(r0 + r)*DD + d], acc);
    part[rq][d] = acc;
    __syncthreads();
    if (tid < DD) {
        float s = part[0][tid] + part[1][tid] + part[2][tid] + part[3][tid] + b_map[tid];
        float sc = tanhf(s);
        ssc[tid] = sc;
        out[OFF_SCORER + b*DD + tid] = sc;
    }
    __syncthreads();
    if (tid < 32) {
        float s = 0.f;
        for (int i = tid; i < DD; i += 32) s += ssc[i]*ssc[i];
        #pragma unroll
        for (int o = 16; o; o >>= 1) s += __shfl_xor_sync(0xffffffffu, s, o);
        if (tid == 0) s_inv = 1.0f / sqrtf(s);
    }
    __syncthreads();
    if (tid < DD) g_scorer_n[b*DD + tid] = ssc[tid] * s_inv;
}

// ---------------------------------------------------------------------------
// K2: scores
// ---------------------------------------------------------------------------
__global__ void __launch_bounds__(128) k_scores(const float* __restrict__ node_embs)
{
    const int b = blockIdx.y, base = blockIdx.x * 128, tid = threadIdx.x;
    const int warp = tid >> 5, lane = tid & 31;
    __shared__ float4 ssc[32];
    if (tid < 32) ssc[tid] = ((const float4*)(g_scorer_n + b*DD))[tid];
    __syncthreads();
    const float4 sv = ssc[lane];
    #pragma unroll
    for (int t = 0; t < 32; t += 4) {
        const int n0 = base + warp * 32 + t;
        float a[4];
        #pragma unroll
        for (int q = 0; q < 4; ++q) {
            const float4 v = ((const float4*)(node_embs + ((size_t)(b*NN + n0 + q))*DD))[lane];
            a[q] = v.x*sv.x + v.y*sv.y + v.z*sv.z + v.w*sv.w;
        }
        #pragma unroll
        for (int o = 16; o; o >>= 1) {
            #pragma unroll
            for (int q = 0; q < 4; ++q) a[q] += __shfl_xor_sync(0xffffffffu, a[q], o);
        }
        if (lane < 4) g_scores[b*NN + n0 + lane] = a[lane];
    }
}

// ---------------------------------------------------------------------------
// K3: softmax stats + partial-bitonic top-64 + gather (A, z, ne)
// ---------------------------------------------------------------------------
__global__ void __launch_bounds__(512) k_topk_gather(
    const float* __restrict__ node_embs, const float* __restrict__ Ahat,
    float* __restrict__ out)
{
    extern __shared__ unsigned long long skey[];
    const int b = blockIdx.x, tid = threadIdx.x;
    const int warp = tid >> 5, lane = tid & 31;
    __shared__ float sred[16], sred2[16];
    __shared__ float s_M, s_logZ;
    __shared__ int   s_idx[KT];
    __shared__ float s_t[KT];
    __shared__ float s_v[KT];
    __shared__ float s_di[KT];

    float lmax = -INFINITY;
    for (int n = tid; n < NN; n += 512) {
        float s = g_scores[b*NN + n];
        lmax = fmaxf(lmax, s);
        unsigned u = __float_as_uint(s);
        unsigned m = (u & 0x80000000u) ? ~u : (u | 0x80000000u);
        skey[n] = ((unsigned long long)m << 32) | (unsigned)(NN - 1 - n);
    }
    #pragma unroll
    for (int o = 16; o; o >>= 1) lmax = fmaxf(lmax, __shfl_xor_sync(0xffffffffu, lmax, o));
    if (lane == 0) sred[warp] = lmax;
    __syncthreads();
    if (tid == 0) { float m = -INFINITY; for (int w = 0; w < 16; ++w) m = fmaxf(m, sred[w]); s_M = m; }
    __syncthreads();
    const float M = s_M;

    float s1 = 0.f, s2 = 0.f;
    for (int n = tid; n < NN; n += 512) {
        float s = g_scores[b*NN + n];
        float e = __expf(s - M);
        s1 += e; s2 = fmaf(s, e, s2);
    }
    #pragma unroll
    for (int o = 16; o; o >>= 1) {
        s1 += __shfl_xor_sync(0xffffffffu, s1, o);
        s2 += __shfl_xor_sync(0xffffffffu, s2, o);
    }
    if (lane == 0) { sred[warp] = s1; sred2[warp] = s2; }
    __syncthreads();
    if (tid == 0) {
        float S1 = 0.f, S2 = 0.f;
        for (int w = 0; w < 16; ++w) { S1 += sred[w]; S2 += sred2[w]; }
        float logZ = M + logf(S1);
        s_logZ = logZ;
        out[OFF_ENT + b] = logZ - S2 / S1;
    }

    for (int k = 2; k <= KT; k <<= 1) {
        for (int j = k >> 1; j > 0; j >>= 1) {
            __syncthreads();
            #pragma unroll
            for (int p = 0; p < 8; ++p) {
                const int i = tid + p * 512;
                const int l = i ^ j;
                if (l > i) {
                    u64 a = skey[i], c = skey[l];
                    bool desc = ((i & k) == 0);
                    if (desc ? (a < c) : (a > c)) { skey[i] = c; skey[l] = a; }
                }
            }
        }
    }
    for (int size = NN; size > KT; size >>= 1) {
        const int half = size >> 1;
        __syncthreads();
        u64 tv[4]; int cnt = 0;
        for (int e = tid; e < half; e += 512) {
            int p = e >> 6, t = e & 63;
            u64 a = skey[p*128 + t], c = skey[p*128 + 64 + t];
            tv[cnt++] = (a > c) ? a : c;
        }
        __syncthreads();
        cnt = 0;
        for (int e = tid; e < half; e += 512) skey[e] = tv[cnt++];
        for (int j = 32; j > 0; j >>= 1) {
            __syncthreads();
            for (int i = tid; i < half; i += 512) {
                const int l = i ^ j;
                if (l > i) {
                    u64 a = skey[i], c = skey[l];
                    bool desc = ((i & KT) == 0);
                    if (desc ? (a < c) : (a > c)) { skey[i] = c; skey[l] = a; }
                }
            }
        }
    }
    __syncthreads();

    if (tid < KT) {
        u64 kk = skey[tid];
        int n = NN - 1 - (int)(kk & 0xFFFu);
        unsigned m = (unsigned)(kk >> 32);
        unsigned u = (m & 0x80000000u) ? (m ^ 0x80000000u) : ~m;
        float s = __uint_as_float(u);
        s_idx[tid] = n; s_t[tid] = tanhf(s); s_v[tid] = s;
    }
    __syncthreads();
    if (tid == 0) {
        float sum = 0.f;
        for (int i = 0; i < KT; ++i) sum += s_v[i];
        out[OFF_POL + b] = sum * (1.f/KT) - s_logZ;
    }

    float* sA = (float*)skey;
    for (int e = tid; e < KT*KT; e += 512) {
        int i = e >> 6, j = e & 63;
        sA[e] = Ahat[(size_t)b*NN*NN + (size_t)s_idx[i]*NN + s_idx[j]];
    }
    __syncthreads();
    if (tid < KT) {
        float s = 0.f;
        for (int i = 0; i < KT; ++i) s += sA[i*KT + tid];
        s_di[tid] = 1.0f / sqrtf(s);
    }
    __syncthreads();
    for (int e = tid; e < KT*KT; e += 512) {
        int i = e >> 6, j = e & 63;
        g_A[b*KT*KT + e] = s_di[j] * sA[e] * s_di[i];
    }

    for (int i = warp; i < DD; i += 16) {
        int k = i & (KT - 1);
        const float* e = node_embs + ((size_t)(b*NN + s_idx[k]))*DD;
        float tv2 = s_t[k];
        for (int d = lane; d < DD; d += 32) {
            float val = e[d];
            g_z[((size_t)b*DD + d)*DD + i] = val * tv2;
            if (i < KT) g_ne[(b*KT + i)*DD + d] = val;
        }
    }
}

// ---------------------------------------------------------------------------
// K4: fused u / rq / preh. 256 thr; 2 rows/warp, k-split x4.
// grid (32, B): 4 rows/block; warp = pr*4 + g.
// ---------------------------------------------------------------------------
__global__ void __launch_bounds__(256) k_gates(
    const float* __restrict__ prevQ,
    const float* __restrict__ Wu, const float* __restrict__ Uu, const float* __restrict__ bu,
    const float* __restrict__ Wr, const float* __restrict__ Ur, const float* __restrict__ br,
    const float* __restrict__ Wh, const float* __restrict__ bh)
{
    extern __shared__ char smraw[];
    u64*    swt = (u64*)smraw;                         // 5*512 u64 (20KB)
    float4* sz  = (float4*)(smraw + 5*512*8);          // 2*512 float4 (16KB)
    float4* sq  = sz + 2*512;                          // 2*512 float4 (16KB)
    const int b = blockIdx.y, i0 = blockIdx.x*4;
    const int tid = threadIdx.x, w = tid>>5, lane = tid&31;
    const int pr = w >> 2, g = w & 3;
    const int rA = pr*2, rB = rA + 1;
    const int giA = i0 + rA, giB = i0 + rB;

    for (int e = tid; e < 512; e += 256) {
        int r = e>>7, k = e&127;
        float a;
        a = Wu[(i0+r)*DD+k]; swt[       e] = pk2(a,a);
        a = Uu[(i0+r)*DD+k]; swt[ 512 + e] = pk2(a,a);
        a = Wr[(i0+r)*DD+k]; swt[1024 + e] = pk2(a,a);
        a = Ur[(i0+r)*DD+k]; swt[1536 + e] = pk2(a,a);
        a = Wh[(i0+r)*DD+k]; swt[2048 + e] = pk2(a,a);
    }
    const float* z = g_z + (size_t)b*DD*DD;
    const float* Q = prevQ + (size_t)b*DD*DD;

    float4 rz[2], rqv[2];
    #pragma unroll
    for (int p = 0; p < 2; ++p) {
        int e = tid + 256*p;
        rz[p]  = ((const float4*)(z + (size_t)(e>>5)*DD))[e&31];
        rqv[p] = ((const float4*)(Q + (size_t)(e>>5)*DD))[e&31];
    }
    #pragma unroll
    for (int p = 0; p < 2; ++p) { int e = tid+256*p; sz[e]=rz[p]; sq[e]=rqv[p]; }
    __syncthreads();

    u64 auA0=0,auA1=0,arA0=0,arA1=0,ahA0=0,ahA1=0;
    u64 auB0=0,auB1=0,arB0=0,arB1=0,ahB0=0,ahB1=0;
    if (g == 0) {
        float4 v;
        v = *(const float4*)&bu[giA*DD + 4*lane]; auA0=pk2(v.x,v.y); auA1=pk2(v.z,v.w);
        v = *(const float4*)&br[giA*DD + 4*lane]; arA0=pk2(v.x,v.y); arA1=pk2(v.z,v.w);
        v = *(const float4*)&bh[giA*DD + 4*lane]; ahA0=pk2(v.x,v.y); ahA1=pk2(v.z,v.w);
        v = *(const float4*)&bu[giB*DD + 4*lane]; auB0=pk2(v.x,v.y); auB1=pk2(v.z,v.w);
        v = *(const float4*)&br[giB*DD + 4*lane]; arB0=pk2(v.x,v.y); arB1=pk2(v.z,v.w);
        v = *(const float4*)&bh[giB*DD + 4*lane]; ahB0=pk2(v.x,v.y); ahB1=pk2(v.z,v.w);
    }

    for (int c = 0; c < 8; ++c) {
        const int cb = c & 1, nb = cb ^ 1;
        if (c < 7) {
            #pragma unroll
            for (int p = 0; p < 2; ++p) {
                int e = tid + 256*p;
                int r16 = (c+1)*16 + (e>>5);
                rz[p]  = ((const float4*)(z + (size_t)r16*DD))[e&31];
                rqv[p] = ((const float4*)(Q + (size_t)r16*DD))[e&31];
            }
        }
        const ulonglong2* zz = (const ulonglong2*)(sz + cb*512);
        const ulonglong2* qq = (const ulonglong2*)(sq + cb*512);
        const int kb = c*16 + g*4;
        const u64* pA = swt + rA*128 + kb;
        const u64* pB = swt + rB*128 + kb;
        #pragma unroll
        for (int q = 0; q < 4; ++q) {
            ulonglong2 zv = zz[(g*4+q)*32 + lane];
            ulonglong2 qv = qq[(g*4+q)*32 + lane];
            u64 wuA=pA[q], uuA=pA[512+q], wrA=pA[1024+q], urA=pA[1536+q], whA=pA[2048+q];
            u64 wuB=pB[q], uuB=pB[512+q], wrB=pB[1024+q], urB=pB[1536+q], whB=pB[2048+q];
            auA0=ffma2(wuA,zv.x,auA0); auA1=ffma2(wuA,zv.y,auA1);
            auA0=ffma2(uuA,qv.x,auA0); auA1=ffma2(uuA,qv.y,auA1);
            arA0=ffma2(wrA,zv.x,arA0); arA1=ffma2(wrA,zv.y,arA1);
            arA0=ffma2(urA,qv.x,arA0); arA1=ffma2(urA,qv.y,arA1);
            ahA0=ffma2(whA,zv.x,ahA0); ahA1=ffma2(whA,zv.y,ahA1);
            auB0=ffma2(wuB,zv.x,auB0); auB1=ffma2(wuB,zv.y,auB1);
            auB0=ffma2(uuB,qv.x,auB0); auB1=ffma2(uuB,qv.y,auB1);
            arB0=ffma2(wrB,zv.x,arB0); arB1=ffma2(wrB,zv.y,arB1);
            arB0=ffma2(urB,qv.x,arB0); arB1=ffma2(urB,qv.y,arB1);
            ahB0=ffma2(whB,zv.x,ahB0); ahB1=ffma2(whB,zv.y,ahB1);
        }
        if (c < 7) {
            #pragma unroll
            for (int p = 0; p < 2; ++p) { int e = tid+256*p; sz[nb*512+e]=rz[p]; sq[nb*512+e]=rqv[p]; }
        }
        __syncthreads();
    }

    // 4-way reduction: groups 1..3 store 12 partials each
    u64* sp = (u64*)sz;   // 32KB region
    if (g > 0) {
        int base = (pr*36 + (g-1)*12)*32 + lane;
        sp[base+0*32]=auA0;  sp[base+1*32]=auA1;  sp[base+2*32]=arA0;  sp[base+3*32]=arA1;
        sp[base+4*32]=ahA0;  sp[base+5*32]=ahA1;  sp[base+6*32]=auB0;  sp[base+7*32]=auB1;
        sp[base+8*32]=arB0;  sp[base+9*32]=arB1;  sp[base+10*32]=ahB0; sp[base+11*32]=ahB1;
    }
    __syncthreads();
    if (g == 0) {
        #pragma unroll
        for (int gi = 0; gi < 3; ++gi) {
            int base = (pr*36 + gi*12)*32 + lane;
            auA0=padd2(auA0,sp[base+0*32]);  auA1=padd2(auA1,sp[base+1*32]);
            arA0=padd2(arA0,sp[base+2*32]);  arA1=padd2(arA1,sp[base+3*32]);
            ahA0=padd2(ahA0,sp[base+4*32]);  ahA1=padd2(ahA1,sp[base+5*32]);
            auB0=padd2(auB0,sp[base+6*32]);  auB1=padd2(auB1,sp[base+7*32]);
            arB0=padd2(arB0,sp[base+8*32]);  arB1=padd2(arB1,sp[base+9*32]);
            ahB0=padd2(ahB0,sp[base+10*32]); ahB1=padd2(ahB1,sp[base+11*32]);
        }
        float f0,f1,f2,f3;
        {
            const size_t o = ((size_t)b*DD + giA)*DD + 4*lane;
            up2(auA0,f0,f1); up2(auA1,f2,f3);
            *(float4*)&g_u[o] = make_float4(sigf(f0),sigf(f1),sigf(f2),sigf(f3));
            up2(arA0,f0,f1); up2(arA1,f2,f3);
            float4 q4 = *(const float4*)&Q[(size_t)giA*DD + 4*lane];
            *(float4*)&g_rq[o] = make_float4(sigf(f0)*q4.x, sigf(f1)*q4.y, sigf(f2)*q4.z, sigf(f3)*q4.w);
            up2(ahA0,f0,f1); up2(ahA1,f2,f3);
            *(float4*)&g_preh[o] = make_float4(f0,f1,f2,f3);
        }
        {
            const size_t o = ((size_t)b*DD + giB)*DD + 4*lane;
            up2(auB0,f0,f1); up2(auB1,f2,f3);
            *(float4*)&g_u[o] = make_float4(sigf(f0),sigf(f1),sigf(f2),sigf(f3));
            up2(arB0,f0,f1); up2(arB1,f2,f3);
            float4 q4 = *(const float4*)&Q[(size_t)giB*DD + 4*lane];
            *(float4*)&g_rq[o] = make_float4(sigf(f0)*q4.x, sigf(f1)*q4.y, sigf(f2)*q4.z, sigf(f3)*q4.w);
            up2(ahB0,f0,f1); up2(ahB1,f2,f3);
            *(float4*)&g_preh[o] = make_float4(f0,f1,f2,f3);
        }
    }
}

// ---------------------------------------------------------------------------
// K5: newQ. 256 thr, 2 rows/warp, k-split x4. grid (32, B).
// ---------------------------------------------------------------------------
__global__ void __launch_bounds__(256) k_newQ(
    const float* __restrict__ prevQ, const float* __restrict__ Uh)
{
    __shared__ u64 swt[512];
    __shared__ float4 sb[2*512];
    __shared__ u64 sp[2*12*32];
    const int b = blockIdx.y, i0 = blockIdx.x*4;
    const int tid = threadIdx.x, w = tid>>5, lane = tid&31;
    const int pr = w >> 2, g = w & 3;
    const int rA = pr*2, rB = rA + 1;
    const int giA = i0 + rA, giB = i0 + rB;
    for (int e = tid; e < 512; e += 256) {
        float a = Uh[(i0 + (e>>7))*DD + (e&127)]; swt[e] = pk2(a,a);
    }
    const float* Bm = g_rq + (size_t)b*DD*DD;
    float4 rb[2];
    #pragma unroll
    for (int p = 0; p < 2; ++p) { int e = tid+256*p; rb[p] = ((const float4*)(Bm + (size_t)(e>>5)*DD))[e&31]; }
    #pragma unroll
    for (int p = 0; p < 2; ++p) { int e = tid+256*p; sb[e]=rb[p]; }
    __syncthreads();
    u64 aA0=0,aA1=0,aB0=0,aB1=0;
    for (int c = 0; c < 8; ++c) {
        const int cb = c & 1, nb = cb ^ 1;
        if (c < 7) {
            #pragma unroll
            for (int p = 0; p < 2; ++p) {
                int e = tid + 256*p;
                rb[p] = ((const float4*)(Bm + (size_t)((c+1)*16 + (e>>5))*DD))[e&31];
            }
        }
        const ulonglong2* bb = (const ulonglong2*)(sb + cb*512);
        const u64* pA = swt + rA*128 + c*16 + g*4;
        const u64* pB = swt + rB*128 + c*16 + g*4;
        #pragma unroll
        for (int q = 0; q < 4; ++q) {
            ulonglong2 bv = bb[(g*4+q)*32 + lane];
            u64 wtA = pA[q], wtB = pB[q];
            aA0 = ffma2(wtA, bv.x, aA0); aA1 = ffma2(wtA, bv.y, aA1);
            aB0 = ffma2(wtB, bv.x, aB0); aB1 = ffma2(wtB, bv.y, aB1);
        }
        if (c < 7) {
            #pragma unroll
            for (int p = 0; p < 2; ++p) { int e = tid+256*p; sb[nb*512+e]=rb[p]; }
        }
        __syncthreads();
    }
    if (g > 0) {
        int base = (pr*12 + (g-1)*4)*32 + lane;
        sp[base] = aA0; sp[base+32] = aA1; sp[base+64] = aB0; sp[base+96] = aB1;
    }
    __syncthreads();
    if (g == 0) {
        #pragma unroll
        for (int gi = 0; gi < 3; ++gi) {
            int base = (pr*12 + gi*4)*32 + lane;
            aA0 = padd2(aA0, sp[base]);    aA1 = padd2(aA1, sp[base+32]);
            aB0 = padd2(aB0, sp[base+64]); aB1 = padd2(aB1, sp[base+96]);
        }
        float f0,f1,f2,f3;
        {
            up2(aA0,f0,f1); up2(aA1,f2,f3);
            const size_t o = ((size_t)b*DD + giA)*DD + 4*lane;
            float4 ph = *(const float4*)&g_preh[o];
            float4 uv = *(const float4*)&g_u[o];
            float4 q4 = *(const float4*)&prevQ[(size_t)b*DD*DD + giA*DD + 4*lane];
            float h0 = tanhf(f0+ph.x), h1 = tanhf(f1+ph.y), h2 = tanhf(f2+ph.z), h3 = tanhf(f3+ph.w);
            *(float4*)&g_newQ[o] = make_float4(
                (1.f-uv.x)*q4.x + uv.x*h0, (1.f-uv.y)*q4.y + uv.y*h1,
                (1.f-uv.z)*q4.z + uv.z*h2, (1.f-uv.w)*q4.w + uv.w*h3);
        }
        {
            up2(aB0,f0,f1); up2(aB1,f2,f3);
            const size_t o = ((size_t)b*DD + giB)*DD + 4*lane;
            float4 ph = *(const float4*)&g_preh[o];
            float4 uv = *(const float4*)&g_u[o];
            float4 q4 = *(const float4*)&prevQ[(size_t)b*DD*DD + giB*DD + 4*lane];
            float h0 = tanhf(f0+ph.x), h1 = tanhf(f1+ph.y), h2 = tanhf(f2+ph.z), h3 = tanhf(f3+ph.w);
            *(float4*)&g_newQ[o] = make_float4(
                (1.f-uv.x)*q4.x + uv.x*h0, (1.f-uv.y)*q4.y + uv.y*h1,
                (1.f-uv.z)*q4.z + uv.z*h2, (1.f-uv.w)*q4.w + uv.w*h3);
        }
    }
}

// ---------------------------------------------------------------------------
// K6: P = ne @ newQ. 256 thr, 2 rows/warp, k-split x4. grid (16, B).
// ---------------------------------------------------------------------------
__global__ void __launch_bounds__(256) k_g1()
{
    __shared__ u64 swt[512];
    __shared__ float4 sb[2*512];
    __shared__ u64 sp[2*12*32];
    const int b = blockIdx.y, i0 = blockIdx.x*4;
    const int tid = threadIdx.x, w = tid>>5, lane = tid&31;
    const int pr = w >> 2, g = w & 3;
    const int rA = pr*2, rB = rA + 1;
    const int giA = i0 + rA, giB = i0 + rB;
    for (int e = tid; e < 512; e += 256) {
        float a = g_ne[((size_t)b*KT + i0 + (e>>7))*DD + (e&127)]; swt[e] = pk2(a,a);
    }
    const float* Bm = g_newQ + (size_t)b*DD*DD;
    float4 rb[2];
    #pragma unroll
    for (int p = 0; p < 2; ++p) { int e = tid+256*p; rb[p] = ((const float4*)(Bm + (size_t)(e>>5)*DD))[e&31]; }
    #pragma unroll
    for (int p = 0; p < 2; ++p) { int e = tid+256*p; sb[e]=rb[p]; }
    __syncthreads();
    u64 aA0=0,aA1=0,aB0=0,aB1=0;
    for (int c = 0; c < 8; ++c) {
        const int cb = c & 1, nb = cb ^ 1;
        if (c < 7) {
            #pragma unroll
            for (int p = 0; p < 2; ++p) {
                int e = tid + 256*p;
                rb[p] = ((const float4*)(Bm + (size_t)((c+1)*16 + (e>>5))*DD))[e&31];
            }
        }
        const ulonglong2* bb = (const ulonglong2*)(sb + cb*512);
        const u64* pA = swt + rA*128 + c*16 + g*4;
        const u64* pB = swt + rB*128 + c*16 + g*4;
        #pragma unroll
        for (int q = 0; q < 4; ++q) {
            ulonglong2 bv = bb[(g*4+q)*32 + lane];
            u64 wtA = pA[q], wtB = pB[q];
            aA0 = ffma2(wtA, bv.x, aA0); aA1 = ffma2(wtA, bv.y, aA1);
            aB0 = ffma2(wtB, bv.x, aB0); aB1 = ffma2(wtB, bv.y, aB1);
        }
        if (c < 7) {
            #pragma unroll
            for (int p = 0; p < 2; ++p) { int e = tid+256*p; sb[nb*512+e]=rb[p]; }
        }
        __syncthreads();
    }
    if (g > 0) {
        int base = (pr*12 + (g-1)*4)*32 + lane;
        sp[base] = aA0; sp[base+32] = aA1; sp[base+64] = aB0; sp[base+96] = aB1;
    }
    __syncthreads();
    if (g == 0) {
        #pragma unroll
        for (int gi = 0; gi < 3; ++gi) {
            int base = (pr*12 + gi*4)*32 + lane;
            aA0 = padd2(aA0, sp[base]);    aA1 = padd2(aA1, sp[base+32]);
            aB0 = padd2(aB0, sp[base+64]); aB1 = padd2(aB1, sp[base+96]);
        }
        float f0,f1,f2,f3;
        up2(aA0,f0,f1); up2(aA1,f2,f3);
        *(float4*)&g_P[((size_t)b*KT + giA)*DD + 4*lane] = make_float4(f0,f1,f2,f3);
        up2(aB0,f0,f1); up2(aB1,f2,f3);
        *(float4*)&g_P[((size_t)b*KT + giB)*DD + 4*lane] = make_float4(f0,f1,f2,f3);
    }
}

// ---------------------------------------------------------------------------
// K7: h1 = relu(A@P); G = h1@staticW. 256 thr, 2 rows/warp, k-split x4.
// grid (16, B).
// ---------------------------------------------------------------------------
__global__ void __launch_bounds__(256) k_g23(const float* __restrict__ sW)
{
    __shared__ u64 sAW[4*KT];
    __shared__ u64 sh1p[4*DD];
    __shared__ float buf[KT*DD];
    __shared__ u64 sp[2*12*32];
    const int b = blockIdx.y, i0 = blockIdx.x*4;
    const int tid = threadIdx.x, w = tid>>5, lane = tid&31;
    const int pr = w >> 2, g = w & 3;
    const int rA = pr*2, rB = rA + 1;
    const int giA = i0 + rA, giB = i0 + rB;
    for (int e = tid; e < 4*KT; e += 256) {
        float a = g_A[b*KT*KT + (i0 + (e>>6))*KT + (e&63)]; sAW[e] = pk2(a,a);
    }
    float4* bf4 = (float4*)buf;
    const float4* Psrc = (const float4*)(g_P + (size_t)b*KT*DD);
    for (int e = tid; e < 2048; e += 256) bf4[e] = Psrc[e];
    __syncthreads();

    // Phase 1: A @ P over k=64, split 4 ways (16 each)
    u64 aA0=0,aA1=0,aB0=0,aB1=0;
    {
        const ulonglong2* bb = (const ulonglong2*)buf;
        const u64* pA = sAW + rA*KT + g*16;
        const u64* pB = sAW + rB*KT + g*16;
        #pragma unroll
        for (int q = 0; q < 16; ++q) {
            ulonglong2 bv = bb[(g*16+q)*32 + lane];
            u64 wtA = pA[q], wtB = pB[q];
            aA0 = ffma2(wtA, bv.x, aA0); aA1 = ffma2(wtA, bv.y, aA1);
            aB0 = ffma2(wtB, bv.x, aB0); aB1 = ffma2(wtB, bv.y, aB1);
        }
    }
    __syncthreads();   // phase-1 readers of buf done
    if (g > 0) {
        int base = (pr*12 + (g-1)*4)*32 + lane;
        sp[base] = aA0; sp[base+32] = aA1; sp[base+64] = aB0; sp[base+96] = aB1;
    }
    __syncthreads();
    if (g == 0) {
        #pragma unroll
        for (int gi = 0; gi < 3; ++gi) {
            int base = (pr*12 + gi*4)*32 + lane;
            aA0 = padd2(aA0, sp[base]);    aA1 = padd2(aA1, sp[base+32]);
            aB0 = padd2(aB0, sp[base+64]); aB1 = padd2(aB1, sp[base+96]);
        }
        float f0,f1,f2,f3;
        up2(aA0,f0,f1); up2(aA1,f2,f3);
        f0=fmaxf(f0,0.f); f1=fmaxf(f1,0.f); f2=fmaxf(f2,0.f); f3=fmaxf(f3,0.f);
        *(float4*)&g_h1[((size_t)b*KT + giA)*DD + 4*lane] = make_float4(f0,f1,f2,f3);
        sh1p[rA*DD + 4*lane+0]=pk2(f0,f0); sh1p[rA*DD + 4*lane+1]=pk2(f1,f1);
        sh1p[rA*DD + 4*lane+2]=pk2(f2,f2); sh1p[rA*DD + 4*lane+3]=pk2(f3,f3);
        up2(aB0,f0,f1); up2(aB1,f2,f3);
        f0=fmaxf(f0,0.f); f1=fmaxf(f1,0.f); f2=fmaxf(f2,0.f); f3=fmaxf(f3,0.f);
        *(float4*)&g_h1[((size_t)b*KT + giB)*DD + 4*lane] = make_float4(f0,f1,f2,f3);
        sh1p[rB*DD + 4*lane+0]=pk2(f0,f0); sh1p[rB*DD + 4*lane+1]=pk2(f1,f1);
        sh1p[rB*DD + 4*lane+2]=pk2(f2,f2); sh1p[rB*DD + 4*lane+3]=pk2(f3,f3);
    }
    __syncthreads();

    // Phase 2: G = h1 @ sW, k=128, chunks of 32 rows double-buffered in buf
    float4 rb[4];
    #pragma unroll
    for (int p = 0; p < 4; ++p) {
        int e = tid + 256*p;
        rb[p] = ((const float4*)(sW + (size_t)(e>>5)*DD))[e&31];
    }
    #pragma unroll
    for (int p = 0; p < 4; ++p) { int e = tid+256*p; bf4[e] = rb[p]; }
    __syncthreads();
    u64 gA0=0,gA1=0,gB0=0,gB1=0;
    for (int c = 0; c < 4; ++c) {
        const int cb = c & 1, nb = cb ^ 1;
        if (c < 3) {
            #pragma unroll
            for (int p = 0; p < 4; ++p) {
                int e = tid + 256*p;
                rb[p] = ((const float4*)(sW + (size_t)((c+1)*32 + (e>>5))*DD))[e&31];
            }
        }
        const ulonglong2* bb = (const ulonglong2*)(buf + cb*4096);
        const u64* hA = sh1p + rA*DD + c*32 + g*8;
        const u64* hB = sh1p + rB*DD + c*32 + g*8;
        #pragma unroll
        for (int q = 0; q < 8; ++q) {
            ulonglong2 bv = bb[(g*8+q)*32 + lane];
            u64 wtA = hA[q], wtB = hB[q];
            gA0 = ffma2(wtA, bv.x, gA0); gA1 = ffma2(wtA, bv.y, gA1);
            gB0 = ffma2(wtB, bv.x, gB0); gB1 = ffma2(wtB, bv.y, gB1);
        }
        if (c < 3) {
            #pragma unroll
            for (int p = 0; p < 4; ++p) { int e = tid+256*p; bf4[nb*1024 + e] = rb[p]; }
        }
        __syncthreads();
    }
    if (g > 0) {
        int base = (pr*12 + (g-1)*4)*32 + lane;
        sp[base] = gA0; sp[base+32] = gA1; sp[base+64] = gB0; sp[base+96] = gB1;
    }
    __syncthreads();
    if (g == 0) {
        #pragma unroll
        for (int gi = 0; gi < 3; ++gi) {
            int base = (pr*12 + gi*4)*32 + lane;
            gA0 = padd2(gA0, sp[base]);    gA1 = padd2(gA1, sp[base+32]);
            gB0 = padd2(gB0, sp[base+64]); gB1 = padd2(gB1, sp[base+96]);
        }
        float f0,f1,f2,f3;
        up2(gA0,f0,f1); up2(gA1,f2,f3);
        *(float4*)&g_G[((size_t)b*KT + giA)*DD + 4*lane] = make_float4(f0,f1,f2,f3);
        up2(gB0,f0,f1); up2(gB1,f2,f3);
        *(float4*)&g_G[((size_t)b*KT + giB)*DD + 4*lane] = make_float4(f0,f1,f2,f3);
    }
}

// ---------------------------------------------------------------------------
// K8: out = (h1 + relu(A @ G)) / 2. 256 thr, 2 rows/warp, k-split x4.
// ---------------------------------------------------------------------------
__global__ void __launch_bounds__(256) k_g4(float* __restrict__ out)
{
    __shared__ u64 sAW[4*KT];
    __shared__ float buf[KT*DD];
    __shared__ u64 sp[2*12*32];
    const int b = blockIdx.y, i0 = blockIdx.x*4;
    const int tid = threadIdx.x, w = tid>>5, lane = tid&31;
    const int pr = w >> 2, g = w & 3;
    const int rA = pr*2, rB = rA + 1;
    const int giA = i0 + rA, giB = i0 + rB;
    for (int e = tid; e < 4*KT; e += 256) {
        float a = g_A[b*KT*KT + (i0 + (e>>6))*KT + (e&63)]; sAW[e] = pk2(a,a);
    }
    float4* bf4 = (float4*)buf;
    const float4* Gsrc = (const float4*)(g_G + (size_t)b*KT*DD);
    for (int e = tid; e < 2048; e += 256) bf4[e] = Gsrc[e];
    __syncthreads();
    u64 aA0=0,aA1=0,aB0=0,aB1=0;
    const ulonglong2* bb = (const ulonglong2*)buf;
    const u64* pA = sAW + rA*KT + g*16;
    const u64* pB = sAW + rB*KT + g*16;
    #pragma unroll
    for (int q = 0; q < 16; ++q) {
        ulonglong2 bv = bb[(g*16+q)*32 + lane];
        u64 wtA = pA[q], wtB = pB[q];
        aA0 = ffma2(wtA, bv.x, aA0); aA1 = ffma2(wtA, bv.y, aA1);
        aB0 = ffma2(wtB, bv.x, aB0); aB1 = ffma2(wtB, bv.y, aB1);
    }
    if (g > 0) {
        int base = (pr*12 + (g-1)*4)*32 + lane;
        sp[base] = aA0; sp[base+32] = aA1; sp[base+64] = aB0; sp[base+96] = aB1;
    }
    __syncthreads();
    if (g == 0) {
        #pragma unroll
        for (int gi = 0; gi < 3; ++gi) {
            int base = (pr*12 + gi*4)*32 + lane;
            aA0 = padd2(aA0, sp[base]);    aA1 = padd2(aA1, sp[base+32]);
            aB0 = padd2(aB0, sp[base+64]); aB1 = padd2(aB1, sp[base+96]);
        }
        float f0,f1,f2,f3;
        up2(aA0,f0,f1); up2(aA1,f2,f3);
        {
            float4 h1v = *(const float4*)&g_h1[((size_t)b*KT + giA)*DD + 4*lane];
            *(float4*)&out[((size_t)b*KT + giA)*DD + 4*lane] = make_float4(
                (h1v.x + fmaxf(f0,0.f))*0.5f, (h1v.y + fmaxf(f1,0.f))*0.5f,
                (h1v.z + fmaxf(f2,0.f))*0.5f, (h1v.w + fmaxf(f3,0.f))*0.5f);
        }
        up2(aB0,f0,f1); up2(aB1,f2,f3);
        {
            float4 h1v = *(const float4*)&g_h1[((size_t)b*KT + giB)*DD + 4*lane];
            *(float4*)&out[((size_t)b*KT + giB)*DD + 4*lane] = make_float4(
                (h1v.x + fmaxf(f0,0.f))*0.5f, (h1v.y + fmaxf(f1,0.f))*0.5f,
                (h1v.z + fmaxf(f2,0.f))*0.5f, (h1v.w + fmaxf(f3,0.f))*0.5f);
        }
    }
}

// ---------------------------------------------------------------------------
extern "C" void kernel_launch(void* const* d_in, const int* in_sizes, int n_in,
                              void* d_out, int out_size)
{
    const float* Ahat      = (const float*)d_in[0];
    const float* node_embs = (const float*)d_in[1];
    const float* ht        = (const float*)d_in[3];
    const float* prevQ     = (const float*)d_in[4];
    const float* W_map     = (const float*)d_in[5];
    const float* b_map     = (const float*)d_in[6];
    const float* Wu        = (const float*)d_in[7];
    const float* Uu        = (const float*)d_in[8];
    const float* bu        = (const float*)d_in[9];
    const float* Wr        = (const float*)d_in[10];
    const float* Ur        = (const float*)d_in[11];
    const float* br        = (const float*)d_in[12];
    const float* Wh        = (const float*)d_in[13];
    const float* Uh        = (const float*)d_in[14];
    const float* bh        = (const float*)d_in[15];
    const float* sW        = (const float*)d_in[16];
    float* out = (float*)d_out;

    const int gates_smem = 5*512*8 + 2*512*16 + 2*512*16;   // 53248 B
    cudaFuncSetAttribute(k_gates, cudaFuncAttributeMaxDynamicSharedMemorySize, gates_smem);

    k_scorer<<<BB, 512>>>(ht, W_map, b_map, out);
    k_scores<<<dim3(32, BB), 128>>>(node_embs);
    k_topk_gather<<<BB, 512, NN * sizeof(unsigned long long)>>>(node_embs, Ahat, out);
    k_gates<<<dim3(32, BB), 256, gates_smem>>>(prevQ, Wu, Uu, bu, Wr, Ur, br, Wh, bh);
    k_newQ<<<dim3(32, BB), 256>>>(prevQ, Uh);
    k_g1<<<dim3(16, BB), 256>>>();
    k_g23<<<dim3(16, BB), 256>>>(sW);
    k_g4<<<dim3(16, BB), 256>>>(out);
}

// round 8
// speedup vs baseline: 3.8261x; 1.0700x over previous
#include <cuda_runtime.h>
#include <math.h>

#define BB 8
#define NN 4096
#define DD 128
#define KT 64
#define RR 512

#define OFF_POL     (BB*KT*DD)
#define OFF_SCORER  (OFF_POL + BB)
#define OFF_ENT     (OFF_SCORER + BB*DD)

typedef unsigned long long u64;

__device__ __forceinline__ u64 pk2(float lo, float hi) {
    u64 r; asm("mov.b64 %0,{%1,%2};" : "=l"(r) : "f"(lo), "f"(hi)); return r;
}
__device__ __forceinline__ void up2(u64 v, float& lo, float& hi) {
    asm("mov.b64 {%0,%1},%2;" : "=f"(lo), "=f"(hi) : "l"(v));
}
__device__ __forceinline__ u64 ffma2(u64 a, u64 b, u64 c) {
    u64 d; asm("fma.rn.f32x2 %0,%1,%2,%3;" : "=l"(d) : "l"(a), "l"(b), "l"(c)); return d;
}
__device__ __forceinline__ u64 padd2(u64 a, u64 b) {
    u64 d; asm("add.rn.f32x2 %0,%1,%2;" : "=l"(d) : "l"(a), "l"(b)); return d;
}
__device__ __forceinline__ float sigf(float x) { return 1.f / (1.f + __expf(-x)); }

// Device scratch
__device__ float g_scorer_n[BB*DD];
__device__ float g_scores[BB*NN];
__device__ u64   g_keys[BB*NN];
__device__ float g_z[BB*DD*DD];
__device__ float g_ne[BB*KT*DD];
__device__ float g_A[BB*KT*KT];
__device__ float g_u[BB*DD*DD];
__device__ float g_rq[BB*DD*DD];
__device__ float g_preh[BB*DD*DD];
__device__ float g_newQ[BB*DD*DD];
__device__ float g_P[BB*KT*DD];
__device__ float g_h1[BB*KT*DD];
__device__ float g_G[BB*KT*DD];

// ---------------------------------------------------------------------------
// K1: scorer
// ---------------------------------------------------------------------------
__global__ void __launch_bounds__(512) k_scorer(
    const float* __restrict__ ht, const float* __restrict__ W_map,
    const float* __restrict__ b_map, float* __restrict__ out)
{
    const int b = blockIdx.x, tid = threadIdx.x;
    __shared__ float sht[RR];
    __shared__ float part[4][DD];
    __shared__ float ssc[DD];
    __shared__ float s_inv;
    sht[tid] = ht[b*RR + tid];
    __syncthreads();
    const int d = tid & 127, rq = tid >> 7;
    float acc = 0.f;
    const int r0 = rq * 128;
    #pragma unroll 4
    for (int r = 0; r < 128; ++r) acc = fmaf(sht[r0 + r], W_map[(r0 + r)*DD + d], acc);
    part[rq][d] = acc;
    __syncthreads();
    if (tid < DD) {
        float s = part[0][tid] + part[1][tid] + part[2][tid] + part[3][tid] + b_map[tid];
        float sc = tanhf(s);
        ssc[tid] = sc;
        out[OFF_SCORER + b*DD + tid] = sc;
    }
    __syncthreads();
    if (tid < 32) {
        float s = 0.f;
        for (int i = tid; i < DD; i += 32) s += ssc[i]*ssc[i];
        #pragma unroll
        for (int o = 16; o; o >>= 1) s += __shfl_xor_sync(0xffffffffu, s, o);
        if (tid == 0) s_inv = 1.0f / sqrtf(s);
    }
    __syncthreads();
    if (tid < DD) g_scorer_n[b*DD + tid] = ssc[tid] * s_inv;
}

// ---------------------------------------------------------------------------
// K2: scores + fused bitonic stage-1 (sort each aligned 64-block)
// ---------------------------------------------------------------------------
__global__ void __launch_bounds__(128) k_scores(const float* __restrict__ node_embs)
{
    const int b = blockIdx.y, base = blockIdx.x * 128, tid = threadIdx.x;
    const int warp = tid >> 5, lane = tid & 31;
    __shared__ float4 ssc[32];
    __shared__ float sc[128];
    __shared__ u64 keys[128];
    if (tid < 32) ssc[tid] = ((const float4*)(g_scorer_n + b*DD))[tid];
    __syncthreads();
    const float4 sv = ssc[lane];
    #pragma unroll
    for (int t = 0; t < 32; t += 4) {
        const int n0 = base + warp * 32 + t;
        float a[4];
        #pragma unroll
        for (int q = 0; q < 4; ++q) {
            const float4 v = ((const float4*)(node_embs + ((size_t)(b*NN + n0 + q))*DD))[lane];
            a[q] = v.x*sv.x + v.y*sv.y + v.z*sv.z + v.w*sv.w;
        }
        #pragma unroll
        for (int o = 16; o; o >>= 1) {
            #pragma unroll
            for (int q = 0; q < 4; ++q) a[q] += __shfl_xor_sync(0xffffffffu, a[q], o);
        }
        if (lane < 4) {
            g_scores[b*NN + n0 + lane] = a[lane];
            sc[warp*32 + t + lane] = a[lane];
        }
    }
    __syncthreads();
    // pack keys (same scheme as topk)
    {
        const int gi = base + tid;
        float s = sc[tid];
        unsigned u = __float_as_uint(s);
        unsigned m = (u & 0x80000000u) ? ~u : (u | 0x80000000u);
        keys[tid] = ((u64)m << 32) | (unsigned)(NN - 1 - gi);
    }
    __syncthreads();
    // bitonic stage-1: sort each 64-block, direction desc iff (i & k)==0
    // (base is a multiple of 128, so local index bits == global for k<=64)
    for (int k = 2; k <= KT; k <<= 1) {
        for (int j = k >> 1; j > 0; j >>= 1) {
            const int i = tid, l = tid ^ j;
            if (l > i) {
                u64 a = keys[i], c = keys[l];
                bool desc = ((i & k) == 0);
                if (desc ? (a < c) : (a > c)) { keys[i] = c; keys[l] = a; }
            }
            __syncthreads();
        }
    }
    g_keys[b*NN + base + tid] = keys[tid];
}

// ---------------------------------------------------------------------------
// K3: softmax stats + bitonic stage-2 top-64 + gather (A, z, ne)
// ---------------------------------------------------------------------------
__global__ void __launch_bounds__(512) k_topk_gather(
    const float* __restrict__ node_embs, const float* __restrict__ Ahat,
    float* __restrict__ out)
{
    extern __shared__ unsigned long long skey[];
    const int b = blockIdx.x, tid = threadIdx.x;
    const int warp = tid >> 5, lane = tid & 31;
    __shared__ float sred[16], sred2[16];
    __shared__ float s_M, s_logZ;
    __shared__ int   s_idx[KT];
    __shared__ float s_t[KT];
    __shared__ float s_v[KT];
    __shared__ float s_di[KT];

    float lmax = -INFINITY;
    for (int n = tid; n < NN; n += 512) {
        lmax = fmaxf(lmax, g_scores[b*NN + n]);
        skey[n] = g_keys[b*NN + n];
    }
    #pragma unroll
    for (int o = 16; o; o >>= 1) lmax = fmaxf(lmax, __shfl_xor_sync(0xffffffffu, lmax, o));
    if (lane == 0) sred[warp] = lmax;
    __syncthreads();
    if (tid == 0) { float m = -INFINITY; for (int w = 0; w < 16; ++w) m = fmaxf(m, sred[w]); s_M = m; }
    __syncthreads();
    const float M = s_M;

    float s1 = 0.f, s2 = 0.f;
    for (int n = tid; n < NN; n += 512) {
        float s = g_scores[b*NN + n];
        float e = __expf(s - M);
        s1 += e; s2 = fmaf(s, e, s2);
    }
    #pragma unroll
    for (int o = 16; o; o >>= 1) {
        s1 += __shfl_xor_sync(0xffffffffu, s1, o);
        s2 += __shfl_xor_sync(0xffffffffu, s2, o);
    }
    if (lane == 0) { sred[warp] = s1; sred2[warp] = s2; }
    __syncthreads();
    if (tid == 0) {
        float S1 = 0.f, S2 = 0.f;
        for (int w = 0; w < 16; ++w) { S1 += sred[w]; S2 += sred2[w]; }
        float logZ = M + logf(S1);
        s_logZ = logZ;
        out[OFF_ENT + b] = logZ - S2 / S1;
    }

    // Stage 2: halving rounds — half-cleaner max-compact + 64-block bitonic merge
    for (int size = NN; size > KT; size >>= 1) {
        const int half = size >> 1;
        __syncthreads();
        u64 tv[4]; int cnt = 0;
        for (int e = tid; e < half; e += 512) {
            int p = e >> 6, t = e & 63;
            u64 a = skey[p*128 + t], c = skey[p*128 + 64 + t];
            tv[cnt++] = (a > c) ? a : c;
        }
        __syncthreads();
        cnt = 0;
        for (int e = tid; e < half; e += 512) skey[e] = tv[cnt++];
        for (int j = 32; j > 0; j >>= 1) {
            __syncthreads();
            for (int i = tid; i < half; i += 512) {
                const int l = i ^ j;
                if (l > i) {
                    u64 a = skey[i], c = skey[l];
                    bool desc = ((i & KT) == 0);
                    if (desc ? (a < c) : (a > c)) { skey[i] = c; skey[l] = a; }
                }
            }
        }
    }
    __syncthreads();

    if (tid < KT) {
        u64 kk = skey[tid];
        int n = NN - 1 - (int)(kk & 0xFFFu);
        unsigned m = (unsigned)(kk >> 32);
        unsigned u = (m & 0x80000000u) ? (m ^ 0x80000000u) : ~m;
        float s = __uint_as_float(u);
        s_idx[tid] = n; s_t[tid] = tanhf(s); s_v[tid] = s;
    }
    __syncthreads();
    if (tid == 0) {
        float sum = 0.f;
        for (int i = 0; i < KT; ++i) sum += s_v[i];
        out[OFF_POL + b] = sum * (1.f/KT) - s_logZ;
    }

    float* sA = (float*)skey;
    for (int e = tid; e < KT*KT; e += 512) {
        int i = e >> 6, j = e & 63;
        sA[e] = Ahat[(size_t)b*NN*NN + (size_t)s_idx[i]*NN + s_idx[j]];
    }
    __syncthreads();
    if (tid < KT) {
        float s = 0.f;
        for (int i = 0; i < KT; ++i) s += sA[i*KT + tid];
        s_di[tid] = 1.0f / sqrtf(s);
    }
    __syncthreads();
    for (int e = tid; e < KT*KT; e += 512) {
        int i = e >> 6, j = e & 63;
        g_A[b*KT*KT + e] = s_di[j] * sA[e] * s_di[i];
    }

    for (int i = warp; i < DD; i += 16) {
        int k = i & (KT - 1);
        const float* e = node_embs + ((size_t)(b*NN + s_idx[k]))*DD;
        float tv2 = s_t[k];
        for (int d = lane; d < DD; d += 32) {
            float val = e[d];
            g_z[((size_t)b*DD + d)*DD + i] = val * tv2;
            if (i < KT) g_ne[(b*KT + i)*DD + d] = val;
        }
    }
}

// ---------------------------------------------------------------------------
// K4: fused u / rq / preh. 2 rows/block, k-split x8. grid (64, B), 256 thr.
// ---------------------------------------------------------------------------
__global__ void __launch_bounds__(256) k_gates(
    const float* __restrict__ prevQ,
    const float* __restrict__ Wu, const float* __restrict__ Uu, const float* __restrict__ bu,
    const float* __restrict__ Wr, const float* __restrict__ Ur, const float* __restrict__ br,
    const float* __restrict__ Wh, const float* __restrict__ bh)
{
    extern __shared__ char smraw[];
    u64*    swt = (u64*)smraw;                  // 5*256 u64 = 10KB
    float4* sz  = (float4*)(smraw + 1280*8);    // 2*512 float4 (16KB)
    float4* sq  = sz + 1024;                    // 2*512 float4 (16KB)
    const int b = blockIdx.y, i0 = blockIdx.x*2;
    const int tid = threadIdx.x, g = tid>>5, lane = tid&31;
    const int giA = i0, giB = i0 + 1;

    // weights: 5 mats x 2 rows x 128
    {
        int e = tid;   // 0..255 covers 2 rows x 128
        int r = e>>7, k = e&127;
        float a;
        a = Wu[(i0+r)*DD+k]; swt[       e] = pk2(a,a);
        a = Uu[(i0+r)*DD+k]; swt[ 256 + e] = pk2(a,a);
        a = Wr[(i0+r)*DD+k]; swt[ 512 + e] = pk2(a,a);
        a = Ur[(i0+r)*DD+k]; swt[ 768 + e] = pk2(a,a);
        a = Wh[(i0+r)*DD+k]; swt[1024 + e] = pk2(a,a);
    }
    const float* z = g_z + (size_t)b*DD*DD;
    const float* Q = prevQ + (size_t)b*DD*DD;

    float4 rz[2], rqv[2];
    #pragma unroll
    for (int p = 0; p < 2; ++p) {
        int e = tid + 256*p;
        rz[p]  = ((const float4*)(z + (size_t)(e>>5)*DD))[e&31];
        rqv[p] = ((const float4*)(Q + (size_t)(e>>5)*DD))[e&31];
    }
    #pragma unroll
    for (int p = 0; p < 2; ++p) { int e = tid+256*p; sz[e]=rz[p]; sq[e]=rqv[p]; }
    __syncthreads();

    u64 auA0=0,auA1=0,arA0=0,arA1=0,ahA0=0,ahA1=0;
    u64 auB0=0,auB1=0,arB0=0,arB1=0,ahB0=0,ahB1=0;
    if (g == 0) {
        float4 v;
        v = *(const float4*)&bu[giA*DD + 4*lane]; auA0=pk2(v.x,v.y); auA1=pk2(v.z,v.w);
        v = *(const float4*)&br[giA*DD + 4*lane]; arA0=pk2(v.x,v.y); arA1=pk2(v.z,v.w);
        v = *(const float4*)&bh[giA*DD + 4*lane]; ahA0=pk2(v.x,v.y); ahA1=pk2(v.z,v.w);
        v = *(const float4*)&bu[giB*DD + 4*lane]; auB0=pk2(v.x,v.y); auB1=pk2(v.z,v.w);
        v = *(const float4*)&br[giB*DD + 4*lane]; arB0=pk2(v.x,v.y); arB1=pk2(v.z,v.w);
        v = *(const float4*)&bh[giB*DD + 4*lane]; ahB0=pk2(v.x,v.y); ahB1=pk2(v.z,v.w);
    }

    for (int c = 0; c < 8; ++c) {
        const int cb = c & 1, nb = cb ^ 1;
        if (c < 7) {
            #pragma unroll
            for (int p = 0; p < 2; ++p) {
                int e = tid + 256*p;
                int r16 = (c+1)*16 + (e>>5);
                rz[p]  = ((const float4*)(z + (size_t)r16*DD))[e&31];
                rqv[p] = ((const float4*)(Q + (size_t)r16*DD))[e&31];
            }
        }
        const ulonglong2* zz = (const ulonglong2*)(sz + cb*512);
        const ulonglong2* qq = (const ulonglong2*)(sq + cb*512);
        const int kb = c*16 + g*2;
        #pragma unroll
        for (int q = 0; q < 2; ++q) {
            ulonglong2 zv = zz[(g*2+q)*32 + lane];
            ulonglong2 qv = qq[(g*2+q)*32 + lane];
            u64 wuA=swt[kb+q],      uuA=swt[256+kb+q],  wrA=swt[512+kb+q];
            u64 urA=swt[768+kb+q],  whA=swt[1024+kb+q];
            u64 wuB=swt[128+kb+q],  uuB=swt[384+kb+q],  wrB=swt[640+kb+q];
            u64 urB=swt[896+kb+q],  whB=swt[1152+kb+q];
            auA0=ffma2(wuA,zv.x,auA0); auA1=ffma2(wuA,zv.y,auA1);
            auA0=ffma2(uuA,qv.x,auA0); auA1=ffma2(uuA,qv.y,auA1);
            arA0=ffma2(wrA,zv.x,arA0); arA1=ffma2(wrA,zv.y,arA1);
            arA0=ffma2(urA,qv.x,arA0); arA1=ffma2(urA,qv.y,arA1);
            ahA0=ffma2(whA,zv.x,ahA0); ahA1=ffma2(whA,zv.y,ahA1);
            auB0=ffma2(wuB,zv.x,auB0); auB1=ffma2(wuB,zv.y,auB1);
            auB0=ffma2(uuB,qv.x,auB0); auB1=ffma2(uuB,qv.y,auB1);
            arB0=ffma2(wrB,zv.x,arB0); arB1=ffma2(wrB,zv.y,arB1);
            arB0=ffma2(urB,qv.x,arB0); arB1=ffma2(urB,qv.y,arB1);
            ahB0=ffma2(whB,zv.x,ahB0); ahB1=ffma2(whB,zv.y,ahB1);
        }
        if (c < 7) {
            #pragma unroll
            for (int p = 0; p < 2; ++p) { int e = tid+256*p; sz[nb*512+e]=rz[p]; sq[nb*512+e]=rqv[p]; }
        }
        __syncthreads();
    }

    // 8-way reduction: groups 1..7 store 12 partials each into sz/sq region
    u64* sp = (u64*)sz;   // 32KB = 4096 u64 >= 7*12*32 = 2688
    if (g > 0) {
        int base = (g-1)*12*32 + lane;
        sp[base+0*32]=auA0;  sp[base+1*32]=auA1;  sp[base+2*32]=arA0;  sp[base+3*32]=arA1;
        sp[base+4*32]=ahA0;  sp[base+5*32]=ahA1;  sp[base+6*32]=auB0;  sp[base+7*32]=auB1;
        sp[base+8*32]=arB0;  sp[base+9*32]=arB1;  sp[base+10*32]=ahB0; sp[base+11*32]=ahB1;
    }
    __syncthreads();
    if (g == 0) {
        #pragma unroll
        for (int gi = 0; gi < 7; ++gi) {
            int base = gi*12*32 + lane;
            auA0=padd2(auA0,sp[base+0*32]);  auA1=padd2(auA1,sp[base+1*32]);
            arA0=padd2(arA0,sp[base+2*32]);  arA1=padd2(arA1,sp[base+3*32]);
            ahA0=padd2(ahA0,sp[base+4*32]);  ahA1=padd2(ahA1,sp[base+5*32]);
            auB0=padd2(auB0,sp[base+6*32]);  auB1=padd2(auB1,sp[base+7*32]);
            arB0=padd2(arB0,sp[base+8*32]);  arB1=padd2(arB1,sp[base+9*32]);
            ahB0=padd2(ahB0,sp[base+10*32]); ahB1=padd2(ahB1,sp[base+11*32]);
        }
        float f0,f1,f2,f3;
        {
            const size_t o = ((size_t)b*DD + giA)*DD + 4*lane;
            up2(auA0,f0,f1); up2(auA1,f2,f3);
            *(float4*)&g_u[o] = make_float4(sigf(f0),sigf(f1),sigf(f2),sigf(f3));
            up2(arA0,f0,f1); up2(arA1,f2,f3);
            float4 q4 = *(const float4*)&Q[(size_t)giA*DD + 4*lane];
            *(float4*)&g_rq[o] = make_float4(sigf(f0)*q4.x, sigf(f1)*q4.y, sigf(f2)*q4.z, sigf(f3)*q4.w);
            up2(ahA0,f0,f1); up2(ahA1,f2,f3);
            *(float4*)&g_preh[o] = make_float4(f0,f1,f2,f3);
        }
        {
            const size_t o = ((size_t)b*DD + giB)*DD + 4*lane;
            up2(auB0,f0,f1); up2(auB1,f2,f3);
            *(float4*)&g_u[o] = make_float4(sigf(f0),sigf(f1),sigf(f2),sigf(f3));
            up2(arB0,f0,f1); up2(arB1,f2,f3);
            float4 q4 = *(const float4*)&Q[(size_t)giB*DD + 4*lane];
            *(float4*)&g_rq[o] = make_float4(sigf(f0)*q4.x, sigf(f1)*q4.y, sigf(f2)*q4.z, sigf(f3)*q4.w);
            up2(ahB0,f0,f1); up2(ahB1,f2,f3);
            *(float4*)&g_preh[o] = make_float4(f0,f1,f2,f3);
        }
    }
}

// ---------------------------------------------------------------------------
// K5: newQ. 2 rows/block, k-split x8. grid (64, B), 256 thr.
// ---------------------------------------------------------------------------
__global__ void __launch_bounds__(256) k_newQ(
    const float* __restrict__ prevQ, const float* __restrict__ Uh)
{
    __shared__ u64 swt[256];
    __shared__ float4 sb[2*512];
    __shared__ u64 sp[7*4*32];
    const int b = blockIdx.y, i0 = blockIdx.x*2;
    const int tid = threadIdx.x, g = tid>>5, lane = tid&31;
    const int giA = i0, giB = i0 + 1;
    {
        int e = tid;
        float a = Uh[(i0 + (e>>7))*DD + (e&127)]; swt[e] = pk2(a,a);
    }
    const float* Bm = g_rq + (size_t)b*DD*DD;
    float4 rb[2];
    #pragma unroll
    for (int p = 0; p < 2; ++p) { int e = tid+256*p; rb[p] = ((const float4*)(Bm + (size_t)(e>>5)*DD))[e&31]; }
    #pragma unroll
    for (int p = 0; p < 2; ++p) { int e = tid+256*p; sb[e]=rb[p]; }
    __syncthreads();
    u64 aA0=0,aA1=0,aB0=0,aB1=0;
    for (int c = 0; c < 8; ++c) {
        const int cb = c & 1, nb = cb ^ 1;
        if (c < 7) {
            #pragma unroll
            for (int p = 0; p < 2; ++p) {
                int e = tid + 256*p;
                rb[p] = ((const float4*)(Bm + (size_t)((c+1)*16 + (e>>5))*DD))[e&31];
            }
        }
        const ulonglong2* bb = (const ulonglong2*)(sb + cb*512);
        const int kb = c*16 + g*2;
        #pragma unroll
        for (int q = 0; q < 2; ++q) {
            ulonglong2 bv = bb[(g*2+q)*32 + lane];
            u64 wtA = swt[kb+q], wtB = swt[128+kb+q];
            aA0 = ffma2(wtA, bv.x, aA0); aA1 = ffma2(wtA, bv.y, aA1);
            aB0 = ffma2(wtB, bv.x, aB0); aB1 = ffma2(wtB, bv.y, aB1);
        }
        if (c < 7) {
            #pragma unroll
            for (int p = 0; p < 2; ++p) { int e = tid+256*p; sb[nb*512+e]=rb[p]; }
        }
        __syncthreads();
    }
    if (g > 0) {
        int base = (g-1)*4*32 + lane;
        sp[base] = aA0; sp[base+32] = aA1; sp[base+64] = aB0; sp[base+96] = aB1;
    }
    __syncthreads();
    if (g == 0) {
        #pragma unroll
        for (int gi = 0; gi < 7; ++gi) {
            int base = gi*4*32 + lane;
            aA0 = padd2(aA0, sp[base]);    aA1 = padd2(aA1, sp[base+32]);
            aB0 = padd2(aB0, sp[base+64]); aB1 = padd2(aB1, sp[base+96]);
        }
        float f0,f1,f2,f3;
        {
            up2(aA0,f0,f1); up2(aA1,f2,f3);
            const size_t o = ((size_t)b*DD + giA)*DD + 4*lane;
            float4 ph = *(const float4*)&g_preh[o];
            float4 uv = *(const float4*)&g_u[o];
            float4 q4 = *(const float4*)&prevQ[(size_t)b*DD*DD + giA*DD + 4*lane];
            float h0 = tanhf(f0+ph.x), h1 = tanhf(f1+ph.y), h2 = tanhf(f2+ph.z), h3 = tanhf(f3+ph.w);
            *(float4*)&g_newQ[o] = make_float4(
                (1.f-uv.x)*q4.x + uv.x*h0, (1.f-uv.y)*q4.y + uv.y*h1,
                (1.f-uv.z)*q4.z + uv.z*h2, (1.f-uv.w)*q4.w + uv.w*h3);
        }
        {
            up2(aB0,f0,f1); up2(aB1,f2,f3);
            const size_t o = ((size_t)b*DD + giB)*DD + 4*lane;
            float4 ph = *(const float4*)&g_preh[o];
            float4 uv = *(const float4*)&g_u[o];
            float4 q4 = *(const float4*)&prevQ[(size_t)b*DD*DD + giB*DD + 4*lane];
            float h0 = tanhf(f0+ph.x), h1 = tanhf(f1+ph.y), h2 = tanhf(f2+ph.z), h3 = tanhf(f3+ph.w);
            *(float4*)&g_newQ[o] = make_float4(
                (1.f-uv.x)*q4.x + uv.x*h0, (1.f-uv.y)*q4.y + uv.y*h1,
                (1.f-uv.z)*q4.z + uv.z*h2, (1.f-uv.w)*q4.w + uv.w*h3);
        }
    }
}

// ---------------------------------------------------------------------------
// K6: P = ne @ newQ. 2 rows/block, k-split x8. grid (32, B), 256 thr.
// ---------------------------------------------------------------------------
__global__ void __launch_bounds__(256) k_g1()
{
    __shared__ u64 swt[256];
    __shared__ float4 sb[2*512];
    __shared__ u64 sp[7*4*32];
    const int b = blockIdx.y, i0 = blockIdx.x*2;
    const int tid = threadIdx.x, g = tid>>5, lane = tid&31;
    const int giA = i0, giB = i0 + 1;
    {
        int e = tid;
        float a = g_ne[((size_t)b*KT + i0 + (e>>7))*DD + (e&127)]; swt[e] = pk2(a,a);
    }
    const float* Bm = g_newQ + (size_t)b*DD*DD;
    float4 rb[2];
    #pragma unroll
    for (int p = 0; p < 2; ++p) { int e = tid+256*p; rb[p] = ((const float4*)(Bm + (size_t)(e>>5)*DD))[e&31]; }
    #pragma unroll
    for (int p = 0; p < 2; ++p) { int e = tid+256*p; sb[e]=rb[p]; }
    __syncthreads();
    u64 aA0=0,aA1=0,aB0=0,aB1=0;
    for (int c = 0; c < 8; ++c) {
        const int cb = c & 1, nb = cb ^ 1;
        if (c < 7) {
            #pragma unroll
            for (int p = 0; p < 2; ++p) {
                int e = tid + 256*p;
                rb[p] = ((const float4*)(Bm + (size_t)((c+1)*16 + (e>>5))*DD))[e&31];
            }
        }
        const ulonglong2* bb = (const ulonglong2*)(sb + cb*512);
        const int kb = c*16 + g*2;
        #pragma unroll
        for (int q = 0; q < 2; ++q) {
            ulonglong2 bv = bb[(g*2+q)*32 + lane];
            u64 wtA = swt[kb+q], wtB = swt[128+kb+q];
            aA0 = ffma2(wtA, bv.x, aA0); aA1 = ffma2(wtA, bv.y, aA1);
            aB0 = ffma2(wtB, bv.x, aB0); aB1 = ffma2(wtB, bv.y, aB1);
        }
        if (c < 7) {
            #pragma unroll
            for (int p = 0; p < 2; ++p) { int e = tid+256*p; sb[nb*512+e]=rb[p]; }
        }
        __syncthreads();
    }
    if (g > 0) {
        int base = (g-1)*4*32 + lane;
        sp[base] = aA0; sp[base+32] = aA1; sp[base+64] = aB0; sp[base+96] = aB1;
    }
    __syncthreads();
    if (g == 0) {
        #pragma unroll
        for (int gi = 0; gi < 7; ++gi) {
            int base = gi*4*32 + lane;
            aA0 = padd2(aA0, sp[base]);    aA1 = padd2(aA1, sp[base+32]);
            aB0 = padd2(aB0, sp[base+64]); aB1 = padd2(aB1, sp[base+96]);
        }
        float f0,f1,f2,f3;
        up2(aA0,f0,f1); up2(aA1,f2,f3);
        *(float4*)&g_P[((size_t)b*KT + giA)*DD + 4*lane] = make_float4(f0,f1,f2,f3);
        up2(aB0,f0,f1); up2(aB1,f2,f3);
        *(float4*)&g_P[((size_t)b*KT + giB)*DD + 4*lane] = make_float4(f0,f1,f2,f3);
    }
}

// ---------------------------------------------------------------------------
// K7: h1 = relu(A@P); G = h1@staticW. 256 thr, 2 rows/warp, k-split x4.
// grid (16, B).
// ---------------------------------------------------------------------------
__global__ void __launch_bounds__(256) k_g23(const float* __restrict__ sW)
{
    __shared__ u64 sAW[4*KT];
    __shared__ u64 sh1p[4*DD];
    __shared__ float buf[KT*DD];
    __shared__ u64 sp[2*12*32];
    const int b = blockIdx.y, i0 = blockIdx.x*4;
    const int tid = threadIdx.x, w = tid>>5, lane = tid&31;
    const int pr = w >> 2, g = w & 3;
    const int rA = pr*2, rB = rA + 1;
    const int giA = i0 + rA, giB = i0 + rB;
    for (int e = tid; e < 4*KT; e += 256) {
        float a = g_A[b*KT*KT + (i0 + (e>>6))*KT + (e&63)]; sAW[e] = pk2(a,a);
    }
    float4* bf4 = (float4*)buf;
    const float4* Psrc = (const float4*)(g_P + (size_t)b*KT*DD);
    for (int e = tid; e < 2048; e += 256) bf4[e] = Psrc[e];
    __syncthreads();

    u64 aA0=0,aA1=0,aB0=0,aB1=0;
    {
        const ulonglong2* bb = (const ulonglong2*)buf;
        const u64* pA = sAW + rA*KT + g*16;
        const u64* pB = sAW + rB*KT + g*16;
        #pragma unroll
        for (int q = 0; q < 16; ++q) {
            ulonglong2 bv = bb[(g*16+q)*32 + lane];
            u64 wtA = pA[q], wtB = pB[q];
            aA0 = ffma2(wtA, bv.x, aA0); aA1 = ffma2(wtA, bv.y, aA1);
            aB0 = ffma2(wtB, bv.x, aB0); aB1 = ffma2(wtB, bv.y, aB1);
        }
    }
    __syncthreads();
    if (g > 0) {
        int base = (pr*12 + (g-1)*4)*32 + lane;
        sp[base] = aA0; sp[base+32] = aA1; sp[base+64] = aB0; sp[base+96] = aB1;
    }
    __syncthreads();
    if (g == 0) {
        #pragma unroll
        for (int gi = 0; gi < 3; ++gi) {
            int base = (pr*12 + gi*4)*32 + lane;
            aA0 = padd2(aA0, sp[base]);    aA1 = padd2(aA1, sp[base+32]);
            aB0 = padd2(aB0, sp[base+64]); aB1 = padd2(aB1, sp[base+96]);
        }
        float f0,f1,f2,f3;
        up2(aA0,f0,f1); up2(aA1,f2,f3);
        f0=fmaxf(f0,0.f); f1=fmaxf(f1,0.f); f2=fmaxf(f2,0.f); f3=fmaxf(f3,0.f);
        *(float4*)&g_h1[((size_t)b*KT + giA)*DD + 4*lane] = make_float4(f0,f1,f2,f3);
        sh1p[rA*DD + 4*lane+0]=pk2(f0,f0); sh1p[rA*DD + 4*lane+1]=pk2(f1,f1);
        sh1p[rA*DD + 4*lane+2]=pk2(f2,f2); sh1p[rA*DD + 4*lane+3]=pk2(f3,f3);
        up2(aB0,f0,f1); up2(aB1,f2,f3);
        f0=fmaxf(f0,0.f); f1=fmaxf(f1,0.f); f2=fmaxf(f2,0.f); f3=fmaxf(f3,0.f);
        *(float4*)&g_h1[((size_t)b*KT + giB)*DD + 4*lane] = make_float4(f0,f1,f2,f3);
        sh1p[rB*DD + 4*lane+0]=pk2(f0,f0); sh1p[rB*DD + 4*lane+1]=pk2(f1,f1);
        sh1p[rB*DD + 4*lane+2]=pk2(f2,f2); sh1p[rB*DD + 4*lane+3]=pk2(f3,f3);
    }
    __syncthreads();

    float4 rb[4];
    #pragma unroll
    for (int p = 0; p < 4; ++p) {
        int e = tid + 256*p;
        rb[p] = ((const float4*)(sW + (size_t)(e>>5)*DD))[e&31];
    }
    #pragma unroll
    for (int p = 0; p < 4; ++p) { int e = tid+256*p; bf4[e] = rb[p]; }
    __syncthreads();
    u64 gA0=0,gA1=0,gB0=0,gB1=0;
    for (int c = 0; c < 4; ++c) {
        const int cb = c & 1, nb = cb ^ 1;
        if (c < 3) {
            #pragma unroll
            for (int p = 0; p < 4; ++p) {
                int e = tid + 256*p;
                rb[p] = ((const float4*)(sW + (size_t)((c+1)*32 + (e>>5))*DD))[e&31];
            }
        }
        const ulonglong2* bb = (const ulonglong2*)(buf + cb*4096);
        const u64* hA = sh1p + rA*DD + c*32 + g*8;
        const u64* hB = sh1p + rB*DD + c*32 + g*8;
        #pragma unroll
        for (int q = 0; q < 8; ++q) {
            ulonglong2 bv = bb[(g*8+q)*32 + lane];
            u64 wtA = hA[q], wtB = hB[q];
            gA0 = ffma2(wtA, bv.x, gA0); gA1 = ffma2(wtA, bv.y, gA1);
            gB0 = ffma2(wtB, bv.x, gB0); gB1 = ffma2(wtB, bv.y, gB1);
        }
        if (c < 3) {
            #pragma unroll
            for (int p = 0; p < 4; ++p) { int e = tid+256*p; bf4[nb*1024 + e] = rb[p]; }
        }
        __syncthreads();
    }
    if (g > 0) {
        int base = (pr*12 + (g-1)*4)*32 + lane;
        sp[base] = gA0; sp[base+32] = gA1; sp[base+64] = gB0; sp[base+96] = gB1;
    }
    __syncthreads();
    if (g == 0) {
        #pragma unroll
        for (int gi = 0; gi < 3; ++gi) {
            int base = (pr*12 + gi*4)*32 + lane;
            gA0 = padd2(gA0, sp[base]);    gA1 = padd2(gA1, sp[base+32]);
            gB0 = padd2(gB0, sp[base+64]); gB1 = padd2(gB1, sp[base+96]);
        }
        float f0,f1,f2,f3;
        up2(gA0,f0,f1); up2(gA1,f2,f3);
        *(float4*)&g_G[((size_t)b*KT + giA)*DD + 4*lane] = make_float4(f0,f1,f2,f3);
        up2(gB0,f0,f1); up2(gB1,f2,f3);
        *(float4*)&g_G[((size_t)b*KT + giB)*DD + 4*lane] = make_float4(f0,f1,f2,f3);
    }
}

// ---------------------------------------------------------------------------
// K8: out = (h1 + relu(A @ G)) / 2. 256 thr, 2 rows/warp, k-split x4.
// ---------------------------------------------------------------------------
__global__ void __launch_bounds__(256) k_g4(float* __restrict__ out)
{
    __shared__ u64 sAW[4*KT];
    __shared__ float buf[KT*DD];
    __shared__ u64 sp[2*12*32];
    const int b = blockIdx.y, i0 = blockIdx.x*4;
    const int tid = threadIdx.x, w = tid>>5, lane = tid&31;
    const int pr = w >> 2, g = w & 3;
    const int rA = pr*2, rB = rA + 1;
    const int giA = i0 + rA, giB = i0 + rB;
    for (int e = tid; e < 4*KT; e += 256) {
        float a = g_A[b*KT*KT + (i0 + (e>>6))*KT + (e&63)]; sAW[e] = pk2(a,a);
    }
    float4* bf4 = (float4*)buf;
    const float4* Gsrc = (const float4*)(g_G + (size_t)b*KT*DD);
    for (int e = tid; e < 2048; e += 256) bf4[e] = Gsrc[e];
    __syncthreads();
    u64 aA0=0,aA1=0,aB0=0,aB1=0;
    const ulonglong2* bb = (const ulonglong2*)buf;
    const u64* pA = sAW + rA*KT + g*16;
    const u64* pB = sAW + rB*KT + g*16;
    #pragma unroll
    for (int q = 0; q < 16; ++q) {
        ulonglong2 bv = bb[(g*16+q)*32 + lane];
        u64 wtA = pA[q], wtB = pB[q];
        aA0 = ffma2(wtA, bv.x, aA0); aA1 = ffma2(wtA, bv.y, aA1);
        aB0 = ffma2(wtB, bv.x, aB0); aB1 = ffma2(wtB, bv.y, aB1);
    }
    if (g > 0) {
        int base = (pr*12 + (g-1)*4)*32 + lane;
        sp[base] = aA0; sp[base+32] = aA1; sp[base+64] = aB0; sp[base+96] = aB1;
    }
    __syncthreads();
    if (g == 0) {
        #pragma unroll
        for (int gi = 0; gi < 3; ++gi) {
            int base = (pr*12 + gi*4)*32 + lane;
            aA0 = padd2(aA0, sp[base]);    aA1 = padd2(aA1, sp[base+32]);
            aB0 = padd2(aB0, sp[base+64]); aB1 = padd2(aB1, sp[base+96]);
        }
        float f0,f1,f2,f3;
        up2(aA0,f0,f1); up2(aA1,f2,f3);
        {
            float4 h1v = *(const float4*)&g_h1[((size_t)b*KT + giA)*DD + 4*lane];
            *(float4*)&out[((size_t)b*KT + giA)*DD + 4*lane] = make_float4(
                (h1v.x + fmaxf(f0,0.f))*0.5f, (h1v.y + fmaxf(f1,0.f))*0.5f,
                (h1v.z + fmaxf(f2,0.f))*0.5f, (h1v.w + fmaxf(f3,0.f))*0.5f);
        }
        up2(aB0,f0,f1); up2(aB1,f2,f3);
        {
            float4 h1v = *(const float4*)&g_h1[((size_t)b*KT + giB)*DD + 4*lane];
            *(float4*)&out[((size_t)b*KT + giB)*DD + 4*lane] = make_float4(
                (h1v.x + fmaxf(f0,0.f))*0.5f, (h1v.y + fmaxf(f1,0.f))*0.5f,
                (h1v.z + fmaxf(f2,0.f))*0.5f, (h1v.w + fmaxf(f3,0.f))*0.5f);
        }
    }
}

// ---------------------------------------------------------------------------
extern "C" void kernel_launch(void* const* d_in, const int* in_sizes, int n_in,
                              void* d_out, int out_size)
{
    const float* Ahat      = (const float*)d_in[0];
    const float* node_embs = (const float*)d_in[1];
    const float* ht        = (const float*)d_in[3];
    const float* prevQ     = (const float*)d_in[4];
    const float* W_map     = (const float*)d_in[5];
    const float* b_map     = (const float*)d_in[6];
    const float* Wu        = (const float*)d_in[7];
    const float* Uu        = (const float*)d_in[8];
    const float* bu        = (const float*)d_in[9];
    const float* Wr        = (const float*)d_in[10];
    const float* Ur        = (const float*)d_in[11];
    const float* br        = (const float*)d_in[12];
    const float* Wh        = (const float*)d_in[13];
    const float* Uh        = (const float*)d_in[14];
    const float* bh        = (const float*)d_in[15];
    const float* sW        = (const float*)d_in[16];
    float* out = (float*)d_out;

    const int gates_smem = 1280*8 + 2*512*16 + 2*512*16;   // 43008 B
    cudaFuncSetAttribute(k_gates, cudaFuncAttributeMaxDynamicSharedMemorySize, gates_smem);

    k_scorer<<<BB, 512>>>(ht, W_map, b_map, out);
    k_scores<<<dim3(32, BB), 128>>>(node_embs);
    k_topk_gather<<<BB, 512, NN * sizeof(unsigned long long)>>>(node_embs, Ahat, out);
    k_gates<<<dim3(64, BB), 256, gates_smem>>>(prevQ, Wu, Uu, bu, Wr, Ur, br, Wh, bh);
    k_newQ<<<dim3(64, BB), 256>>>(prevQ, Uh);
    k_g1<<<dim3(32, BB), 256>>>();
    k_g23<<<dim3(16, BB), 256>>>(sW);
    k_g4<<<dim3(16, BB), 256>>>(out);
}